// round 12
// baseline (speedup 1.0000x reference)
#include <cuda_runtime.h>
#include <math.h>

#define NPTS 4096
#define NB   2
#define KS   8
#define KC   (NPTS / KS)     // 512
#define RSQ  0.99999500003749968f   // 1/sqrt(1 + 1e-5)

// TC dynamic smem: Wv[4][128][20] + Xs[4][16][132] floats
#define STG   4
#define WV_N  (STG * 128 * 20)
#define XS_N  (STG * 16 * 132)
#define TCSM  ((WV_N + XS_N) * 4)    // 74752 bytes

// ---------------------------------------------------------------------------
// Packed fp32x2 helpers (Blackwell FFMA2)
// ---------------------------------------------------------------------------
__device__ __forceinline__ unsigned long long pack2(float x, float y) {
    unsigned long long r;
    asm("mov.b64 %0, {%1, %2};" : "=l"(r) : "f"(x), "f"(y));
    return r;
}
__device__ __forceinline__ void ffma2(unsigned long long& d,
                                      unsigned long long a,
                                      unsigned long long b) {
    asm("fma.rn.f32x2 %0, %1, %2, %0;" : "+l"(d) : "l"(a), "l"(b));
}
__device__ __forceinline__ float2 unpack2(unsigned long long v) {
    float2 f;
    asm("mov.b64 {%0, %1}, %2;" : "=f"(f.x), "=f"(f.y) : "l"(v));
    return f;
}

// ---------------------------------------------------------------------------
// TF32 tensor-core helpers (3xTF32)
// ---------------------------------------------------------------------------
__device__ __forceinline__ unsigned f2tf(float f) {
    unsigned r;
    asm("cvt.rna.tf32.f32 %0, %1;" : "=r"(r) : "f"(f));
    return r;
}
__device__ __forceinline__ void split_tf(float f, unsigned& hi, unsigned& lo) {
    hi = f2tf(f);
    lo = f2tf(f - __uint_as_float(hi));
}
__device__ __forceinline__ void mma_tf32(float* d, const unsigned* a, const unsigned* b) {
    asm("mma.sync.aligned.m16n8k8.row.col.f32.tf32.tf32.f32 "
        "{%0,%1,%2,%3}, {%4,%5,%6,%7}, {%8,%9}, {%0,%1,%2,%3};"
        : "+f"(d[0]), "+f"(d[1]), "+f"(d[2]), "+f"(d[3])
        : "r"(a[0]), "r"(a[1]), "r"(a[2]), "r"(a[3]), "r"(b[0]), "r"(b[1]));
}

// ---------------------------------------------------------------------------
// cp.async helpers
// ---------------------------------------------------------------------------
__device__ __forceinline__ void cpa16(void* smem, const void* gmem) {
    unsigned s = (unsigned)__cvta_generic_to_shared(smem);
    asm volatile("cp.async.cg.shared.global [%0], [%1], 16;\n" :: "r"(s), "l"(gmem));
}
#define CP_COMMIT() asm volatile("cp.async.commit_group;\n" ::: "memory")
#define CP_WAIT2()  asm volatile("cp.async.wait_group 2;\n" ::: "memory")

// ---------------------------------------------------------------------------
// Scratch (static __device__ globals)
// ---------------------------------------------------------------------------
__device__ float g_h1   [NB * 128  * NPTS];
__device__ float g_h0   [NB * 128  * NPTS];
__device__ float g_q    [NB * 32   * NPTS];
__device__ float g_v    [NB * 128  * NPTS];
__device__ float g_E    [(size_t)NB * NPTS * NPTS];   // unnormalized P
__device__ float g_t    [NB * 128  * NPTS];
__device__ float g_feats[NB * 512  * NPTS];
__device__ float g_hf   [NB * 1024 * NPTS];
__device__ float g_pool [NB * 2048];
__device__ float g_pbias[NB * 512];
__device__ float g_h512 [NB * 512  * NPTS];
__device__ float g_h256 [NB * 256  * NPTS];
__device__ float g_pOut [KS * NB * 128 * NPTS];
__device__ float g_pSum [KS * NB * NPTS];
__device__ float g_m    [NB * NPTS];
__device__ float g_s    [NB * NPTS];
__device__ float g_invs [NB * NPTS];

// ---------------------------------------------------------------------------
// Input MLP stage 1
// ---------------------------------------------------------------------------
__global__ void mlp1_kernel(const float* __restrict__ x, const float* __restrict__ w1,
                            const float* __restrict__ g, const float* __restrict__ bb,
                            float* __restrict__ h1)
{
    int n = blockIdx.x * 256 + threadIdx.x;
    int c = blockIdx.y;
    int b = blockIdx.z;
    float x0 = x[((long)b * 15 +  9) * NPTS + n];
    float x1 = x[((long)b * 15 + 10) * NPTS + n];
    float x2 = x[((long)b * 15 + 11) * NPTS + n];
    float acc = w1[c*3+0]*x0 + w1[c*3+1]*x1 + w1[c*3+2]*x2;
    acc = acc * (g[c] * RSQ) + bb[c];
    h1[((long)b * 128 + c) * NPTS + n] = fmaxf(acc, 0.f);
}

// ---------------------------------------------------------------------------
// FFMA2 GEMM (kept for q only, O=32)
// ---------------------------------------------------------------------------
template<int TN>
__global__ __launch_bounds__(256) void gemm_kernel(
    const float* __restrict__ W, int ldW,
    const float* __restrict__ X, long strideX,
    float* __restrict__ Y, long strideY,
    int O, int C,
    const float* __restrict__ convBias, int convBiasStride,
    const float* __restrict__ scale,
    const float* __restrict__ bias,
    int act,
    const float* __restrict__ resid, long strideResid)
{
    constexpr int CT = TN / 16;
    constexpr int XL = (4 * TN) / 256;
    const int bN = blockIdx.x * TN;
    const int bM = blockIdx.y * 128;
    const int b  = blockIdx.z;
    const float* Wb = W;
    const float* Xb = X + (long)b * strideX;

    __shared__ __align__(16) float Ws[2][16][128];
    __shared__ __align__(16) float Xs[2][16][TN];

    const int tid = threadIdx.x;
    const int tm0 = (tid >> 4) * 4;
    const int tn0 = (tid & 15) * 4;

    const int wm  = tid >> 2;
    const int wkq = (tid & 3) * 4;
    int xk[XL], xn[XL];
    #pragma unroll
    for (int l = 0; l < XL; l++) {
        int idx = tid + l * 256;
        xk[l] = idx / (TN / 4);
        xn[l] = (idx % (TN / 4)) * 4;
    }

    unsigned long long acc2[4][CT];
    #pragma unroll
    for (int i = 0; i < 4; i++)
        #pragma unroll
        for (int j = 0; j < CT; j++) acc2[i][j] = 0ull;

    float4 wr0, wr1, xr[XL];
    const int T = C / 16;

    {
        wr0 = make_float4(0.f,0.f,0.f,0.f);
        wr1 = make_float4(0.f,0.f,0.f,0.f);
        if (bM + wm      < O) wr0 = *(const float4*)&Wb[(long)(bM + wm     ) * ldW + wkq];
        if (bM + wm + 64 < O) wr1 = *(const float4*)&Wb[(long)(bM + wm + 64) * ldW + wkq];
        #pragma unroll
        for (int l = 0; l < XL; l++)
            xr[l] = *(const float4*)&Xb[(long)xk[l] * NPTS + bN + xn[l]];
        Ws[0][wkq+0][wm] = wr0.x; Ws[0][wkq+1][wm] = wr0.y;
        Ws[0][wkq+2][wm] = wr0.z; Ws[0][wkq+3][wm] = wr0.w;
        Ws[0][wkq+0][wm+64] = wr1.x; Ws[0][wkq+1][wm+64] = wr1.y;
        Ws[0][wkq+2][wm+64] = wr1.z; Ws[0][wkq+3][wm+64] = wr1.w;
        #pragma unroll
        for (int l = 0; l < XL; l++)
            *(float4*)&Xs[0][xk[l]][xn[l]] = xr[l];
    }
    __syncthreads();

    for (int t = 0; t < T; t++) {
        const int cur = t & 1;
        const int nxt = cur ^ 1;
        const bool more = (t + 1 < T);

        if (more) {
            int k0 = (t + 1) * 16;
            wr0 = make_float4(0.f,0.f,0.f,0.f);
            wr1 = make_float4(0.f,0.f,0.f,0.f);
            if (bM + wm      < O) wr0 = *(const float4*)&Wb[(long)(bM + wm     ) * ldW + k0 + wkq];
            if (bM + wm + 64 < O) wr1 = *(const float4*)&Wb[(long)(bM + wm + 64) * ldW + k0 + wkq];
            #pragma unroll
            for (int l = 0; l < XL; l++)
                xr[l] = *(const float4*)&Xb[(long)(k0 + xk[l]) * NPTS + bN + xn[l]];
        }

        #pragma unroll
        for (int k = 0; k < 16; k++) {
            ulonglong2 a01 = *(const ulonglong2*)&Ws[cur][k][tm0];
            ulonglong2 a23 = *(const ulonglong2*)&Ws[cur][k][tm0 + 64];
            unsigned long long ap[4] = {a01.x, a01.y, a23.x, a23.y};
            float xv[CT];
            float4 x0 = *(const float4*)&Xs[cur][k][tn0];
            xv[0] = x0.x; xv[1] = x0.y; xv[2] = x0.z; xv[3] = x0.w;
            if (CT == 8) {
                float4 x1 = *(const float4*)&Xs[cur][k][tn0 + 64];
                xv[4] = x1.x; xv[5] = x1.y; xv[6] = x1.z; xv[7] = x1.w;
            }
            unsigned long long bs[CT];
            #pragma unroll
            for (int c = 0; c < CT; c++) bs[c] = pack2(xv[c], xv[c]);
            #pragma unroll
            for (int mp = 0; mp < 4; mp++)
                #pragma unroll
                for (int c = 0; c < CT; c++)
                    ffma2(acc2[mp][c], ap[mp], bs[c]);
        }

        if (more) {
            Ws[nxt][wkq+0][wm] = wr0.x; Ws[nxt][wkq+1][wm] = wr0.y;
            Ws[nxt][wkq+2][wm] = wr0.z; Ws[nxt][wkq+3][wm] = wr0.w;
            Ws[nxt][wkq+0][wm+64] = wr1.x; Ws[nxt][wkq+1][wm+64] = wr1.y;
            Ws[nxt][wkq+2][wm+64] = wr1.z; Ws[nxt][wkq+3][wm+64] = wr1.w;
            #pragma unroll
            for (int l = 0; l < XL; l++)
                *(float4*)&Xs[nxt][xk[l]][xn[l]] = xr[l];
            __syncthreads();
        }
    }

    #pragma unroll
    for (int mp = 0; mp < 4; mp++) {
        int rowbase = bM + tm0 + ((mp >= 2) ? 64 : 0) + (mp & 1) * 2;
        #pragma unroll
        for (int sub = 0; sub < 2; sub++) {
            int o = rowbase + sub;
            if (o >= O) continue;
            float cb = convBias ? convBias[b * convBiasStride + o] : 0.f;
            float sc = scale ? scale[o] * RSQ : 1.f;
            float bi = bias ? bias[o] : 0.f;
            float* Yrow = Y + (long)b * strideY + (long)o * NPTS;
            const float* resRow = resid ? (resid + (long)b * strideResid + (long)o * NPTS) : (const float*)0;
            #pragma unroll
            for (int c = 0; c < CT; c++) {
                int n = bN + tn0 + ((c < 4) ? c : (64 + c - 4));
                float2 pr = unpack2(acc2[mp][c]);
                float v = sub ? pr.y : pr.x;
                v = (v + cb) * sc + bi;
                if (act == 1)      v = fmaxf(v, 0.f);
                else if (act == 2) v = (v > 0.f) ? v : 0.2f * v;
                if (resRow) v += resRow[n];
                Yrow[n] = v;
            }
        }
    }
}

// ---------------------------------------------------------------------------
// TC GEMM with cp.async 4-stage pipeline.
// W tile row-major Wv[st][128][20]; X tile Xs[st][16][132].
// 8 warps = 2(M)x4(N), warp tile 64x32. O multiple of 128.
// Epilogue: v=(acc+convBias)*scale+bias; act; +resid; *colScale[n]
// ---------------------------------------------------------------------------
#define WVX(st,m,k) Wv_[(((st)*128 + (m)) * 20) + (k)]
#define XSX(st,k,n) Xs_[(((st)*16 + (k)) * 132) + (n)]

__global__ __launch_bounds__(256) void tc_gemm_kernel(
    const float* __restrict__ W, int ldW,
    const float* __restrict__ X, long strideX,
    float* __restrict__ Y, long strideY,
    int C,
    const float* __restrict__ convBias, int convBiasStride,
    const float* __restrict__ scale,
    const float* __restrict__ bias,
    int act,
    const float* __restrict__ resid, long strideResid,
    const float* __restrict__ colScale)
{
    extern __shared__ float dynsm[];
    float* Wv_ = dynsm;
    float* Xs_ = dynsm + WV_N;

    const int bN = blockIdx.x * 128;
    const int bM = blockIdx.y * 128;
    const int b  = blockIdx.z;
    const float* Wb = W;
    const float* Xb = X + (long)b * strideX;

    const int tid    = threadIdx.x;
    const int wid    = tid >> 5;
    const int lane   = tid & 31;
    const int warp_m = wid >> 2;
    const int warp_n = wid & 3;

    const int wm = tid & 127;          // W loader row
    const int wc = tid >> 7;           // W loader chunk base (0/1, also +2)
    const int xk = tid >> 4;           // X loader k
    const int xn = (tid & 15) * 8;     // X loader col base

    float acc[4][4][4];
    #pragma unroll
    for (int mi = 0; mi < 4; mi++)
        #pragma unroll
        for (int ni = 0; ni < 4; ni++)
            #pragma unroll
            for (int r = 0; r < 4; r++) acc[mi][ni][r] = 0.f;

    const int T = C / 16;

    // stage issue (uniform predicate, unconditional commit)
    #define TC_ISSUE(tt) do {                                                  \
        int _t = (tt);                                                         \
        if (_t < T) {                                                          \
            int _st = _t & 3;                                                  \
            const float* _wr = Wb + (long)(bM + wm) * ldW + _t * 16;           \
            cpa16(&WVX(_st, wm, wc * 4),       _wr + wc * 4);                  \
            cpa16(&WVX(_st, wm, (wc + 2) * 4), _wr + (wc + 2) * 4);            \
            const float* _xr = Xb + (long)(_t * 16 + xk) * NPTS + bN + xn;     \
            cpa16(&XSX(_st, xk, xn),     _xr);                                 \
            cpa16(&XSX(_st, xk, xn + 4), _xr + 4);                             \
        }                                                                      \
        CP_COMMIT();                                                           \
    } while (0)

    TC_ISSUE(0); TC_ISSUE(1); TC_ISSUE(2);

    const int alr = lane >> 2;
    const int akc = lane & 3;
    const int bnr = warp_n * 32 + (lane >> 2);

    for (int t = 0; t < T; t++) {
        CP_WAIT2();
        __syncthreads();
        TC_ISSUE(t + 3);

        const int cur = t & 3;
        #pragma unroll
        for (int kk = 0; kk < 2; kk++) {
            const int k0 = kk * 8;
            unsigned bh[4][2], bl[4][2];
            #pragma unroll
            for (int ni = 0; ni < 4; ni++) {
                #pragma unroll
                for (int r = 0; r < 2; r++) {
                    float f = XSX(cur, k0 + akc + r*4, bnr + ni*8);
                    split_tf(f, bh[ni][r], bl[ni][r]);
                }
            }
            #pragma unroll
            for (int mi = 0; mi < 4; mi++) {
                int m0 = warp_m * 64 + mi * 16 + alr;
                float f0 = WVX(cur, m0,     k0 + akc);
                float f1 = WVX(cur, m0 + 8, k0 + akc);
                float f2 = WVX(cur, m0,     k0 + akc + 4);
                float f3 = WVX(cur, m0 + 8, k0 + akc + 4);
                unsigned ah[4], al[4];
                split_tf(f0, ah[0], al[0]);
                split_tf(f1, ah[1], al[1]);
                split_tf(f2, ah[2], al[2]);
                split_tf(f3, ah[3], al[3]);
                #pragma unroll
                for (int ni = 0; ni < 4; ni++) {
                    mma_tf32(acc[mi][ni], ah, bh[ni]);
                    mma_tf32(acc[mi][ni], al, bh[ni]);
                    mma_tf32(acc[mi][ni], ah, bl[ni]);
                }
            }
        }
    }

    // epilogue
    #pragma unroll
    for (int mi = 0; mi < 4; mi++) {
        #pragma unroll
        for (int rr = 0; rr < 2; rr++) {
            int o = bM + warp_m * 64 + mi * 16 + (lane >> 2) + rr * 8;
            float cb = convBias ? convBias[b * convBiasStride + o] : 0.f;
            float sc = scale ? scale[o] * RSQ : 1.f;
            float bi = bias ? bias[o] : 0.f;
            float* Yrow = Y + (long)b * strideY + (long)o * NPTS;
            const float* resRow = resid ? (resid + (long)b * strideResid + (long)o * NPTS) : (const float*)0;
            #pragma unroll
            for (int ni = 0; ni < 4; ni++) {
                int col = bN + warp_n * 32 + ni * 8 + (lane & 3) * 2;
                #pragma unroll
                for (int cc = 0; cc < 2; cc++) {
                    float v = acc[mi][ni][rr * 2 + cc];
                    v = (v + cb) * sc + bi;
                    if (act == 1)      v = fmaxf(v, 0.f);
                    else if (act == 2) v = (v > 0.f) ? v : 0.2f * v;
                    if (resRow) v += resRow[col + cc];
                    if (colScale) v *= colScale[(long)b * NPTS + col + cc];
                    Yrow[col + cc] = v;
                }
            }
        }
    }
}

// ---------------------------------------------------------------------------
// TC apply with cp.async: pOut[ks][b] = V'(:,chunk) @ P(chunk,:) ;
// pSum = colsum of invs-weighted P (= colsum of attn) via preloaded isv table.
// V' is already invs-scaled (done in the v-GEMM epilogue).
// ---------------------------------------------------------------------------
__global__ __launch_bounds__(256) void tc_apply_kernel(
    const float* __restrict__ V,
    const float* __restrict__ P,
    const float* __restrict__ invs,
    float* __restrict__ pOut,
    float* __restrict__ pSum)
{
    extern __shared__ float dynsm[];
    float* Wv_ = dynsm;
    float* Xs_ = dynsm + WV_N;
    __shared__ float isv_all[KC];

    const int bN = blockIdx.x * 128;
    const int ks = blockIdx.y;
    const int b  = blockIdx.z;
    const float* Wb = V + (long)b * 128 * NPTS + (long)ks * KC;
    const float* Xb = P + (long)b * NPTS * NPTS + (long)ks * KC * NPTS;
    const float* invb = invs + (long)b * NPTS + (long)ks * KC;

    const int tid    = threadIdx.x;
    const int wid    = tid >> 5;
    const int lane   = tid & 31;
    const int warp_m = wid >> 2;
    const int warp_n = wid & 3;

    const int wm = tid & 127;
    const int wc = tid >> 7;
    const int xk = tid >> 4;
    const int xn = (tid & 15) * 8;

    // preload invs for this K chunk (for colsum weighting)
    #pragma unroll
    for (int l = 0; l < KC / 256; l++)
        isv_all[tid + l * 256] = invb[tid + l * 256];

    float acc[4][4][4];
    #pragma unroll
    for (int mi = 0; mi < 4; mi++)
        #pragma unroll
        for (int ni = 0; ni < 4; ni++)
            #pragma unroll
            for (int r = 0; r < 4; r++) acc[mi][ni][r] = 0.f;
    float ssum = 0.f;

    const int T = KC / 16;

    #define AP_ISSUE(tt) do {                                                  \
        int _t = (tt);                                                         \
        if (_t < T) {                                                          \
            int _st = _t & 3;                                                  \
            const float* _wr = Wb + (long)wm * NPTS + _t * 16;                 \
            cpa16(&WVX(_st, wm, wc * 4),       _wr + wc * 4);                  \
            cpa16(&WVX(_st, wm, (wc + 2) * 4), _wr + (wc + 2) * 4);            \
            const float* _xr = Xb + (long)(_t * 16 + xk) * NPTS + bN + xn;     \
            cpa16(&XSX(_st, xk, xn),     _xr);                                 \
            cpa16(&XSX(_st, xk, xn + 4), _xr + 4);                             \
        }                                                                      \
        CP_COMMIT();                                                           \
    } while (0)

    AP_ISSUE(0); AP_ISSUE(1); AP_ISSUE(2);

    const int alr = lane >> 2;
    const int akc = lane & 3;
    const int bnr = warp_n * 32 + (lane >> 2);

    for (int t = 0; t < T; t++) {
        CP_WAIT2();
        __syncthreads();
        AP_ISSUE(t + 3);

        const int cur = t & 3;
        #pragma unroll
        for (int kk = 0; kk < 2; kk++) {
            const int k0 = kk * 8;
            unsigned bh[4][2], bl[4][2];
            #pragma unroll
            for (int ni = 0; ni < 4; ni++) {
                #pragma unroll
                for (int r = 0; r < 2; r++) {
                    float f = XSX(cur, k0 + akc + r*4, bnr + ni*8);
                    split_tf(f, bh[ni][r], bl[ni][r]);
                }
            }
            #pragma unroll
            for (int mi = 0; mi < 4; mi++) {
                int m0 = warp_m * 64 + mi * 16 + alr;
                float f0 = WVX(cur, m0,     k0 + akc);
                float f1 = WVX(cur, m0 + 8, k0 + akc);
                float f2 = WVX(cur, m0,     k0 + akc + 4);
                float f3 = WVX(cur, m0 + 8, k0 + akc + 4);
                unsigned ah[4], al[4];
                split_tf(f0, ah[0], al[0]);
                split_tf(f1, ah[1], al[1]);
                split_tf(f2, ah[2], al[2]);
                split_tf(f3, ah[3], al[3]);
                #pragma unroll
                for (int ni = 0; ni < 4; ni++) {
                    mma_tf32(acc[mi][ni], ah, bh[ni]);
                    mma_tf32(acc[mi][ni], al, bh[ni]);
                    mma_tf32(acc[mi][ni], ah, bl[ni]);
                }
            }
        }

        // fused colsum of attn = sum_k isv[k] * P[k][col]
        if (tid < 128) {
            float s = 0.f;
            #pragma unroll
            for (int k = 0; k < 16; k++)
                s += XSX(cur, k, tid) * isv_all[t * 16 + k];
            ssum += s;
        }
    }

    float* Ob = pOut + ((long)(ks * NB + b) * 128) * NPTS;
    #pragma unroll
    for (int mi = 0; mi < 4; mi++) {
        #pragma unroll
        for (int rr = 0; rr < 2; rr++) {
            int o = warp_m * 64 + mi * 16 + (lane >> 2) + rr * 8;
            float* Yrow = Ob + (long)o * NPTS;
            #pragma unroll
            for (int ni = 0; ni < 4; ni++) {
                int col = bN + warp_n * 32 + ni * 8 + (lane & 3) * 2;
                Yrow[col]     = acc[mi][ni][rr * 2];
                Yrow[col + 1] = acc[mi][ni][rr * 2 + 1];
            }
        }
    }
    if (tid < 128)
        pSum[(long)(ks * NB + b) * NPTS + bN + tid] = ssum;
}

// ---------------------------------------------------------------------------
// Apply reduce: t[b,c,n] = h[b,c,n] - (sum_ks pOut)/(1e-9 + sum_ks pSum)
// ---------------------------------------------------------------------------
__global__ __launch_bounds__(256) void apply_reduce_kernel(
    const float* __restrict__ pOut, const float* __restrict__ pSum,
    const float* __restrict__ h, long hStride, float* __restrict__ t)
{
    int n = blockIdx.x * 256 + threadIdx.x;
    int c = blockIdx.y;
    int b = blockIdx.z;
    float num = 0.f, den = 0.f;
    #pragma unroll
    for (int ks = 0; ks < KS; ks++) {
        num += pOut[((long)(ks * NB + b) * 128 + c) * NPTS + n];
        den += pSum[(long)(ks * NB + b) * NPTS + n];
    }
    t[((long)b * 128 + c) * NPTS + n] =
        h[(long)b * hStride + (long)c * NPTS + n] - num / (1e-9f + den);
}

// ---------------------------------------------------------------------------
// emax: row maxima of E (atomicMax int bits; valid since final max >= 0)
// ---------------------------------------------------------------------------
__global__ __launch_bounds__(256) void emax_kernel(const float* __restrict__ q,
                                                   float* __restrict__ m)
{
    int bj = blockIdx.x * 64;
    int bi = blockIdx.y * 64;
    int b  = blockIdx.z;
    const float* Q = q + (long)b * 32 * NPTS;

    __shared__ __align__(16) float Qi[32][64];
    __shared__ __align__(16) float Qj[32][64];
    __shared__ float sm[64][17];

    int tid = threadIdx.x;
    #pragma unroll
    for (int l = 0; l < 2; l++) {
        int idx = tid + l * 256;
        int d   = idx >> 4;
        int nq  = (idx & 15) * 4;
        *(float4*)&Qi[d][nq] = *(const float4*)&Q[(long)d * NPTS + bi + nq];
        *(float4*)&Qj[d][nq] = *(const float4*)&Q[(long)d * NPTS + bj + nq];
    }
    __syncthreads();

    int ti = (tid >> 4) * 4;
    int tj = (tid & 15) * 4;
    unsigned long long acc2[2][4];
    #pragma unroll
    for (int p = 0; p < 2; p++)
        #pragma unroll
        for (int c = 0; c < 4; c++) acc2[p][c] = 0ull;

    #pragma unroll
    for (int d = 0; d < 32; d++) {
        ulonglong2 a = *(const ulonglong2*)&Qi[d][ti];
        unsigned long long ap[2] = {a.x, a.y};
        float4 c4 = *(const float4*)&Qj[d][tj];
        float cv[4] = {c4.x, c4.y, c4.z, c4.w};
        unsigned long long bs[4];
        #pragma unroll
        for (int c = 0; c < 4; c++) bs[c] = pack2(cv[c], cv[c]);
        #pragma unroll
        for (int p = 0; p < 2; p++)
            #pragma unroll
            for (int c = 0; c < 4; c++) ffma2(acc2[p][c], ap[p], bs[c]);
    }

    float rmax[4] = {-1e30f, -1e30f, -1e30f, -1e30f};
    #pragma unroll
    for (int p = 0; p < 2; p++)
        #pragma unroll
        for (int c = 0; c < 4; c++) {
            float2 u = unpack2(acc2[p][c]);
            rmax[p*2]     = fmaxf(rmax[p*2],     u.x);
            rmax[p*2 + 1] = fmaxf(rmax[p*2 + 1], u.y);
        }
    #pragma unroll
    for (int r = 0; r < 4; r++) sm[ti + r][tid & 15] = rmax[r];
    __syncthreads();
    if (tid < 64) {
        float v = sm[tid][0];
        #pragma unroll
        for (int k = 1; k < 16; k++) v = fmaxf(v, sm[tid][k]);
        atomicMax((int*)&m[b * NPTS + bi + tid], __float_as_int(v));
    }
}

// ---------------------------------------------------------------------------
// pexp: recompute E, write P = exp(E - m_i), accumulate row sums
// ---------------------------------------------------------------------------
__global__ __launch_bounds__(256) void pexp_kernel(const float* __restrict__ q,
                                                   const float* __restrict__ m,
                                                   float* __restrict__ P,
                                                   float* __restrict__ s)
{
    int bj = blockIdx.x * 64;
    int bi = blockIdx.y * 64;
    int b  = blockIdx.z;
    const float* Q = q + (long)b * 32 * NPTS;
    float* Pb = P + (long)b * NPTS * NPTS;

    __shared__ __align__(16) float Qi[32][64];
    __shared__ __align__(16) float Qj[32][64];
    __shared__ float sm[64][17];

    int tid = threadIdx.x;
    #pragma unroll
    for (int l = 0; l < 2; l++) {
        int idx = tid + l * 256;
        int d   = idx >> 4;
        int nq  = (idx & 15) * 4;
        *(float4*)&Qi[d][nq] = *(const float4*)&Q[(long)d * NPTS + bi + nq];
        *(float4*)&Qj[d][nq] = *(const float4*)&Q[(long)d * NPTS + bj + nq];
    }
    __syncthreads();

    int ti = (tid >> 4) * 4;
    int tj = (tid & 15) * 4;
    unsigned long long acc2[2][4];
    #pragma unroll
    for (int p = 0; p < 2; p++)
        #pragma unroll
        for (int c = 0; c < 4; c++) acc2[p][c] = 0ull;

    #pragma unroll
    for (int d = 0; d < 32; d++) {
        ulonglong2 a = *(const ulonglong2*)&Qi[d][ti];
        unsigned long long ap[2] = {a.x, a.y};
        float4 c4 = *(const float4*)&Qj[d][tj];
        float cv[4] = {c4.x, c4.y, c4.z, c4.w};
        unsigned long long bs[4];
        #pragma unroll
        for (int c = 0; c < 4; c++) bs[c] = pack2(cv[c], cv[c]);
        #pragma unroll
        for (int p = 0; p < 2; p++)
            #pragma unroll
            for (int c = 0; c < 4; c++) ffma2(acc2[p][c], ap[p], bs[c]);
    }

    float mrow[4], rsum[4] = {0.f, 0.f, 0.f, 0.f};
    #pragma unroll
    for (int r = 0; r < 4; r++) mrow[r] = m[b * NPTS + bi + ti + r];

    #pragma unroll
    for (int p = 0; p < 2; p++) {
        float2 u0 = unpack2(acc2[p][0]);
        float2 u1 = unpack2(acc2[p][1]);
        float2 u2 = unpack2(acc2[p][2]);
        float2 u3 = unpack2(acc2[p][3]);
        int r0 = bi + ti + p * 2;
        float m0 = mrow[p*2], m1 = mrow[p*2 + 1];
        float4 row0 = make_float4(__expf(u0.x - m0), __expf(u1.x - m0),
                                  __expf(u2.x - m0), __expf(u3.x - m0));
        float4 row1 = make_float4(__expf(u0.y - m1), __expf(u1.y - m1),
                                  __expf(u2.y - m1), __expf(u3.y - m1));
        rsum[p*2]     += row0.x + row0.y + row0.z + row0.w;
        rsum[p*2 + 1] += row1.x + row1.y + row1.z + row1.w;
        *(float4*)&Pb[(long)r0       * NPTS + bj + tj] = row0;
        *(float4*)&Pb[(long)(r0 + 1) * NPTS + bj + tj] = row1;
    }

    #pragma unroll
    for (int r = 0; r < 4; r++) sm[ti + r][tid & 15] = rsum[r];
    __syncthreads();
    if (tid < 64) {
        float v = 0.f;
        #pragma unroll
        for (int k = 0; k < 16; k++) v += sm[tid][k];
        atomicAdd(&s[b * NPTS + bi + tid], v);
    }
}

__global__ void zero2_kernel(float* __restrict__ a, float* __restrict__ c, int len)
{
    int i = blockIdx.x * 256 + threadIdx.x;
    if (i < len) { a[i] = 0.f; c[i] = 0.f; }
}

__global__ void inv_kernel(const float* __restrict__ s, float* __restrict__ invs, int len)
{
    int i = blockIdx.x * 256 + threadIdx.x;
    if (i < len) invs[i] = 1.0f / s[i];
}

// ---------------------------------------------------------------------------
// Pool, pbias, final
// ---------------------------------------------------------------------------
__global__ __launch_bounds__(256) void pool_kernel(const float* __restrict__ hf,
                                                   float* __restrict__ pool)
{
    int c = blockIdx.x, b = blockIdx.y, tid = threadIdx.x;
    const float* row = hf + ((long)b * 1024 + c) * NPTS;
    float m = -1e30f, sum = 0.f;
    for (int n = tid; n < NPTS; n += 256) {
        float v = row[n];
        m = fmaxf(m, v);
        sum += v;
    }
    __shared__ float sm[256], ss[256];
    sm[tid] = m; ss[tid] = sum; __syncthreads();
    for (int st = 128; st > 0; st >>= 1) {
        if (tid < st) {
            sm[tid] = fmaxf(sm[tid], sm[tid + st]);
            ss[tid] += ss[tid + st];
        }
        __syncthreads();
    }
    if (tid == 0) {
        pool[b * 2048 + c]        = sm[0];
        pool[b * 2048 + 1024 + c] = ss[0] * (1.f / NPTS);
    }
}

__global__ __launch_bounds__(256) void pbias_kernel(const float* __restrict__ ws1,
                                                    const float* __restrict__ bs1,
                                                    const float* __restrict__ pool,
                                                    float* __restrict__ pbias)
{
    int o = blockIdx.x, b = blockIdx.y, tid = threadIdx.x;
    float acc = 0.f;
    for (int c = tid; c < 1024; c += 256) {
        acc += ws1[(long)o * 3072 + 1024 + c] * pool[b * 2048 + c];
        acc += ws1[(long)o * 3072 + 2048 + c] * pool[b * 2048 + 1024 + c];
    }
    __shared__ float red[256];
    red[tid] = acc; __syncthreads();
    for (int st = 128; st > 0; st >>= 1) {
        if (tid < st) red[tid] += red[tid + st];
        __syncthreads();
    }
    if (tid == 0) pbias[b * 512 + o] = bs1[o] + red[0];
}

__global__ __launch_bounds__(128) void final_kernel(const float* __restrict__ h256,
                                                    const float* __restrict__ ws3,
                                                    const float* __restrict__ bs3,
                                                    float* __restrict__ out)
{
    __shared__ float Wsh[8][256];
    int tid = threadIdx.x;
    for (int l = tid; l < 2048; l += 128) Wsh[l >> 8][l & 255] = ws3[l];
    __syncthreads();

    int n = blockIdx.x * 128 + tid;
    int b = blockIdx.y;
    const float* hb = h256 + (long)b * 256 * NPTS;

    float acc[8];
    #pragma unroll
    for (int k = 0; k < 8; k++) acc[k] = bs3[k];
    for (int c = 0; c < 256; c++) {
        float xv = hb[(long)c * NPTS + n];
        #pragma unroll
        for (int k = 0; k < 8; k++) acc[k] += Wsh[k][c] * xv;
    }
    float m = acc[0];
    #pragma unroll
    for (int k = 1; k < 8; k++) m = fmaxf(m, acc[k]);
    float s = 0.f;
    #pragma unroll
    for (int k = 0; k < 8; k++) s += __expf(acc[k] - m);
    float lse = m + logf(s);
    float* op = out + ((long)b * NPTS + n) * 8;
    #pragma unroll
    for (int k = 0; k < 8; k++) op[k] = acc[k] - lse;
}

// ---------------------------------------------------------------------------
// Host orchestration
// ---------------------------------------------------------------------------
static inline void launch_gemm64(const float* W, int ldW,
                                 const float* X, long sX,
                                 float* Y, long sY, int O, int C,
                                 const float* cb, int cbs,
                                 const float* sc, const float* bi, int act,
                                 const float* res, long sres)
{
    dim3 grid(NPTS / 64, (O + 127) / 128, NB);
    gemm_kernel<64><<<grid, 256>>>(W, ldW, X, sX, Y, sY, O, C,
                                   cb, cbs, sc, bi, act, res, sres);
}

static inline void launch_tc(const float* W, int ldW,
                             const float* X, long sX,
                             float* Y, long sY, int O, int C,
                             const float* cb, int cbs,
                             const float* sc, const float* bi, int act,
                             const float* res, long sres,
                             const float* colScale)
{
    dim3 grid(NPTS / 128, O / 128, NB);
    tc_gemm_kernel<<<grid, 256, TCSM>>>(W, ldW, X, sX, Y, sY, C,
                                        cb, cbs, sc, bi, act, res, sres, colScale);
}

extern "C" void kernel_launch(void* const* d_in, const int* in_sizes, int n_in,
                              void* d_out, int out_size)
{
    (void)in_sizes; (void)n_in; (void)out_size;

    cudaFuncSetAttribute((const void*)tc_gemm_kernel,
                         cudaFuncAttributeMaxDynamicSharedMemorySize, TCSM);
    cudaFuncSetAttribute((const void*)tc_apply_kernel,
                         cudaFuncAttributeMaxDynamicSharedMemorySize, TCSM);

    const float* x      = (const float*)d_in[0];
    const float* w1     = (const float*)d_in[1];
    const float* bn1_g  = (const float*)d_in[2];
    const float* bn1_b  = (const float*)d_in[3];
    const float* w2     = (const float*)d_in[4];
    const float* bn2_g  = (const float*)d_in[5];
    const float* bn2_b  = (const float*)d_in[6];
    const float* sa_wqk = (const float*)d_in[7];
    const float* sa_wv  = (const float*)d_in[8];
    const float* sa_bv  = (const float*)d_in[9];
    const float* sa_wt  = (const float*)d_in[10];
    const float* sa_bt  = (const float*)d_in[11];
    const float* sa_bng = (const float*)d_in[12];
    const float* sa_bnb = (const float*)d_in[13];
    const float* wf     = (const float*)d_in[14];
    const float* bnf_g  = (const float*)d_in[15];
    const float* bnf_b  = (const float*)d_in[16];
    const float* ws1    = (const float*)d_in[17];
    const float* bs1    = (const float*)d_in[18];
    const float* bns1_g = (const float*)d_in[19];
    const float* bns1_b = (const float*)d_in[20];
    const float* ws2    = (const float*)d_in[21];
    const float* bs2    = (const float*)d_in[22];
    const float* bns2_g = (const float*)d_in[23];
    const float* bns2_b = (const float*)d_in[24];
    const float* ws3    = (const float*)d_in[25];
    const float* bs3    = (const float*)d_in[26];

    float *p_h1, *p_h0, *p_q, *p_v, *p_E, *p_t, *p_feats, *p_hf, *p_pool,
          *p_pbias, *p_h512, *p_h256, *p_pOut, *p_pSum, *p_m, *p_s, *p_invs;
    cudaGetSymbolAddress((void**)&p_h1,    g_h1);
    cudaGetSymbolAddress((void**)&p_h0,    g_h0);
    cudaGetSymbolAddress((void**)&p_q,     g_q);
    cudaGetSymbolAddress((void**)&p_v,     g_v);
    cudaGetSymbolAddress((void**)&p_E,     g_E);
    cudaGetSymbolAddress((void**)&p_t,     g_t);
    cudaGetSymbolAddress((void**)&p_feats, g_feats);
    cudaGetSymbolAddress((void**)&p_hf,    g_hf);
    cudaGetSymbolAddress((void**)&p_pool,  g_pool);
    cudaGetSymbolAddress((void**)&p_pbias, g_pbias);
    cudaGetSymbolAddress((void**)&p_h512,  g_h512);
    cudaGetSymbolAddress((void**)&p_h256,  g_h256);
    cudaGetSymbolAddress((void**)&p_pOut,  g_pOut);
    cudaGetSymbolAddress((void**)&p_pSum,  g_pSum);
    cudaGetSymbolAddress((void**)&p_m,     g_m);
    cudaGetSymbolAddress((void**)&p_s,     g_s);
    cudaGetSymbolAddress((void**)&p_invs,  g_invs);

    // input MLP
    mlp1_kernel<<<dim3(NPTS / 256, 128, NB), 256>>>(x, w1, bn1_g, bn1_b, p_h1);
    launch_tc(w2, 128, p_h1, 128L * NPTS, p_h0, 128L * NPTS, 128, 128,
              0, 0, bn2_g, bn2_b, 1, 0, 0, 0);

    // 4 self-attention layers
    for (int i = 0; i < 4; i++) {
        const float* h   = (i == 0) ? p_h0 : (p_feats + (long)(i - 1) * 128 * NPTS);
        long hStride     = (i == 0) ? 128L * NPTS : 512L * NPTS;

        // q = wqk_i @ h  (FFMA2, O=32)
        launch_gemm64(sa_wqk + (long)i * 32 * 128, 128, h, hStride,
                      p_q, 32L * NPTS, 32, 128, 0, 0, 0, 0, 0, 0, 0);

        // fused energy/softmax: row maxes, P = exp(E - m), row sums, invs
        zero2_kernel<<<(NB * NPTS + 255) / 256, 256>>>(p_m, p_s, NB * NPTS);
        emax_kernel<<<dim3(64, 64, NB), 256>>>(p_q, p_m);
        pexp_kernel<<<dim3(64, 64, NB), 256>>>(p_q, p_m, p_E, p_s);
        inv_kernel<<<(NB * NPTS + 255) / 256, 256>>>(p_s, p_invs, NB * NPTS);

        // v' = (wv_i @ h + bv_i) * invs[n]   [TC, row-norm folded into V]
        launch_tc(sa_wv + (long)i * 128 * 128, 128, h, hStride,
                  p_v, 128L * NPTS, 128, 128,
                  sa_bv + (long)i * 128, 0, 0, 0, 0, 0, 0, p_invs);

        // K-split apply: pOut = V' @ P, pSum = colsum(attn); then reduce
        tc_apply_kernel<<<dim3(NPTS / 128, KS, NB), 256, TCSM>>>(p_v, p_E, p_invs,
                                                                 p_pOut, p_pSum);
        apply_reduce_kernel<<<dim3(NPTS / 256, 128, NB), 256>>>(p_pOut, p_pSum,
                                                                h, hStride, p_t);

        // h_new = relu(bn(wt_i @ t + bt_i)) + h   [TC]
        launch_tc(sa_wt + (long)i * 128 * 128, 128, p_t, 128L * NPTS,
                  p_feats + (long)i * 128 * NPTS, 512L * NPTS, 128, 128,
                  sa_bt + (long)i * 128, 0,
                  sa_bng + (long)i * 128, sa_bnb + (long)i * 128, 1,
                  h, hStride, 0);
    }

    // hf = leaky_relu(bn(wf @ feats), 0.2)   [TC]
    launch_tc(wf, 512, p_feats, 512L * NPTS, p_hf, 1024L * NPTS, 1024, 512,
              0, 0, bnf_g, bnf_b, 2, 0, 0, 0);

    // pooling + folded per-batch bias for ws1
    pool_kernel<<<dim3(1024, NB), 256>>>(p_hf, p_pool);
    pbias_kernel<<<dim3(512, NB), 256>>>(ws1, bs1, p_pool, p_pbias);

    // h512 = relu(bn(ws1[:, :1024] @ hf + pbias))   [TC]
    launch_tc(ws1, 3072, p_hf, 1024L * NPTS, p_h512, 512L * NPTS, 512, 1024,
              p_pbias, 512, bns1_g, bns1_b, 1, 0, 0, 0);

    // h256 = relu(bn(ws2 @ h512 + bs2))   [TC]
    launch_tc(ws2, 512, p_h512, 512L * NPTS, p_h256, 256L * NPTS, 256, 512,
              bs2, 0, bns2_g, bns2_b, 1, 0, 0, 0);

    // logits + log_softmax + transpose
    final_kernel<<<dim3(NPTS / 128, NB), 128>>>(p_h256, ws3, bs3, (float*)d_out);
}

// round 13
// speedup vs baseline: 1.0101x; 1.0101x over previous
#include <cuda_runtime.h>
#include <math.h>

#define NPTS 4096
#define NB   2
#define KS   8
#define KC   (NPTS / KS)     // 512
#define RSQ  0.99999500003749968f   // 1/sqrt(1 + 1e-5)

// TC dynamic smem: Wv[3][128][20] + Xs[3][16][132] floats
#define STG   3
#define WV_N  (STG * 128 * 20)
#define XS_N  (STG * 16 * 132)
#define TCSM  ((WV_N + XS_N) * 4)    // 56064 bytes -> 2 blocks/SM

// ---------------------------------------------------------------------------
// Packed fp32x2 helpers (Blackwell FFMA2)
// ---------------------------------------------------------------------------
__device__ __forceinline__ unsigned long long pack2(float x, float y) {
    unsigned long long r;
    asm("mov.b64 %0, {%1, %2};" : "=l"(r) : "f"(x), "f"(y));
    return r;
}
__device__ __forceinline__ void ffma2(unsigned long long& d,
                                      unsigned long long a,
                                      unsigned long long b) {
    asm("fma.rn.f32x2 %0, %1, %2, %0;" : "+l"(d) : "l"(a), "l"(b));
}
__device__ __forceinline__ float2 unpack2(unsigned long long v) {
    float2 f;
    asm("mov.b64 {%0, %1}, %2;" : "=f"(f.x), "=f"(f.y) : "l"(v));
    return f;
}

// ---------------------------------------------------------------------------
// TF32 tensor-core helpers (3xTF32)
// ---------------------------------------------------------------------------
__device__ __forceinline__ unsigned f2tf(float f) {
    unsigned r;
    asm("cvt.rna.tf32.f32 %0, %1;" : "=r"(r) : "f"(f));
    return r;
}
__device__ __forceinline__ void split_tf(float f, unsigned& hi, unsigned& lo) {
    hi = f2tf(f);
    lo = f2tf(f - __uint_as_float(hi));
}
__device__ __forceinline__ void mma_tf32(float* d, const unsigned* a, const unsigned* b) {
    asm("mma.sync.aligned.m16n8k8.row.col.f32.tf32.tf32.f32 "
        "{%0,%1,%2,%3}, {%4,%5,%6,%7}, {%8,%9}, {%0,%1,%2,%3};"
        : "+f"(d[0]), "+f"(d[1]), "+f"(d[2]), "+f"(d[3])
        : "r"(a[0]), "r"(a[1]), "r"(a[2]), "r"(a[3]), "r"(b[0]), "r"(b[1]));
}

// ---------------------------------------------------------------------------
// cp.async helpers
// ---------------------------------------------------------------------------
__device__ __forceinline__ void cpa16(void* smem, const void* gmem) {
    unsigned s = (unsigned)__cvta_generic_to_shared(smem);
    asm volatile("cp.async.cg.shared.global [%0], [%1], 16;\n" :: "r"(s), "l"(gmem));
}
#define CP_COMMIT() asm volatile("cp.async.commit_group;\n" ::: "memory")
#define CP_WAIT1()  asm volatile("cp.async.wait_group 1;\n" ::: "memory")

// ---------------------------------------------------------------------------
// Scratch (static __device__ globals)
// ---------------------------------------------------------------------------
__device__ float g_h1   [NB * 128  * NPTS];
__device__ float g_h0   [NB * 128  * NPTS];
__device__ float g_q    [NB * 32   * NPTS];
__device__ float g_v    [NB * 128  * NPTS];
__device__ float g_E    [(size_t)NB * NPTS * NPTS];   // unnormalized P
__device__ float g_t    [NB * 128  * NPTS];
__device__ float g_feats[NB * 512  * NPTS];
__device__ float g_hf   [NB * 1024 * NPTS];
__device__ float g_pool [NB * 2048];
__device__ float g_pbias[NB * 512];
__device__ float g_h512 [NB * 512  * NPTS];
__device__ float g_h256 [NB * 256  * NPTS];
__device__ float g_pOut [KS * NB * 128 * NPTS];
__device__ float g_pSum [KS * NB * NPTS];
__device__ float g_m    [NB * NPTS];
__device__ float g_s    [NB * NPTS];
__device__ float g_invs [NB * NPTS];

// ---------------------------------------------------------------------------
// Input MLP stage 1
// ---------------------------------------------------------------------------
__global__ void mlp1_kernel(const float* __restrict__ x, const float* __restrict__ w1,
                            const float* __restrict__ g, const float* __restrict__ bb,
                            float* __restrict__ h1)
{
    int n = blockIdx.x * 256 + threadIdx.x;
    int c = blockIdx.y;
    int b = blockIdx.z;
    float x0 = x[((long)b * 15 +  9) * NPTS + n];
    float x1 = x[((long)b * 15 + 10) * NPTS + n];
    float x2 = x[((long)b * 15 + 11) * NPTS + n];
    float acc = w1[c*3+0]*x0 + w1[c*3+1]*x1 + w1[c*3+2]*x2;
    acc = acc * (g[c] * RSQ) + bb[c];
    h1[((long)b * 128 + c) * NPTS + n] = fmaxf(acc, 0.f);
}

// ---------------------------------------------------------------------------
// FFMA2 GEMM (kept for q only, O=32)
// ---------------------------------------------------------------------------
template<int TN>
__global__ __launch_bounds__(256) void gemm_kernel(
    const float* __restrict__ W, int ldW,
    const float* __restrict__ X, long strideX,
    float* __restrict__ Y, long strideY,
    int O, int C,
    const float* __restrict__ convBias, int convBiasStride,
    const float* __restrict__ scale,
    const float* __restrict__ bias,
    int act,
    const float* __restrict__ resid, long strideResid)
{
    constexpr int CT = TN / 16;
    constexpr int XL = (4 * TN) / 256;
    const int bN = blockIdx.x * TN;
    const int bM = blockIdx.y * 128;
    const int b  = blockIdx.z;
    const float* Wb = W;
    const float* Xb = X + (long)b * strideX;

    __shared__ __align__(16) float Ws[2][16][128];
    __shared__ __align__(16) float Xs[2][16][TN];

    const int tid = threadIdx.x;
    const int tm0 = (tid >> 4) * 4;
    const int tn0 = (tid & 15) * 4;

    const int wm  = tid >> 2;
    const int wkq = (tid & 3) * 4;
    int xk[XL], xn[XL];
    #pragma unroll
    for (int l = 0; l < XL; l++) {
        int idx = tid + l * 256;
        xk[l] = idx / (TN / 4);
        xn[l] = (idx % (TN / 4)) * 4;
    }

    unsigned long long acc2[4][CT];
    #pragma unroll
    for (int i = 0; i < 4; i++)
        #pragma unroll
        for (int j = 0; j < CT; j++) acc2[i][j] = 0ull;

    float4 wr0, wr1, xr[XL];
    const int T = C / 16;

    {
        wr0 = make_float4(0.f,0.f,0.f,0.f);
        wr1 = make_float4(0.f,0.f,0.f,0.f);
        if (bM + wm      < O) wr0 = *(const float4*)&Wb[(long)(bM + wm     ) * ldW + wkq];
        if (bM + wm + 64 < O) wr1 = *(const float4*)&Wb[(long)(bM + wm + 64) * ldW + wkq];
        #pragma unroll
        for (int l = 0; l < XL; l++)
            xr[l] = *(const float4*)&Xb[(long)xk[l] * NPTS + bN + xn[l]];
        Ws[0][wkq+0][wm] = wr0.x; Ws[0][wkq+1][wm] = wr0.y;
        Ws[0][wkq+2][wm] = wr0.z; Ws[0][wkq+3][wm] = wr0.w;
        Ws[0][wkq+0][wm+64] = wr1.x; Ws[0][wkq+1][wm+64] = wr1.y;
        Ws[0][wkq+2][wm+64] = wr1.z; Ws[0][wkq+3][wm+64] = wr1.w;
        #pragma unroll
        for (int l = 0; l < XL; l++)
            *(float4*)&Xs[0][xk[l]][xn[l]] = xr[l];
    }
    __syncthreads();

    for (int t = 0; t < T; t++) {
        const int cur = t & 1;
        const int nxt = cur ^ 1;
        const bool more = (t + 1 < T);

        if (more) {
            int k0 = (t + 1) * 16;
            wr0 = make_float4(0.f,0.f,0.f,0.f);
            wr1 = make_float4(0.f,0.f,0.f,0.f);
            if (bM + wm      < O) wr0 = *(const float4*)&Wb[(long)(bM + wm     ) * ldW + k0 + wkq];
            if (bM + wm + 64 < O) wr1 = *(const float4*)&Wb[(long)(bM + wm + 64) * ldW + k0 + wkq];
            #pragma unroll
            for (int l = 0; l < XL; l++)
                xr[l] = *(const float4*)&Xb[(long)(k0 + xk[l]) * NPTS + bN + xn[l]];
        }

        #pragma unroll
        for (int k = 0; k < 16; k++) {
            ulonglong2 a01 = *(const ulonglong2*)&Ws[cur][k][tm0];
            ulonglong2 a23 = *(const ulonglong2*)&Ws[cur][k][tm0 + 64];
            unsigned long long ap[4] = {a01.x, a01.y, a23.x, a23.y};
            float xv[CT];
            float4 x0 = *(const float4*)&Xs[cur][k][tn0];
            xv[0] = x0.x; xv[1] = x0.y; xv[2] = x0.z; xv[3] = x0.w;
            if (CT == 8) {
                float4 x1 = *(const float4*)&Xs[cur][k][tn0 + 64];
                xv[4] = x1.x; xv[5] = x1.y; xv[6] = x1.z; xv[7] = x1.w;
            }
            unsigned long long bs[CT];
            #pragma unroll
            for (int c = 0; c < CT; c++) bs[c] = pack2(xv[c], xv[c]);
            #pragma unroll
            for (int mp = 0; mp < 4; mp++)
                #pragma unroll
                for (int c = 0; c < CT; c++)
                    ffma2(acc2[mp][c], ap[mp], bs[c]);
        }

        if (more) {
            Ws[nxt][wkq+0][wm] = wr0.x; Ws[nxt][wkq+1][wm] = wr0.y;
            Ws[nxt][wkq+2][wm] = wr0.z; Ws[nxt][wkq+3][wm] = wr0.w;
            Ws[nxt][wkq+0][wm+64] = wr1.x; Ws[nxt][wkq+1][wm+64] = wr1.y;
            Ws[nxt][wkq+2][wm+64] = wr1.z; Ws[nxt][wkq+3][wm+64] = wr1.w;
            #pragma unroll
            for (int l = 0; l < XL; l++)
                *(float4*)&Xs[nxt][xk[l]][xn[l]] = xr[l];
            __syncthreads();
        }
    }

    #pragma unroll
    for (int mp = 0; mp < 4; mp++) {
        int rowbase = bM + tm0 + ((mp >= 2) ? 64 : 0) + (mp & 1) * 2;
        #pragma unroll
        for (int sub = 0; sub < 2; sub++) {
            int o = rowbase + sub;
            if (o >= O) continue;
            float cb = convBias ? convBias[b * convBiasStride + o] : 0.f;
            float sc = scale ? scale[o] * RSQ : 1.f;
            float bi = bias ? bias[o] : 0.f;
            float* Yrow = Y + (long)b * strideY + (long)o * NPTS;
            const float* resRow = resid ? (resid + (long)b * strideResid + (long)o * NPTS) : (const float*)0;
            #pragma unroll
            for (int c = 0; c < CT; c++) {
                int n = bN + tn0 + ((c < 4) ? c : (64 + c - 4));
                float2 pr = unpack2(acc2[mp][c]);
                float v = sub ? pr.y : pr.x;
                v = (v + cb) * sc + bi;
                if (act == 1)      v = fmaxf(v, 0.f);
                else if (act == 2) v = (v > 0.f) ? v : 0.2f * v;
                if (resRow) v += resRow[n];
                Yrow[n] = v;
            }
        }
    }
}

// ---------------------------------------------------------------------------
// TC GEMM with cp.async 3-stage pipeline, 2 blocks/SM.
// W tile row-major Wv[st][128][20]; X tile Xs[st][16][132].
// 8 warps = 2(M)x4(N), warp tile 64x32. O multiple of 128.
// ---------------------------------------------------------------------------
#define WVX(st,m,k) Wv_[(((st)*128 + (m)) * 20) + (k)]
#define XSX(st,k,n) Xs_[(((st)*16 + (k)) * 132) + (n)]

__global__ __launch_bounds__(256, 2) void tc_gemm_kernel(
    const float* __restrict__ W, int ldW,
    const float* __restrict__ X, long strideX,
    float* __restrict__ Y, long strideY,
    int C,
    const float* __restrict__ convBias, int convBiasStride,
    const float* __restrict__ scale,
    const float* __restrict__ bias,
    int act,
    const float* __restrict__ resid, long strideResid,
    const float* __restrict__ colScale)
{
    extern __shared__ float dynsm[];
    float* Wv_ = dynsm;
    float* Xs_ = dynsm + WV_N;

    const int bN = blockIdx.x * 128;
    const int bM = blockIdx.y * 128;
    const int b  = blockIdx.z;
    const float* Wb = W;
    const float* Xb = X + (long)b * strideX;

    const int tid    = threadIdx.x;
    const int wid    = tid >> 5;
    const int lane   = tid & 31;
    const int warp_m = wid >> 2;
    const int warp_n = wid & 3;

    const int wm = tid & 127;
    const int wc = tid >> 7;
    const int xk = tid >> 4;
    const int xn = (tid & 15) * 8;

    float acc[4][4][4];
    #pragma unroll
    for (int mi = 0; mi < 4; mi++)
        #pragma unroll
        for (int ni = 0; ni < 4; ni++)
            #pragma unroll
            for (int r = 0; r < 4; r++) acc[mi][ni][r] = 0.f;

    const int T = C / 16;

    #define TC_ISSUE(tt, st) do {                                              \
        int _t = (tt); int _st = (st);                                         \
        if (_t < T) {                                                          \
            const float* _wr = Wb + (long)(bM + wm) * ldW + _t * 16;           \
            cpa16(&WVX(_st, wm, wc * 4),       _wr + wc * 4);                  \
            cpa16(&WVX(_st, wm, (wc + 2) * 4), _wr + (wc + 2) * 4);            \
            const float* _xr = Xb + (long)(_t * 16 + xk) * NPTS + bN + xn;     \
            cpa16(&XSX(_st, xk, xn),     _xr);                                 \
            cpa16(&XSX(_st, xk, xn + 4), _xr + 4);                             \
        }                                                                      \
        CP_COMMIT();                                                           \
    } while (0)

    TC_ISSUE(0, 0); TC_ISSUE(1, 1);

    const int alr = lane >> 2;
    const int akc = lane & 3;
    const int bnr = warp_n * 32 + (lane >> 2);

    int cur = 0;
    for (int t = 0; t < T; t++) {
        CP_WAIT1();
        __syncthreads();
        int nst = cur + 2; if (nst >= STG) nst -= STG;
        TC_ISSUE(t + 2, nst);

        #pragma unroll
        for (int kk = 0; kk < 2; kk++) {
            const int k0 = kk * 8;
            unsigned bh[4][2], bl[4][2];
            #pragma unroll
            for (int ni = 0; ni < 4; ni++) {
                #pragma unroll
                for (int r = 0; r < 2; r++) {
                    float f = XSX(cur, k0 + akc + r*4, bnr + ni*8);
                    split_tf(f, bh[ni][r], bl[ni][r]);
                }
            }
            #pragma unroll
            for (int mi = 0; mi < 4; mi++) {
                int m0 = warp_m * 64 + mi * 16 + alr;
                float f0 = WVX(cur, m0,     k0 + akc);
                float f1 = WVX(cur, m0 + 8, k0 + akc);
                float f2 = WVX(cur, m0,     k0 + akc + 4);
                float f3 = WVX(cur, m0 + 8, k0 + akc + 4);
                unsigned ah[4], al[4];
                split_tf(f0, ah[0], al[0]);
                split_tf(f1, ah[1], al[1]);
                split_tf(f2, ah[2], al[2]);
                split_tf(f3, ah[3], al[3]);
                #pragma unroll
                for (int ni = 0; ni < 4; ni++) {
                    mma_tf32(acc[mi][ni], ah, bh[ni]);
                    mma_tf32(acc[mi][ni], al, bh[ni]);
                    mma_tf32(acc[mi][ni], ah, bl[ni]);
                }
            }
        }

        cur = (cur + 1 == STG) ? 0 : cur + 1;
    }

    // epilogue
    #pragma unroll
    for (int mi = 0; mi < 4; mi++) {
        #pragma unroll
        for (int rr = 0; rr < 2; rr++) {
            int o = bM + warp_m * 64 + mi * 16 + (lane >> 2) + rr * 8;
            float cb = convBias ? convBias[b * convBiasStride + o] : 0.f;
            float sc = scale ? scale[o] * RSQ : 1.f;
            float bi = bias ? bias[o] : 0.f;
            float* Yrow = Y + (long)b * strideY + (long)o * NPTS;
            const float* resRow = resid ? (resid + (long)b * strideResid + (long)o * NPTS) : (const float*)0;
            #pragma unroll
            for (int ni = 0; ni < 4; ni++) {
                int col = bN + warp_n * 32 + ni * 8 + (lane & 3) * 2;
                #pragma unroll
                for (int cc = 0; cc < 2; cc++) {
                    float v = acc[mi][ni][rr * 2 + cc];
                    v = (v + cb) * sc + bi;
                    if (act == 1)      v = fmaxf(v, 0.f);
                    else if (act == 2) v = (v > 0.f) ? v : 0.2f * v;
                    if (resRow) v += resRow[col + cc];
                    if (colScale) v *= colScale[(long)b * NPTS + col + cc];
                    Yrow[col + cc] = v;
                }
            }
        }
    }
}

// ---------------------------------------------------------------------------
// TC apply with cp.async, 2 blocks/SM: pOut = V'(:,chunk) @ P(chunk,:);
// pSum = colsum of invs-weighted P via preloaded isv table.
// ---------------------------------------------------------------------------
__global__ __launch_bounds__(256, 2) void tc_apply_kernel(
    const float* __restrict__ V,
    const float* __restrict__ P,
    const float* __restrict__ invs,
    float* __restrict__ pOut,
    float* __restrict__ pSum)
{
    extern __shared__ float dynsm[];
    float* Wv_ = dynsm;
    float* Xs_ = dynsm + WV_N;
    __shared__ float isv_all[KC];

    const int bN = blockIdx.x * 128;
    const int ks = blockIdx.y;
    const int b  = blockIdx.z;
    const float* Wb = V + (long)b * 128 * NPTS + (long)ks * KC;
    const float* Xb = P + (long)b * NPTS * NPTS + (long)ks * KC * NPTS;
    const float* invb = invs + (long)b * NPTS + (long)ks * KC;

    const int tid    = threadIdx.x;
    const int wid    = tid >> 5;
    const int lane   = tid & 31;
    const int warp_m = wid >> 2;
    const int warp_n = wid & 3;

    const int wm = tid & 127;
    const int wc = tid >> 7;
    const int xk = tid >> 4;
    const int xn = (tid & 15) * 8;

    #pragma unroll
    for (int l = 0; l < KC / 256; l++)
        isv_all[tid + l * 256] = invb[tid + l * 256];

    float acc[4][4][4];
    #pragma unroll
    for (int mi = 0; mi < 4; mi++)
        #pragma unroll
        for (int ni = 0; ni < 4; ni++)
            #pragma unroll
            for (int r = 0; r < 4; r++) acc[mi][ni][r] = 0.f;
    float ssum = 0.f;

    const int T = KC / 16;

    #define AP_ISSUE(tt, st) do {                                              \
        int _t = (tt); int _st = (st);                                         \
        if (_t < T) {                                                          \
            const float* _wr = Wb + (long)wm * NPTS + _t * 16;                 \
            cpa16(&WVX(_st, wm, wc * 4),       _wr + wc * 4);                  \
            cpa16(&WVX(_st, wm, (wc + 2) * 4), _wr + (wc + 2) * 4);            \
            const float* _xr = Xb + (long)(_t * 16 + xk) * NPTS + bN + xn;     \
            cpa16(&XSX(_st, xk, xn),     _xr);                                 \
            cpa16(&XSX(_st, xk, xn + 4), _xr + 4);                             \
        }                                                                      \
        CP_COMMIT();                                                           \
    } while (0)

    AP_ISSUE(0, 0); AP_ISSUE(1, 1);

    const int alr = lane >> 2;
    const int akc = lane & 3;
    const int bnr = warp_n * 32 + (lane >> 2);

    int cur = 0;
    for (int t = 0; t < T; t++) {
        CP_WAIT1();
        __syncthreads();
        int nst = cur + 2; if (nst >= STG) nst -= STG;
        AP_ISSUE(t + 2, nst);

        #pragma unroll
        for (int kk = 0; kk < 2; kk++) {
            const int k0 = kk * 8;
            unsigned bh[4][2], bl[4][2];
            #pragma unroll
            for (int ni = 0; ni < 4; ni++) {
                #pragma unroll
                for (int r = 0; r < 2; r++) {
                    float f = XSX(cur, k0 + akc + r*4, bnr + ni*8);
                    split_tf(f, bh[ni][r], bl[ni][r]);
                }
            }
            #pragma unroll
            for (int mi = 0; mi < 4; mi++) {
                int m0 = warp_m * 64 + mi * 16 + alr;
                float f0 = WVX(cur, m0,     k0 + akc);
                float f1 = WVX(cur, m0 + 8, k0 + akc);
                float f2 = WVX(cur, m0,     k0 + akc + 4);
                float f3 = WVX(cur, m0 + 8, k0 + akc + 4);
                unsigned ah[4], al[4];
                split_tf(f0, ah[0], al[0]);
                split_tf(f1, ah[1], al[1]);
                split_tf(f2, ah[2], al[2]);
                split_tf(f3, ah[3], al[3]);
                #pragma unroll
                for (int ni = 0; ni < 4; ni++) {
                    mma_tf32(acc[mi][ni], ah, bh[ni]);
                    mma_tf32(acc[mi][ni], al, bh[ni]);
                    mma_tf32(acc[mi][ni], ah, bl[ni]);
                }
            }
        }

        if (tid < 128) {
            float s = 0.f;
            #pragma unroll
            for (int k = 0; k < 16; k++)
                s += XSX(cur, k, tid) * isv_all[t * 16 + k];
            ssum += s;
        }

        cur = (cur + 1 == STG) ? 0 : cur + 1;
    }

    float* Ob = pOut + ((long)(ks * NB + b) * 128) * NPTS;
    #pragma unroll
    for (int mi = 0; mi < 4; mi++) {
        #pragma unroll
        for (int rr = 0; rr < 2; rr++) {
            int o = warp_m * 64 + mi * 16 + (lane >> 2) + rr * 8;
            float* Yrow = Ob + (long)o * NPTS;
            #pragma unroll
            for (int ni = 0; ni < 4; ni++) {
                int col = bN + warp_n * 32 + ni * 8 + (lane & 3) * 2;
                Yrow[col]     = acc[mi][ni][rr * 2];
                Yrow[col + 1] = acc[mi][ni][rr * 2 + 1];
            }
        }
    }
    if (tid < 128)
        pSum[(long)(ks * NB + b) * NPTS + bN + tid] = ssum;
}

// ---------------------------------------------------------------------------
// Apply reduce: t[b,c,n] = h[b,c,n] - (sum_ks pOut)/(1e-9 + sum_ks pSum)
// ---------------------------------------------------------------------------
__global__ __launch_bounds__(256) void apply_reduce_kernel(
    const float* __restrict__ pOut, const float* __restrict__ pSum,
    const float* __restrict__ h, long hStride, float* __restrict__ t)
{
    int n = blockIdx.x * 256 + threadIdx.x;
    int c = blockIdx.y;
    int b = blockIdx.z;
    float num = 0.f, den = 0.f;
    #pragma unroll
    for (int ks = 0; ks < KS; ks++) {
        num += pOut[((long)(ks * NB + b) * 128 + c) * NPTS + n];
        den += pSum[(long)(ks * NB + b) * NPTS + n];
    }
    t[((long)b * 128 + c) * NPTS + n] =
        h[(long)b * hStride + (long)c * NPTS + n] - num / (1e-9f + den);
}

// ---------------------------------------------------------------------------
// emax: row maxima of E (atomicMax int bits; valid since final max >= 0)
// ---------------------------------------------------------------------------
__global__ __launch_bounds__(256) void emax_kernel(const float* __restrict__ q,
                                                   float* __restrict__ m)
{
    int bj = blockIdx.x * 64;
    int bi = blockIdx.y * 64;
    int b  = blockIdx.z;
    const float* Q = q + (long)b * 32 * NPTS;

    __shared__ __align__(16) float Qi[32][64];
    __shared__ __align__(16) float Qj[32][64];
    __shared__ float sm[64][17];

    int tid = threadIdx.x;
    #pragma unroll
    for (int l = 0; l < 2; l++) {
        int idx = tid + l * 256;
        int d   = idx >> 4;
        int nq  = (idx & 15) * 4;
        *(float4*)&Qi[d][nq] = *(const float4*)&Q[(long)d * NPTS + bi + nq];
        *(float4*)&Qj[d][nq] = *(const float4*)&Q[(long)d * NPTS + bj + nq];
    }
    __syncthreads();

    int ti = (tid >> 4) * 4;
    int tj = (tid & 15) * 4;
    unsigned long long acc2[2][4];
    #pragma unroll
    for (int p = 0; p < 2; p++)
        #pragma unroll
        for (int c = 0; c < 4; c++) acc2[p][c] = 0ull;

    #pragma unroll
    for (int d = 0; d < 32; d++) {
        ulonglong2 a = *(const ulonglong2*)&Qi[d][ti];
        unsigned long long ap[2] = {a.x, a.y};
        float4 c4 = *(const float4*)&Qj[d][tj];
        float cv[4] = {c4.x, c4.y, c4.z, c4.w};
        unsigned long long bs[4];
        #pragma unroll
        for (int c = 0; c < 4; c++) bs[c] = pack2(cv[c], cv[c]);
        #pragma unroll
        for (int p = 0; p < 2; p++)
            #pragma unroll
            for (int c = 0; c < 4; c++) ffma2(acc2[p][c], ap[p], bs[c]);
    }

    float rmax[4] = {-1e30f, -1e30f, -1e30f, -1e30f};
    #pragma unroll
    for (int p = 0; p < 2; p++)
        #pragma unroll
        for (int c = 0; c < 4; c++) {
            float2 u = unpack2(acc2[p][c]);
            rmax[p*2]     = fmaxf(rmax[p*2],     u.x);
            rmax[p*2 + 1] = fmaxf(rmax[p*2 + 1], u.y);
        }
    #pragma unroll
    for (int r = 0; r < 4; r++) sm[ti + r][tid & 15] = rmax[r];
    __syncthreads();
    if (tid < 64) {
        float v = sm[tid][0];
        #pragma unroll
        for (int k = 1; k < 16; k++) v = fmaxf(v, sm[tid][k]);
        atomicMax((int*)&m[b * NPTS + bi + tid], __float_as_int(v));
    }
}

// ---------------------------------------------------------------------------
// pexp: recompute E, write P = exp(E - m_i), accumulate row sums
// ---------------------------------------------------------------------------
__global__ __launch_bounds__(256) void pexp_kernel(const float* __restrict__ q,
                                                   const float* __restrict__ m,
                                                   float* __restrict__ P,
                                                   float* __restrict__ s)
{
    int bj = blockIdx.x * 64;
    int bi = blockIdx.y * 64;
    int b  = blockIdx.z;
    const float* Q = q + (long)b * 32 * NPTS;
    float* Pb = P + (long)b * NPTS * NPTS;

    __shared__ __align__(16) float Qi[32][64];
    __shared__ __align__(16) float Qj[32][64];
    __shared__ float sm[64][17];

    int tid = threadIdx.x;
    #pragma unroll
    for (int l = 0; l < 2; l++) {
        int idx = tid + l * 256;
        int d   = idx >> 4;
        int nq  = (idx & 15) * 4;
        *(float4*)&Qi[d][nq] = *(const float4*)&Q[(long)d * NPTS + bi + nq];
        *(float4*)&Qj[d][nq] = *(const float4*)&Q[(long)d * NPTS + bj + nq];
    }
    __syncthreads();

    int ti = (tid >> 4) * 4;
    int tj = (tid & 15) * 4;
    unsigned long long acc2[2][4];
    #pragma unroll
    for (int p = 0; p < 2; p++)
        #pragma unroll
        for (int c = 0; c < 4; c++) acc2[p][c] = 0ull;

    #pragma unroll
    for (int d = 0; d < 32; d++) {
        ulonglong2 a = *(const ulonglong2*)&Qi[d][ti];
        unsigned long long ap[2] = {a.x, a.y};
        float4 c4 = *(const float4*)&Qj[d][tj];
        float cv[4] = {c4.x, c4.y, c4.z, c4.w};
        unsigned long long bs[4];
        #pragma unroll
        for (int c = 0; c < 4; c++) bs[c] = pack2(cv[c], cv[c]);
        #pragma unroll
        for (int p = 0; p < 2; p++)
            #pragma unroll
            for (int c = 0; c < 4; c++) ffma2(acc2[p][c], ap[p], bs[c]);
    }

    float mrow[4], rsum[4] = {0.f, 0.f, 0.f, 0.f};
    #pragma unroll
    for (int r = 0; r < 4; r++) mrow[r] = m[b * NPTS + bi + ti + r];

    #pragma unroll
    for (int p = 0; p < 2; p++) {
        float2 u0 = unpack2(acc2[p][0]);
        float2 u1 = unpack2(acc2[p][1]);
        float2 u2 = unpack2(acc2[p][2]);
        float2 u3 = unpack2(acc2[p][3]);
        int r0 = bi + ti + p * 2;
        float m0 = mrow[p*2], m1 = mrow[p*2 + 1];
        float4 row0 = make_float4(__expf(u0.x - m0), __expf(u1.x - m0),
                                  __expf(u2.x - m0), __expf(u3.x - m0));
        float4 row1 = make_float4(__expf(u0.y - m1), __expf(u1.y - m1),
                                  __expf(u2.y - m1), __expf(u3.y - m1));
        rsum[p*2]     += row0.x + row0.y + row0.z + row0.w;
        rsum[p*2 + 1] += row1.x + row1.y + row1.z + row1.w;
        *(float4*)&Pb[(long)r0       * NPTS + bj + tj] = row0;
        *(float4*)&Pb[(long)(r0 + 1) * NPTS + bj + tj] = row1;
    }

    #pragma unroll
    for (int r = 0; r < 4; r++) sm[ti + r][tid & 15] = rsum[r];
    __syncthreads();
    if (tid < 64) {
        float v = 0.f;
        #pragma unroll
        for (int k = 0; k < 16; k++) v += sm[tid][k];
        atomicAdd(&s[b * NPTS + bi + tid], v);
    }
}

__global__ void zero2_kernel(float* __restrict__ a, float* __restrict__ c, int len)
{
    int i = blockIdx.x * 256 + threadIdx.x;
    if (i < len) { a[i] = 0.f; c[i] = 0.f; }
}

__global__ void inv_kernel(const float* __restrict__ s, float* __restrict__ invs, int len)
{
    int i = blockIdx.x * 256 + threadIdx.x;
    if (i < len) invs[i] = 1.0f / s[i];
}

// ---------------------------------------------------------------------------
// Pool, pbias, final
// ---------------------------------------------------------------------------
__global__ __launch_bounds__(256) void pool_kernel(const float* __restrict__ hf,
                                                   float* __restrict__ pool)
{
    int c = blockIdx.x, b = blockIdx.y, tid = threadIdx.x;
    const float* row = hf + ((long)b * 1024 + c) * NPTS;
    float m = -1e30f, sum = 0.f;
    for (int n = tid; n < NPTS; n += 256) {
        float v = row[n];
        m = fmaxf(m, v);
        sum += v;
    }
    __shared__ float sm[256], ss[256];
    sm[tid] = m; ss[tid] = sum; __syncthreads();
    for (int st = 128; st > 0; st >>= 1) {
        if (tid < st) {
            sm[tid] = fmaxf(sm[tid], sm[tid + st]);
            ss[tid] += ss[tid + st];
        }
        __syncthreads();
    }
    if (tid == 0) {
        pool[b * 2048 + c]        = sm[0];
        pool[b * 2048 + 1024 + c] = ss[0] * (1.f / NPTS);
    }
}

__global__ __launch_bounds__(256) void pbias_kernel(const float* __restrict__ ws1,
                                                    const float* __restrict__ bs1,
                                                    const float* __restrict__ pool,
                                                    float* __restrict__ pbias)
{
    int o = blockIdx.x, b = blockIdx.y, tid = threadIdx.x;
    float acc = 0.f;
    for (int c = tid; c < 1024; c += 256) {
        acc += ws1[(long)o * 3072 + 1024 + c] * pool[b * 2048 + c];
        acc += ws1[(long)o * 3072 + 2048 + c] * pool[b * 2048 + 1024 + c];
    }
    __shared__ float red[256];
    red[tid] = acc; __syncthreads();
    for (int st = 128; st > 0; st >>= 1) {
        if (tid < st) red[tid] += red[tid + st];
        __syncthreads();
    }
    if (tid == 0) pbias[b * 512 + o] = bs1[o] + red[0];
}

__global__ __launch_bounds__(128) void final_kernel(const float* __restrict__ h256,
                                                    const float* __restrict__ ws3,
                                                    const float* __restrict__ bs3,
                                                    float* __restrict__ out)
{
    __shared__ float Wsh[8][256];
    int tid = threadIdx.x;
    for (int l = tid; l < 2048; l += 128) Wsh[l >> 8][l & 255] = ws3[l];
    __syncthreads();

    int n = blockIdx.x * 128 + tid;
    int b = blockIdx.y;
    const float* hb = h256 + (long)b * 256 * NPTS;

    float acc[8];
    #pragma unroll
    for (int k = 0; k < 8; k++) acc[k] = bs3[k];
    for (int c = 0; c < 256; c++) {
        float xv = hb[(long)c * NPTS + n];
        #pragma unroll
        for (int k = 0; k < 8; k++) acc[k] += Wsh[k][c] * xv;
    }
    float m = acc[0];
    #pragma unroll
    for (int k = 1; k < 8; k++) m = fmaxf(m, acc[k]);
    float s = 0.f;
    #pragma unroll
    for (int k = 0; k < 8; k++) s += __expf(acc[k] - m);
    float lse = m + logf(s);
    float* op = out + ((long)b * NPTS + n) * 8;
    #pragma unroll
    for (int k = 0; k < 8; k++) op[k] = acc[k] - lse;
}

// ---------------------------------------------------------------------------
// Host orchestration
// ---------------------------------------------------------------------------
static inline void launch_gemm64(const float* W, int ldW,
                                 const float* X, long sX,
                                 float* Y, long sY, int O, int C,
                                 const float* cb, int cbs,
                                 const float* sc, const float* bi, int act,
                                 const float* res, long sres)
{
    dim3 grid(NPTS / 64, (O + 127) / 128, NB);
    gemm_kernel<64><<<grid, 256>>>(W, ldW, X, sX, Y, sY, O, C,
                                   cb, cbs, sc, bi, act, res, sres);
}

static inline void launch_tc(const float* W, int ldW,
                             const float* X, long sX,
                             float* Y, long sY, int O, int C,
                             const float* cb, int cbs,
                             const float* sc, const float* bi, int act,
                             const float* res, long sres,
                             const float* colScale)
{
    dim3 grid(NPTS / 128, O / 128, NB);
    tc_gemm_kernel<<<grid, 256, TCSM>>>(W, ldW, X, sX, Y, sY, C,
                                        cb, cbs, sc, bi, act, res, sres, colScale);
}

extern "C" void kernel_launch(void* const* d_in, const int* in_sizes, int n_in,
                              void* d_out, int out_size)
{
    (void)in_sizes; (void)n_in; (void)out_size;

    cudaFuncSetAttribute((const void*)tc_gemm_kernel,
                         cudaFuncAttributeMaxDynamicSharedMemorySize, TCSM);
    cudaFuncSetAttribute((const void*)tc_apply_kernel,
                         cudaFuncAttributeMaxDynamicSharedMemorySize, TCSM);

    const float* x      = (const float*)d_in[0];
    const float* w1     = (const float*)d_in[1];
    const float* bn1_g  = (const float*)d_in[2];
    const float* bn1_b  = (const float*)d_in[3];
    const float* w2     = (const float*)d_in[4];
    const float* bn2_g  = (const float*)d_in[5];
    const float* bn2_b  = (const float*)d_in[6];
    const float* sa_wqk = (const float*)d_in[7];
    const float* sa_wv  = (const float*)d_in[8];
    const float* sa_bv  = (const float*)d_in[9];
    const float* sa_wt  = (const float*)d_in[10];
    const float* sa_bt  = (const float*)d_in[11];
    const float* sa_bng = (const float*)d_in[12];
    const float* sa_bnb = (const float*)d_in[13];
    const float* wf     = (const float*)d_in[14];
    const float* bnf_g  = (const float*)d_in[15];
    const float* bnf_b  = (const float*)d_in[16];
    const float* ws1    = (const float*)d_in[17];
    const float* bs1    = (const float*)d_in[18];
    const float* bns1_g = (const float*)d_in[19];
    const float* bns1_b = (const float*)d_in[20];
    const float* ws2    = (const float*)d_in[21];
    const float* bs2    = (const float*)d_in[22];
    const float* bns2_g = (const float*)d_in[23];
    const float* bns2_b = (const float*)d_in[24];
    const float* ws3    = (const float*)d_in[25];
    const float* bs3    = (const float*)d_in[26];

    float *p_h1, *p_h0, *p_q, *p_v, *p_E, *p_t, *p_feats, *p_hf, *p_pool,
          *p_pbias, *p_h512, *p_h256, *p_pOut, *p_pSum, *p_m, *p_s, *p_invs;
    cudaGetSymbolAddress((void**)&p_h1,    g_h1);
    cudaGetSymbolAddress((void**)&p_h0,    g_h0);
    cudaGetSymbolAddress((void**)&p_q,     g_q);
    cudaGetSymbolAddress((void**)&p_v,     g_v);
    cudaGetSymbolAddress((void**)&p_E,     g_E);
    cudaGetSymbolAddress((void**)&p_t,     g_t);
    cudaGetSymbolAddress((void**)&p_feats, g_feats);
    cudaGetSymbolAddress((void**)&p_hf,    g_hf);
    cudaGetSymbolAddress((void**)&p_pool,  g_pool);
    cudaGetSymbolAddress((void**)&p_pbias, g_pbias);
    cudaGetSymbolAddress((void**)&p_h512,  g_h512);
    cudaGetSymbolAddress((void**)&p_h256,  g_h256);
    cudaGetSymbolAddress((void**)&p_pOut,  g_pOut);
    cudaGetSymbolAddress((void**)&p_pSum,  g_pSum);
    cudaGetSymbolAddress((void**)&p_m,     g_m);
    cudaGetSymbolAddress((void**)&p_s,     g_s);
    cudaGetSymbolAddress((void**)&p_invs,  g_invs);

    // input MLP
    mlp1_kernel<<<dim3(NPTS / 256, 128, NB), 256>>>(x, w1, bn1_g, bn1_b, p_h1);
    launch_tc(w2, 128, p_h1, 128L * NPTS, p_h0, 128L * NPTS, 128, 128,
              0, 0, bn2_g, bn2_b, 1, 0, 0, 0);

    // 4 self-attention layers
    for (int i = 0; i < 4; i++) {
        const float* h   = (i == 0) ? p_h0 : (p_feats + (long)(i - 1) * 128 * NPTS);
        long hStride     = (i == 0) ? 128L * NPTS : 512L * NPTS;

        // q = wqk_i @ h  (FFMA2, O=32)
        launch_gemm64(sa_wqk + (long)i * 32 * 128, 128, h, hStride,
                      p_q, 32L * NPTS, 32, 128, 0, 0, 0, 0, 0, 0, 0);

        // fused energy/softmax: row maxes, P = exp(E - m), row sums, invs
        zero2_kernel<<<(NB * NPTS + 255) / 256, 256>>>(p_m, p_s, NB * NPTS);
        emax_kernel<<<dim3(64, 64, NB), 256>>>(p_q, p_m);
        pexp_kernel<<<dim3(64, 64, NB), 256>>>(p_q, p_m, p_E, p_s);
        inv_kernel<<<(NB * NPTS + 255) / 256, 256>>>(p_s, p_invs, NB * NPTS);

        // v' = (wv_i @ h + bv_i) * invs[n]   [TC, row-norm folded into V]
        launch_tc(sa_wv + (long)i * 128 * 128, 128, h, hStride,
                  p_v, 128L * NPTS, 128, 128,
                  sa_bv + (long)i * 128, 0, 0, 0, 0, 0, 0, p_invs);

        // K-split apply: pOut = V' @ P, pSum = colsum(attn); then reduce
        tc_apply_kernel<<<dim3(NPTS / 128, KS, NB), 256, TCSM>>>(p_v, p_E, p_invs,
                                                                 p_pOut, p_pSum);
        apply_reduce_kernel<<<dim3(NPTS / 256, 128, NB), 256>>>(p_pOut, p_pSum,
                                                                h, hStride, p_t);

        // h_new = relu(bn(wt_i @ t + bt_i)) + h   [TC]
        launch_tc(sa_wt + (long)i * 128 * 128, 128, p_t, 128L * NPTS,
                  p_feats + (long)i * 128 * NPTS, 512L * NPTS, 128, 128,
                  sa_bt + (long)i * 128, 0,
                  sa_bng + (long)i * 128, sa_bnb + (long)i * 128, 1,
                  h, hStride, 0);
    }

    // hf = leaky_relu(bn(wf @ feats), 0.2)   [TC]
    launch_tc(wf, 512, p_feats, 512L * NPTS, p_hf, 1024L * NPTS, 1024, 512,
              0, 0, bnf_g, bnf_b, 2, 0, 0, 0);

    // pooling + folded per-batch bias for ws1
    pool_kernel<<<dim3(1024, NB), 256>>>(p_hf, p_pool);
    pbias_kernel<<<dim3(512, NB), 256>>>(ws1, bs1, p_pool, p_pbias);

    // h512 = relu(bn(ws1[:, :1024] @ hf + pbias))   [TC]
    launch_tc(ws1, 3072, p_hf, 1024L * NPTS, p_h512, 512L * NPTS, 512, 1024,
              p_pbias, 512, bns1_g, bns1_b, 1, 0, 0, 0);

    // h256 = relu(bn(ws2 @ h512 + bs2))   [TC]
    launch_tc(ws2, 512, p_h512, 512L * NPTS, p_h256, 256L * NPTS, 256, 512,
              bs2, 0, bns2_g, bns2_b, 1, 0, 0, 0);

    // logits + log_softmax + transpose
    final_kernel<<<dim3(NPTS / 128, NB), 128>>>(p_h256, ws3, bs3, (float*)d_out);
}

// round 15
// speedup vs baseline: 1.1721x; 1.1604x over previous
#include <cuda_runtime.h>
#include <math.h>

#define NPTS 4096
#define NB   2
#define KS   8
#define KC   (NPTS / KS)     // 512
#define RSQ  0.99999500003749968f   // 1/sqrt(1 + 1e-5)

// ---------------------------------------------------------------------------
// Packed fp32x2 helpers (Blackwell FFMA2 — only reachable via PTX)
// ---------------------------------------------------------------------------
__device__ __forceinline__ unsigned long long pack2(float x, float y) {
    unsigned long long r;
    asm("mov.b64 %0, {%1, %2};" : "=l"(r) : "f"(x), "f"(y));
    return r;
}
__device__ __forceinline__ void ffma2(unsigned long long& d,
                                      unsigned long long a,
                                      unsigned long long b) {
    asm("fma.rn.f32x2 %0, %1, %2, %0;" : "+l"(d) : "l"(a), "l"(b));
}
__device__ __forceinline__ float2 unpack2(unsigned long long v) {
    float2 f;
    asm("mov.b64 {%0, %1}, %2;" : "=f"(f.x), "=f"(f.y) : "l"(v));
    return f;
}

// ---------------------------------------------------------------------------
// TF32 tensor-core helpers (3xTF32 error-compensated path)
// ---------------------------------------------------------------------------
__device__ __forceinline__ unsigned f2tf(float f) {
    unsigned r;
    asm("cvt.rna.tf32.f32 %0, %1;" : "=r"(r) : "f"(f));
    return r;
}
__device__ __forceinline__ void split_tf(float f, unsigned& hi, unsigned& lo) {
    hi = f2tf(f);
    lo = f2tf(f - __uint_as_float(hi));
}
__device__ __forceinline__ void mma_tf32(float* d, const unsigned* a, const unsigned* b) {
    asm("mma.sync.aligned.m16n8k8.row.col.f32.tf32.tf32.f32 "
        "{%0,%1,%2,%3}, {%4,%5,%6,%7}, {%8,%9}, {%0,%1,%2,%3};"
        : "+f"(d[0]), "+f"(d[1]), "+f"(d[2]), "+f"(d[3])
        : "r"(a[0]), "r"(a[1]), "r"(a[2]), "r"(a[3]), "r"(b[0]), "r"(b[1]));
}

// ---------------------------------------------------------------------------
// Scratch (static __device__ globals; no allocations anywhere)
// ---------------------------------------------------------------------------
__device__ float g_h1   [NB * 128  * NPTS];
__device__ float g_h0   [NB * 128  * NPTS];
__device__ float g_q    [NB * 32   * NPTS];
__device__ float g_v    [NB * 128  * NPTS];
__device__ float g_E    [(size_t)NB * NPTS * NPTS];   // holds unnormalized P
__device__ float g_t    [NB * 128  * NPTS];
__device__ float g_feats[NB * 512  * NPTS];
__device__ float g_hf   [NB * 1024 * NPTS];
__device__ float g_pool [NB * 2048];
__device__ float g_pbias[NB * 512];
__device__ float g_h512 [NB * 512  * NPTS];
__device__ float g_h256 [NB * 256  * NPTS];
__device__ float g_pOut [KS * NB * 128 * NPTS];       // apply partials
__device__ float g_pSum [KS * NB * NPTS];             // colsum partials
__device__ float g_nq2  [NB * NPTS];                  // ||q_i||^2
__device__ float g_nq2M [NB];                         // max_i ||q_i||^2
__device__ float g_s    [NB * NPTS];                  // row exp-sums
__device__ float g_invs [NB * NPTS];                  // 1/s

// ---------------------------------------------------------------------------
// Input MLP stage 1: h1 = relu(bn1(w1 @ x[:,9:12,:]))
// ---------------------------------------------------------------------------
__global__ void mlp1_kernel(const float* __restrict__ x, const float* __restrict__ w1,
                            const float* __restrict__ g, const float* __restrict__ bb,
                            float* __restrict__ h1)
{
    int n = blockIdx.x * 256 + threadIdx.x;
    int c = blockIdx.y;
    int b = blockIdx.z;
    float x0 = x[((long)b * 15 +  9) * NPTS + n];
    float x1 = x[((long)b * 15 + 10) * NPTS + n];
    float x2 = x[((long)b * 15 + 11) * NPTS + n];
    float acc = w1[c*3+0]*x0 + w1[c*3+1]*x1 + w1[c*3+2]*x2;
    acc = acc * (g[c] * RSQ) + bb[c];
    h1[((long)b * 128 + c) * NPTS + n] = fmaxf(acc, 0.f);
}

// ---------------------------------------------------------------------------
// FFMA2 GEMM (small convs: q, v, wt, w2)
// ---------------------------------------------------------------------------
template<int TN>
__global__ __launch_bounds__(256) void gemm_kernel(
    const float* __restrict__ W, int ldW,
    const float* __restrict__ X, long strideX,
    float* __restrict__ Y, long strideY,
    int O, int C,
    const float* __restrict__ convBias, int convBiasStride,
    const float* __restrict__ scale,
    const float* __restrict__ bias,
    int act,
    const float* __restrict__ resid, long strideResid)
{
    constexpr int CT = TN / 16;
    constexpr int XL = (4 * TN) / 256;
    const int bN = blockIdx.x * TN;
    const int bM = blockIdx.y * 128;
    const int b  = blockIdx.z;
    const float* Wb = W;
    const float* Xb = X + (long)b * strideX;

    __shared__ __align__(16) float Ws[2][16][128];
    __shared__ __align__(16) float Xs[2][16][TN];

    const int tid = threadIdx.x;
    const int tm0 = (tid >> 4) * 4;
    const int tn0 = (tid & 15) * 4;

    const int wm  = tid >> 2;
    const int wkq = (tid & 3) * 4;
    int xk[XL], xn[XL];
    #pragma unroll
    for (int l = 0; l < XL; l++) {
        int idx = tid + l * 256;
        xk[l] = idx / (TN / 4);
        xn[l] = (idx % (TN / 4)) * 4;
    }

    unsigned long long acc2[4][CT];
    #pragma unroll
    for (int i = 0; i < 4; i++)
        #pragma unroll
        for (int j = 0; j < CT; j++) acc2[i][j] = 0ull;

    float4 wr0, wr1, xr[XL];
    const int T = C / 16;

    {
        wr0 = make_float4(0.f,0.f,0.f,0.f);
        wr1 = make_float4(0.f,0.f,0.f,0.f);
        if (bM + wm      < O) wr0 = *(const float4*)&Wb[(long)(bM + wm     ) * ldW + wkq];
        if (bM + wm + 64 < O) wr1 = *(const float4*)&Wb[(long)(bM + wm + 64) * ldW + wkq];
        #pragma unroll
        for (int l = 0; l < XL; l++)
            xr[l] = *(const float4*)&Xb[(long)xk[l] * NPTS + bN + xn[l]];
        Ws[0][wkq+0][wm] = wr0.x; Ws[0][wkq+1][wm] = wr0.y;
        Ws[0][wkq+2][wm] = wr0.z; Ws[0][wkq+3][wm] = wr0.w;
        Ws[0][wkq+0][wm+64] = wr1.x; Ws[0][wkq+1][wm+64] = wr1.y;
        Ws[0][wkq+2][wm+64] = wr1.z; Ws[0][wkq+3][wm+64] = wr1.w;
        #pragma unroll
        for (int l = 0; l < XL; l++)
            *(float4*)&Xs[0][xk[l]][xn[l]] = xr[l];
    }
    __syncthreads();

    for (int t = 0; t < T; t++) {
        const int cur = t & 1;
        const int nxt = cur ^ 1;
        const bool more = (t + 1 < T);

        if (more) {
            int k0 = (t + 1) * 16;
            wr0 = make_float4(0.f,0.f,0.f,0.f);
            wr1 = make_float4(0.f,0.f,0.f,0.f);
            if (bM + wm      < O) wr0 = *(const float4*)&Wb[(long)(bM + wm     ) * ldW + k0 + wkq];
            if (bM + wm + 64 < O) wr1 = *(const float4*)&Wb[(long)(bM + wm + 64) * ldW + k0 + wkq];
            #pragma unroll
            for (int l = 0; l < XL; l++)
                xr[l] = *(const float4*)&Xb[(long)(k0 + xk[l]) * NPTS + bN + xn[l]];
        }

        #pragma unroll
        for (int k = 0; k < 16; k++) {
            ulonglong2 a01 = *(const ulonglong2*)&Ws[cur][k][tm0];
            ulonglong2 a23 = *(const ulonglong2*)&Ws[cur][k][tm0 + 64];
            unsigned long long ap[4] = {a01.x, a01.y, a23.x, a23.y};
            float xv[CT];
            float4 x0 = *(const float4*)&Xs[cur][k][tn0];
            xv[0] = x0.x; xv[1] = x0.y; xv[2] = x0.z; xv[3] = x0.w;
            if (CT == 8) {
                float4 x1 = *(const float4*)&Xs[cur][k][tn0 + 64];
                xv[4] = x1.x; xv[5] = x1.y; xv[6] = x1.z; xv[7] = x1.w;
            }
            unsigned long long bs[CT];
            #pragma unroll
            for (int c = 0; c < CT; c++) bs[c] = pack2(xv[c], xv[c]);
            #pragma unroll
            for (int mp = 0; mp < 4; mp++)
                #pragma unroll
                for (int c = 0; c < CT; c++)
                    ffma2(acc2[mp][c], ap[mp], bs[c]);
        }

        if (more) {
            Ws[nxt][wkq+0][wm] = wr0.x; Ws[nxt][wkq+1][wm] = wr0.y;
            Ws[nxt][wkq+2][wm] = wr0.z; Ws[nxt][wkq+3][wm] = wr0.w;
            Ws[nxt][wkq+0][wm+64] = wr1.x; Ws[nxt][wkq+1][wm+64] = wr1.y;
            Ws[nxt][wkq+2][wm+64] = wr1.z; Ws[nxt][wkq+3][wm+64] = wr1.w;
            #pragma unroll
            for (int l = 0; l < XL; l++)
                *(float4*)&Xs[nxt][xk[l]][xn[l]] = xr[l];
            __syncthreads();
        }
    }

    #pragma unroll
    for (int mp = 0; mp < 4; mp++) {
        int rowbase = bM + tm0 + ((mp >= 2) ? 64 : 0) + (mp & 1) * 2;
        #pragma unroll
        for (int sub = 0; sub < 2; sub++) {
            int o = rowbase + sub;
            if (o >= O) continue;
            float cb = convBias ? convBias[b * convBiasStride + o] : 0.f;
            float sc = scale ? scale[o] * RSQ : 1.f;
            float bi = bias ? bias[o] : 0.f;
            float* Yrow = Y + (long)b * strideY + (long)o * NPTS;
            const float* resRow = resid ? (resid + (long)b * strideResid + (long)o * NPTS) : (const float*)0;
            #pragma unroll
            for (int c = 0; c < CT; c++) {
                int n = bN + tn0 + ((c < 4) ? c : (64 + c - 4));
                float2 pr = unpack2(acc2[mp][c]);
                float v = sub ? pr.y : pr.x;
                v = (v + cb) * sc + bi;
                if (act == 1)      v = fmaxf(v, 0.f);
                else if (act == 2) v = (v > 0.f) ? v : 0.2f * v;
                if (resRow) v += resRow[n];
                Yrow[n] = v;
            }
        }
    }
}

// ---------------------------------------------------------------------------
// TC GEMM (3xTF32, m16n8k8): 256 threads, 8 warps = 2(M)x4(N),
// warp tile 64x32 (4 m16 x 4 n8), in-register splits. 2 blocks/SM target.
// ---------------------------------------------------------------------------
__global__ __launch_bounds__(256, 2) void tc_gemm_kernel(
    const float* __restrict__ W, int ldW,
    const float* __restrict__ X, long strideX,
    float* __restrict__ Y, long strideY,
    int C,
    const float* __restrict__ convBias, int convBiasStride,
    const float* __restrict__ scale,
    const float* __restrict__ bias,
    int act)
{
    const int bN = blockIdx.x * 128;
    const int bM = blockIdx.y * 128;
    const int b  = blockIdx.z;
    const float* Wb = W;
    const float* Xb = X + (long)b * strideX;

    __shared__ __align__(16) float Ws[2][16][132];
    __shared__ __align__(16) float Xs[2][16][132];

    const int tid    = threadIdx.x;
    const int wid    = tid >> 5;
    const int lane   = tid & 31;
    const int warp_m = wid >> 2;       // 0..1
    const int warp_n = wid & 3;        // 0..3

    const int wm  = tid >> 2;          // 0..63
    const int wkq = (tid & 3) * 4;
    const int xka = tid >> 5, xna = (tid & 31) * 4;   // k 0..7
    const int xkb = xka + 8;                          // k 8..15

    float acc[4][4][4];
    #pragma unroll
    for (int mi = 0; mi < 4; mi++)
        #pragma unroll
        for (int ni = 0; ni < 4; ni++)
            #pragma unroll
            for (int r = 0; r < 4; r++) acc[mi][ni][r] = 0.f;

    float4 wr0, wr1, xr0, xr1;
    const int T = C / 16;

    {
        wr0 = *(const float4*)&Wb[(long)(bM + wm     ) * ldW + wkq];
        wr1 = *(const float4*)&Wb[(long)(bM + wm + 64) * ldW + wkq];
        xr0 = *(const float4*)&Xb[(long)xka * NPTS + bN + xna];
        xr1 = *(const float4*)&Xb[(long)xkb * NPTS + bN + xna];
        Ws[0][wkq+0][wm] = wr0.x; Ws[0][wkq+1][wm] = wr0.y;
        Ws[0][wkq+2][wm] = wr0.z; Ws[0][wkq+3][wm] = wr0.w;
        Ws[0][wkq+0][wm+64] = wr1.x; Ws[0][wkq+1][wm+64] = wr1.y;
        Ws[0][wkq+2][wm+64] = wr1.z; Ws[0][wkq+3][wm+64] = wr1.w;
        *(float4*)&Xs[0][xka][xna] = xr0;
        *(float4*)&Xs[0][xkb][xna] = xr1;
    }
    __syncthreads();

    const int alr = lane >> 2;   // 0..7
    const int akc = lane & 3;    // 0..3
    const int bnr = warp_n * 32 + (lane >> 2);

    for (int t = 0; t < T; t++) {
        const int cur = t & 1;
        const int nxt = cur ^ 1;
        const bool more = (t + 1 < T);

        if (more) {
            int k0 = (t + 1) * 16;
            wr0 = *(const float4*)&Wb[(long)(bM + wm     ) * ldW + k0 + wkq];
            wr1 = *(const float4*)&Wb[(long)(bM + wm + 64) * ldW + k0 + wkq];
            xr0 = *(const float4*)&Xb[(long)(k0 + xka) * NPTS + bN + xna];
            xr1 = *(const float4*)&Xb[(long)(k0 + xkb) * NPTS + bN + xna];
        }

        #pragma unroll
        for (int kk = 0; kk < 2; kk++) {
            const int k0 = kk * 8;
            unsigned bh[4][2], bl[4][2];
            #pragma unroll
            for (int ni = 0; ni < 4; ni++) {
                #pragma unroll
                for (int r = 0; r < 2; r++) {
                    float f = Xs[cur][k0 + akc + r*4][bnr + ni*8];
                    split_tf(f, bh[ni][r], bl[ni][r]);
                }
            }
            #pragma unroll
            for (int mi = 0; mi < 4; mi++) {
                int m0 = warp_m * 64 + mi * 16 + alr;
                float f0 = Ws[cur][k0 + akc    ][m0];
                float f1 = Ws[cur][k0 + akc    ][m0 + 8];
                float f2 = Ws[cur][k0 + akc + 4][m0];
                float f3 = Ws[cur][k0 + akc + 4][m0 + 8];
                unsigned ah[4], al[4];
                split_tf(f0, ah[0], al[0]);
                split_tf(f1, ah[1], al[1]);
                split_tf(f2, ah[2], al[2]);
                split_tf(f3, ah[3], al[3]);
                #pragma unroll
                for (int ni = 0; ni < 4; ni++) {
                    mma_tf32(acc[mi][ni], ah, bh[ni]);
                    mma_tf32(acc[mi][ni], al, bh[ni]);
                    mma_tf32(acc[mi][ni], ah, bl[ni]);
                }
            }
        }

        if (more) {
            Ws[nxt][wkq+0][wm] = wr0.x; Ws[nxt][wkq+1][wm] = wr0.y;
            Ws[nxt][wkq+2][wm] = wr0.z; Ws[nxt][wkq+3][wm] = wr0.w;
            Ws[nxt][wkq+0][wm+64] = wr1.x; Ws[nxt][wkq+1][wm+64] = wr1.y;
            Ws[nxt][wkq+2][wm+64] = wr1.z; Ws[nxt][wkq+3][wm+64] = wr1.w;
            *(float4*)&Xs[nxt][xka][xna] = xr0;
            *(float4*)&Xs[nxt][xkb][xna] = xr1;
            __syncthreads();
        }
    }

    // epilogue
    #pragma unroll
    for (int mi = 0; mi < 4; mi++) {
        #pragma unroll
        for (int rr = 0; rr < 2; rr++) {
            int o = bM + warp_m * 64 + mi * 16 + (lane >> 2) + rr * 8;
            float cb = convBias ? convBias[b * convBiasStride + o] : 0.f;
            float sc = scale ? scale[o] * RSQ : 1.f;
            float bi = bias ? bias[o] : 0.f;
            float* Yrow = Y + (long)b * strideY + (long)o * NPTS;
            #pragma unroll
            for (int ni = 0; ni < 4; ni++) {
                int col = bN + warp_n * 32 + ni * 8 + (lane & 3) * 2;
                #pragma unroll
                for (int cc = 0; cc < 2; cc++) {
                    float v = acc[mi][ni][rr * 2 + cc];
                    v = (v + cb) * sc + bi;
                    if (act == 1)      v = fmaxf(v, 0.f);
                    else if (act == 2) v = (v > 0.f) ? v : 0.2f * v;
                    Yrow[col + cc] = v;
                }
            }
        }
    }
}

// ---------------------------------------------------------------------------
// TC apply (K-split, fused colsum): A rows scaled by invs at load time, so
// smem holds true attention values A = P/s. partial = sum_chunk V·A.
// ---------------------------------------------------------------------------
__global__ __launch_bounds__(256, 2) void tc_apply_kernel(
    const float* __restrict__ V,
    const float* __restrict__ A,
    const float* __restrict__ invs,
    float* __restrict__ pOut,
    float* __restrict__ pSum)
{
    const int bN = blockIdx.x * 128;
    const int ks = blockIdx.y;
    const int b  = blockIdx.z;
    const float* Wb = V + (long)b * 128 * NPTS + (long)ks * KC;
    const float* Xb = A + (long)b * NPTS * NPTS + (long)ks * KC * NPTS;
    const float* invb = invs + (long)b * NPTS + (long)ks * KC;

    __shared__ __align__(16) float Ws[2][16][132];
    __shared__ __align__(16) float Xs[2][16][132];

    const int tid    = threadIdx.x;
    const int wid    = tid >> 5;
    const int lane   = tid & 31;
    const int warp_m = wid >> 2;
    const int warp_n = wid & 3;

    const int wm  = tid >> 2;
    const int wkq = (tid & 3) * 4;
    const int xka = tid >> 5, xna = (tid & 31) * 4;
    const int xkb = xka + 8;

    float acc[4][4][4];
    #pragma unroll
    for (int mi = 0; mi < 4; mi++)
        #pragma unroll
        for (int ni = 0; ni < 4; ni++)
            #pragma unroll
            for (int r = 0; r < 4; r++) acc[mi][ni][r] = 0.f;
    float ssum = 0.f;

    float4 wr0, wr1, xr0, xr1;

    {
        float ia = invb[xka], ib = invb[xkb];
        wr0 = *(const float4*)&Wb[(long)(wm     ) * NPTS + wkq];
        wr1 = *(const float4*)&Wb[(long)(wm + 64) * NPTS + wkq];
        xr0 = *(const float4*)&Xb[(long)xka * NPTS + bN + xna];
        xr1 = *(const float4*)&Xb[(long)xkb * NPTS + bN + xna];
        xr0.x *= ia; xr0.y *= ia; xr0.z *= ia; xr0.w *= ia;
        xr1.x *= ib; xr1.y *= ib; xr1.z *= ib; xr1.w *= ib;
        Ws[0][wkq+0][wm] = wr0.x; Ws[0][wkq+1][wm] = wr0.y;
        Ws[0][wkq+2][wm] = wr0.z; Ws[0][wkq+3][wm] = wr0.w;
        Ws[0][wkq+0][wm+64] = wr1.x; Ws[0][wkq+1][wm+64] = wr1.y;
        Ws[0][wkq+2][wm+64] = wr1.z; Ws[0][wkq+3][wm+64] = wr1.w;
        *(float4*)&Xs[0][xka][xna] = xr0;
        *(float4*)&Xs[0][xkb][xna] = xr1;
    }
    __syncthreads();

    const int alr = lane >> 2;
    const int akc = lane & 3;
    const int bnr = warp_n * 32 + (lane >> 2);

    const int T = KC / 16;
    for (int t = 0; t < T; t++) {
        const int cur = t & 1;
        const int nxt = cur ^ 1;
        const bool more = (t + 1 < T);

        if (more) {
            int k0 = (t + 1) * 16;
            float ia = invb[k0 + xka], ib = invb[k0 + xkb];
            wr0 = *(const float4*)&Wb[(long)(wm     ) * NPTS + k0 + wkq];
            wr1 = *(const float4*)&Wb[(long)(wm + 64) * NPTS + k0 + wkq];
            xr0 = *(const float4*)&Xb[(long)(k0 + xka) * NPTS + bN + xna];
            xr1 = *(const float4*)&Xb[(long)(k0 + xkb) * NPTS + bN + xna];
            xr0.x *= ia; xr0.y *= ia; xr0.z *= ia; xr0.w *= ia;
            xr1.x *= ib; xr1.y *= ib; xr1.z *= ib; xr1.w *= ib;
        }

        #pragma unroll
        for (int kk = 0; kk < 2; kk++) {
            const int k0 = kk * 8;
            unsigned bh[4][2], bl[4][2];
            #pragma unroll
            for (int ni = 0; ni < 4; ni++) {
                #pragma unroll
                for (int r = 0; r < 2; r++) {
                    float f = Xs[cur][k0 + akc + r*4][bnr + ni*8];
                    split_tf(f, bh[ni][r], bl[ni][r]);
                }
            }
            #pragma unroll
            for (int mi = 0; mi < 4; mi++) {
                int m0 = warp_m * 64 + mi * 16 + alr;
                float f0 = Ws[cur][k0 + akc    ][m0];
                float f1 = Ws[cur][k0 + akc    ][m0 + 8];
                float f2 = Ws[cur][k0 + akc + 4][m0];
                float f3 = Ws[cur][k0 + akc + 4][m0 + 8];
                unsigned ah[4], al[4];
                split_tf(f0, ah[0], al[0]);
                split_tf(f1, ah[1], al[1]);
                split_tf(f2, ah[2], al[2]);
                split_tf(f3, ah[3], al[3]);
                #pragma unroll
                for (int ni = 0; ni < 4; ni++) {
                    mma_tf32(acc[mi][ni], ah, bh[ni]);
                    mma_tf32(acc[mi][ni], al, bh[ni]);
                    mma_tf32(acc[mi][ni], ah, bl[ni]);
                }
            }
        }

        // fused colsum over true A values (threads 0..127, one column each)
        if (tid < 128) {
            float s = 0.f;
            #pragma unroll
            for (int k = 0; k < 16; k++) s += Xs[cur][k][tid];
            ssum += s;
        }

        if (more) {
            Ws[nxt][wkq+0][wm] = wr0.x; Ws[nxt][wkq+1][wm] = wr0.y;
            Ws[nxt][wkq+2][wm] = wr0.z; Ws[nxt][wkq+3][wm] = wr0.w;
            Ws[nxt][wkq+0][wm+64] = wr1.x; Ws[nxt][wkq+1][wm+64] = wr1.y;
            Ws[nxt][wkq+2][wm+64] = wr1.z; Ws[nxt][wkq+3][wm+64] = wr1.w;
            *(float4*)&Xs[nxt][xka][xna] = xr0;
            *(float4*)&Xs[nxt][xkb][xna] = xr1;
            __syncthreads();
        }
    }

    float* Ob = pOut + ((long)(ks * NB + b) * 128) * NPTS;
    #pragma unroll
    for (int mi = 0; mi < 4; mi++) {
        #pragma unroll
        for (int rr = 0; rr < 2; rr++) {
            int o = warp_m * 64 + mi * 16 + (lane >> 2) + rr * 8;
            float* Yrow = Ob + (long)o * NPTS;
            #pragma unroll
            for (int ni = 0; ni < 4; ni++) {
                int col = bN + warp_n * 32 + ni * 8 + (lane & 3) * 2;
                Yrow[col]     = acc[mi][ni][rr * 2];
                Yrow[col + 1] = acc[mi][ni][rr * 2 + 1];
            }
        }
    }
    if (tid < 128)
        pSum[(long)(ks * NB + b) * NPTS + bN + tid] = ssum;
}

// ---------------------------------------------------------------------------
// Apply reduce: t[b,c,n] = h[b,c,n] - (sum_ks pOut)/(1e-9 + sum_ks pSum)
// ---------------------------------------------------------------------------
__global__ __launch_bounds__(256) void apply_reduce_kernel(
    const float* __restrict__ pOut, const float* __restrict__ pSum,
    const float* __restrict__ h, long hStride, float* __restrict__ t)
{
    int n = blockIdx.x * 256 + threadIdx.x;
    int c = blockIdx.y;
    int b = blockIdx.z;
    float num = 0.f, den = 0.f;
    #pragma unroll
    for (int ks = 0; ks < KS; ks++) {
        num += pOut[((long)(ks * NB + b) * 128 + c) * NPTS + n];
        den += pSum[(long)(ks * NB + b) * NPTS + n];
    }
    t[((long)b * 128 + c) * NPTS + n] =
        h[(long)b * hStride + (long)c * NPTS + n] - num / (1e-9f + den);
}

// ---------------------------------------------------------------------------
// qnorm: nq2[i] = ||q_i||^2 and per-batch max (atomicMax on int bits; values
// are >= 0 and nq2M is zero-initialized, so signed-int ordering is correct).
// ---------------------------------------------------------------------------
__global__ __launch_bounds__(256) void qnorm_kernel(const float* __restrict__ q,
                                                    float* __restrict__ nq2,
                                                    float* __restrict__ nq2M)
{
    int i = blockIdx.x * 256 + threadIdx.x;
    int b = blockIdx.y;
    const float* Q = q + (long)b * 32 * NPTS;
    float s = 0.f;
    #pragma unroll
    for (int d = 0; d < 32; d++) {
        float v = Q[(long)d * NPTS + i];
        s += v * v;
    }
    nq2[b * NPTS + i] = s;

    __shared__ float red[256];
    int tid = threadIdx.x;
    red[tid] = s; __syncthreads();
    for (int st = 128; st > 0; st >>= 1) {
        if (tid < st) red[tid] = fmaxf(red[tid], red[tid + st]);
        __syncthreads();
    }
    if (tid == 0) atomicMax((int*)&nq2M[b], __float_as_int(red[0]));
}

// ---------------------------------------------------------------------------
// pexp: compute E tile, write P = exp(E - m_i) with the Cauchy-Schwarz shift
// m_i = ||q_i|| * max_j ||q_j||  (>= row max; softmax is shift-invariant),
// accumulate row sums via atomicAdd.
// ---------------------------------------------------------------------------
__global__ __launch_bounds__(256) void pexp_kernel(const float* __restrict__ q,
                                                   const float* __restrict__ nq2,
                                                   const float* __restrict__ nq2M,
                                                   float* __restrict__ P,
                                                   float* __restrict__ s)
{
    int bj = blockIdx.x * 64;
    int bi = blockIdx.y * 64;
    int b  = blockIdx.z;
    const float* Q = q + (long)b * 32 * NPTS;
    float* Pb = P + (long)b * NPTS * NPTS;

    __shared__ __align__(16) float Qi[32][64];
    __shared__ __align__(16) float Qj[32][64];
    __shared__ float sm[64][17];

    int tid = threadIdx.x;
    #pragma unroll
    for (int l = 0; l < 2; l++) {
        int idx = tid + l * 256;
        int d   = idx >> 4;
        int nq  = (idx & 15) * 4;
        *(float4*)&Qi[d][nq] = *(const float4*)&Q[(long)d * NPTS + bi + nq];
        *(float4*)&Qj[d][nq] = *(const float4*)&Q[(long)d * NPTS + bj + nq];
    }
    __syncthreads();

    int ti = (tid >> 4) * 4;
    int tj = (tid & 15) * 4;
    unsigned long long acc2[2][4];
    #pragma unroll
    for (int p = 0; p < 2; p++)
        #pragma unroll
        for (int c = 0; c < 4; c++) acc2[p][c] = 0ull;

    #pragma unroll
    for (int d = 0; d < 32; d++) {
        ulonglong2 a = *(const ulonglong2*)&Qi[d][ti];
        unsigned long long ap[2] = {a.x, a.y};
        float4 c4 = *(const float4*)&Qj[d][tj];
        float cv[4] = {c4.x, c4.y, c4.z, c4.w};
        unsigned long long bs[4];
        #pragma unroll
        for (int c = 0; c < 4; c++) bs[c] = pack2(cv[c], cv[c]);
        #pragma unroll
        for (int p = 0; p < 2; p++)
            #pragma unroll
            for (int c = 0; c < 4; c++) ffma2(acc2[p][c], ap[p], bs[c]);
    }

    float sM = sqrtf(nq2M[b]);
    float mrow[4], rsum[4] = {0.f, 0.f, 0.f, 0.f};
    #pragma unroll
    for (int r = 0; r < 4; r++)
        mrow[r] = sqrtf(nq2[b * NPTS + bi + ti + r]) * sM;

    #pragma unroll
    for (int p = 0; p < 2; p++) {
        float2 u0 = unpack2(acc2[p][0]);
        float2 u1 = unpack2(acc2[p][1]);
        float2 u2 = unpack2(acc2[p][2]);
        float2 u3 = unpack2(acc2[p][3]);
        int r0 = bi + ti + p * 2;
        float m0 = mrow[p*2], m1 = mrow[p*2 + 1];
        float4 row0 = make_float4(__expf(u0.x - m0), __expf(u1.x - m0),
                                  __expf(u2.x - m0), __expf(u3.x - m0));
        float4 row1 = make_float4(__expf(u0.y - m1), __expf(u1.y - m1),
                                  __expf(u2.y - m1), __expf(u3.y - m1));
        rsum[p*2]     += row0.x + row0.y + row0.z + row0.w;
        rsum[p*2 + 1] += row1.x + row1.y + row1.z + row1.w;
        *(float4*)&Pb[(long)r0       * NPTS + bj + tj] = row0;
        *(float4*)&Pb[(long)(r0 + 1) * NPTS + bj + tj] = row1;
    }

    #pragma unroll
    for (int r = 0; r < 4; r++) sm[ti + r][tid & 15] = rsum[r];
    __syncthreads();
    if (tid < 64) {
        float v = 0.f;
        #pragma unroll
        for (int k = 0; k < 16; k++) v += sm[tid][k];
        atomicAdd(&s[b * NPTS + bi + tid], v);
    }
}

// zero s (len) and nq2M (NB)
__global__ void zero2_kernel(float* __restrict__ a, float* __restrict__ c, int len)
{
    int i = blockIdx.x * 256 + threadIdx.x;
    if (i < len) a[i] = 0.f;
    if (i < NB)  c[i] = 0.f;
}

// invs = 1/s  (guard against pathological underflow)
__global__ void inv_kernel(const float* __restrict__ s, float* __restrict__ invs, int len)
{
    int i = blockIdx.x * 256 + threadIdx.x;
    if (i < len) invs[i] = 1.0f / fmaxf(s[i], 1e-37f);
}

// ---------------------------------------------------------------------------
// Global max / mean pool over N for hf (1024 channels)
// ---------------------------------------------------------------------------
__global__ __launch_bounds__(256) void pool_kernel(const float* __restrict__ hf,
                                                   float* __restrict__ pool)
{
    int c = blockIdx.x, b = blockIdx.y, tid = threadIdx.x;
    const float* row = hf + ((long)b * 1024 + c) * NPTS;
    float m = -1e30f, sum = 0.f;
    for (int n = tid; n < NPTS; n += 256) {
        float v = row[n];
        m = fmaxf(m, v);
        sum += v;
    }
    __shared__ float sm[256], ss[256];
    sm[tid] = m; ss[tid] = sum; __syncthreads();
    for (int st = 128; st > 0; st >>= 1) {
        if (tid < st) {
            sm[tid] = fmaxf(sm[tid], sm[tid + st]);
            ss[tid] += ss[tid + st];
        }
        __syncthreads();
    }
    if (tid == 0) {
        pool[b * 2048 + c]        = sm[0];
        pool[b * 2048 + 1024 + c] = ss[0] * (1.f / NPTS);
    }
}

// ---------------------------------------------------------------------------
// pbias[b,o] = bs1[o] + sum_c ws1[o,1024+c]*max[b,c] + ws1[o,2048+c]*mean[b,c]
// ---------------------------------------------------------------------------
__global__ __launch_bounds__(256) void pbias_kernel(const float* __restrict__ ws1,
                                                    const float* __restrict__ bs1,
                                                    const float* __restrict__ pool,
                                                    float* __restrict__ pbias)
{
    int o = blockIdx.x, b = blockIdx.y, tid = threadIdx.x;
    float acc = 0.f;
    for (int c = tid; c < 1024; c += 256) {
        acc += ws1[(long)o * 3072 + 1024 + c] * pool[b * 2048 + c];
        acc += ws1[(long)o * 3072 + 2048 + c] * pool[b * 2048 + 1024 + c];
    }
    __shared__ float red[256];
    red[tid] = acc; __syncthreads();
    for (int st = 128; st > 0; st >>= 1) {
        if (tid < st) red[tid] += red[tid + st];
        __syncthreads();
    }
    if (tid == 0) pbias[b * 512 + o] = bs1[o] + red[0];
}

// ---------------------------------------------------------------------------
// Final: logits = ws3 @ h256 + bs3; log_softmax over 8 channels; transpose out
// ---------------------------------------------------------------------------
__global__ __launch_bounds__(128) void final_kernel(const float* __restrict__ h256,
                                                    const float* __restrict__ ws3,
                                                    const float* __restrict__ bs3,
                                                    float* __restrict__ out)
{
    __shared__ float Wsh[8][256];
    int tid = threadIdx.x;
    for (int l = tid; l < 2048; l += 128) Wsh[l >> 8][l & 255] = ws3[l];
    __syncthreads();

    int n = blockIdx.x * 128 + tid;
    int b = blockIdx.y;
    const float* hb = h256 + (long)b * 256 * NPTS;

    float acc[8];
    #pragma unroll
    for (int k = 0; k < 8; k++) acc[k] = bs3[k];
    for (int c = 0; c < 256; c++) {
        float xv = hb[(long)c * NPTS + n];
        #pragma unroll
        for (int k = 0; k < 8; k++) acc[k] += Wsh[k][c] * xv;
    }
    float m = acc[0];
    #pragma unroll
    for (int k = 1; k < 8; k++) m = fmaxf(m, acc[k]);
    float s = 0.f;
    #pragma unroll
    for (int k = 0; k < 8; k++) s += __expf(acc[k] - m);
    float lse = m + logf(s);
    float* op = out + ((long)b * NPTS + n) * 8;
    #pragma unroll
    for (int k = 0; k < 8; k++) op[k] = acc[k] - lse;
}

// ---------------------------------------------------------------------------
// Host orchestration
// ---------------------------------------------------------------------------
static inline void launch_gemm64(const float* W, int ldW,
                                 const float* X, long sX,
                                 float* Y, long sY, int O, int C,
                                 const float* cb, int cbs,
                                 const float* sc, const float* bi, int act,
                                 const float* res, long sres)
{
    dim3 grid(NPTS / 64, (O + 127) / 128, NB);
    gemm_kernel<64><<<grid, 256>>>(W, ldW, X, sX, Y, sY, O, C,
                                   cb, cbs, sc, bi, act, res, sres);
}

static inline void launch_tc(const float* W, int ldW,
                             const float* X, long sX,
                             float* Y, long sY, int O, int C,
                             const float* cb, int cbs,
                             const float* sc, const float* bi, int act)
{
    dim3 grid(NPTS / 128, O / 128, NB);
    tc_gemm_kernel<<<grid, 256>>>(W, ldW, X, sX, Y, sY, C, cb, cbs, sc, bi, act);
}

extern "C" void kernel_launch(void* const* d_in, const int* in_sizes, int n_in,
                              void* d_out, int out_size)
{
    (void)in_sizes; (void)n_in; (void)out_size;

    const float* x      = (const float*)d_in[0];
    const float* w1     = (const float*)d_in[1];
    const float* bn1_g  = (const float*)d_in[2];
    const float* bn1_b  = (const float*)d_in[3];
    const float* w2     = (const float*)d_in[4];
    const float* bn2_g  = (const float*)d_in[5];
    const float* bn2_b  = (const float*)d_in[6];
    const float* sa_wqk = (const float*)d_in[7];
    const float* sa_wv  = (const float*)d_in[8];
    const float* sa_bv  = (const float*)d_in[9];
    const float* sa_wt  = (const float*)d_in[10];
    const float* sa_bt  = (const float*)d_in[11];
    const float* sa_bng = (const float*)d_in[12];
    const float* sa_bnb = (const float*)d_in[13];
    const float* wf     = (const float*)d_in[14];
    const float* bnf_g  = (const float*)d_in[15];
    const float* bnf_b  = (const float*)d_in[16];
    const float* ws1    = (const float*)d_in[17];
    const float* bs1    = (const float*)d_in[18];
    const float* bns1_g = (const float*)d_in[19];
    const float* bns1_b = (const float*)d_in[20];
    const float* ws2    = (const float*)d_in[21];
    const float* bs2    = (const float*)d_in[22];
    const float* bns2_g = (const float*)d_in[23];
    const float* bns2_b = (const float*)d_in[24];
    const float* ws3    = (const float*)d_in[25];
    const float* bs3    = (const float*)d_in[26];

    float *p_h1, *p_h0, *p_q, *p_v, *p_E, *p_t, *p_feats, *p_hf, *p_pool,
          *p_pbias, *p_h512, *p_h256, *p_pOut, *p_pSum, *p_nq2, *p_nq2M,
          *p_s, *p_invs;
    cudaGetSymbolAddress((void**)&p_h1,    g_h1);
    cudaGetSymbolAddress((void**)&p_h0,    g_h0);
    cudaGetSymbolAddress((void**)&p_q,     g_q);
    cudaGetSymbolAddress((void**)&p_v,     g_v);
    cudaGetSymbolAddress((void**)&p_E,     g_E);
    cudaGetSymbolAddress((void**)&p_t,     g_t);
    cudaGetSymbolAddress((void**)&p_feats, g_feats);
    cudaGetSymbolAddress((void**)&p_hf,    g_hf);
    cudaGetSymbolAddress((void**)&p_pool,  g_pool);
    cudaGetSymbolAddress((void**)&p_pbias, g_pbias);
    cudaGetSymbolAddress((void**)&p_h512,  g_h512);
    cudaGetSymbolAddress((void**)&p_h256,  g_h256);
    cudaGetSymbolAddress((void**)&p_pOut,  g_pOut);
    cudaGetSymbolAddress((void**)&p_pSum,  g_pSum);
    cudaGetSymbolAddress((void**)&p_nq2,   g_nq2);
    cudaGetSymbolAddress((void**)&p_nq2M,  g_nq2M);
    cudaGetSymbolAddress((void**)&p_s,     g_s);
    cudaGetSymbolAddress((void**)&p_invs,  g_invs);

    // input MLP
    mlp1_kernel<<<dim3(NPTS / 256, 128, NB), 256>>>(x, w1, bn1_g, bn1_b, p_h1);
    launch_gemm64(w2, 128, p_h1, 128L * NPTS, p_h0, 128L * NPTS, 128, 128,
                  0, 0, bn2_g, bn2_b, 1, 0, 0);

    // 4 self-attention layers
    for (int i = 0; i < 4; i++) {
        const float* h   = (i == 0) ? p_h0 : (p_feats + (long)(i - 1) * 128 * NPTS);
        long hStride     = (i == 0) ? 128L * NPTS : 512L * NPTS;

        // q = wqk_i @ h
        launch_gemm64(sa_wqk + (long)i * 32 * 128, 128, h, hStride,
                      p_q, 32L * NPTS, 32, 128, 0, 0, 0, 0, 0, 0, 0);
        // v = wv_i @ h + bv_i
        launch_gemm64(sa_wv + (long)i * 128 * 128, 128, h, hStride,
                      p_v, 128L * NPTS, 128, 128,
                      sa_bv + (long)i * 128, 0, 0, 0, 0, 0, 0);

        // fused energy/softmax: norm bound, P = exp(E - m), row sums, invs
        zero2_kernel<<<(NB * NPTS + 255) / 256, 256>>>(p_s, p_nq2M, NB * NPTS);
        qnorm_kernel<<<dim3(NPTS / 256, NB), 256>>>(p_q, p_nq2, p_nq2M);
        pexp_kernel<<<dim3(64, 64, NB), 256>>>(p_q, p_nq2, p_nq2M, p_E, p_s);
        inv_kernel<<<(NB * NPTS + 255) / 256, 256>>>(p_s, p_invs, NB * NPTS);

        // TC K-split apply (A scaled at load) with fused colsum, then reduce
        tc_apply_kernel<<<dim3(NPTS / 128, KS, NB), 256>>>(p_v, p_E, p_invs,
                                                           p_pOut, p_pSum);
        apply_reduce_kernel<<<dim3(NPTS / 256, 128, NB), 256>>>(p_pOut, p_pSum,
                                                                h, hStride, p_t);

        // h_new = relu(bn(wt_i @ t + bt_i)) + h  -> feats slice i
        launch_gemm64(sa_wt + (long)i * 128 * 128, 128, p_t, 128L * NPTS,
                      p_feats + (long)i * 128 * NPTS, 512L * NPTS, 128, 128,
                      sa_bt + (long)i * 128, 0,
                      sa_bng + (long)i * 128, sa_bnb + (long)i * 128, 1,
                      h, hStride);
    }

    // hf = leaky_relu(bn(wf @ feats), 0.2)   [TC]
    launch_tc(wf, 512, p_feats, 512L * NPTS, p_hf, 1024L * NPTS, 1024, 512,
              0, 0, bnf_g, bnf_b, 2);

    // pooling + folded per-batch bias for ws1
    pool_kernel<<<dim3(1024, NB), 256>>>(p_hf, p_pool);
    pbias_kernel<<<dim3(512, NB), 256>>>(ws1, bs1, p_pool, p_pbias);

    // h512 = relu(bn(ws1[:, :1024] @ hf + pbias))   [TC]
    launch_tc(ws1, 3072, p_hf, 1024L * NPTS, p_h512, 512L * NPTS, 512, 1024,
              p_pbias, 512, bns1_g, bns1_b, 1);

    // h256 = relu(bn(ws2 @ h512 + bs2))   [TC]
    launch_tc(ws2, 512, p_h512, 512L * NPTS, p_h256, 256L * NPTS, 256, 512,
              bs2, 0, bns2_g, bns2_b, 1);

    // logits + log_softmax + transpose
    final_kernel<<<dim3(NPTS / 128, NB), 128>>>(p_h256, ws3, bs3, (float*)d_out);
}

// round 16
// speedup vs baseline: 1.3286x; 1.1335x over previous
#include <cuda_runtime.h>
#include <math.h>

#define NPTS 4096
#define NB   2
#define KS   8
#define KC   (NPTS / KS)     // 512
#define RSQ  0.99999500003749968f   // 1/sqrt(1 + 1e-5)

// ---------------------------------------------------------------------------
// Packed fp32x2 helpers (Blackwell FFMA2 — only reachable via PTX)
// ---------------------------------------------------------------------------
__device__ __forceinline__ unsigned long long pack2(float x, float y) {
    unsigned long long r;
    asm("mov.b64 %0, {%1, %2};" : "=l"(r) : "f"(x), "f"(y));
    return r;
}
__device__ __forceinline__ void ffma2(unsigned long long& d,
                                      unsigned long long a,
                                      unsigned long long b) {
    asm("fma.rn.f32x2 %0, %1, %2, %0;" : "+l"(d) : "l"(a), "l"(b));
}
__device__ __forceinline__ float2 unpack2(unsigned long long v) {
    float2 f;
    asm("mov.b64 {%0, %1}, %2;" : "=f"(f.x), "=f"(f.y) : "l"(v));
    return f;
}

// ---------------------------------------------------------------------------
// TF32 tensor-core helpers (3xTF32 error-compensated path)
// ---------------------------------------------------------------------------
__device__ __forceinline__ unsigned f2tf(float f) {
    unsigned r;
    asm("cvt.rna.tf32.f32 %0, %1;" : "=r"(r) : "f"(f));
    return r;
}
__device__ __forceinline__ void split_tf(float f, unsigned& hi, unsigned& lo) {
    hi = f2tf(f);
    lo = f2tf(f - __uint_as_float(hi));
}
__device__ __forceinline__ void mma_tf32(float* d, const unsigned* a, const unsigned* b) {
    asm("mma.sync.aligned.m16n8k8.row.col.f32.tf32.tf32.f32 "
        "{%0,%1,%2,%3}, {%4,%5,%6,%7}, {%8,%9}, {%0,%1,%2,%3};"
        : "+f"(d[0]), "+f"(d[1]), "+f"(d[2]), "+f"(d[3])
        : "r"(a[0]), "r"(a[1]), "r"(a[2]), "r"(a[3]), "r"(b[0]), "r"(b[1]));
}

// ---------------------------------------------------------------------------
// Scratch (static __device__ globals; no allocations anywhere)
// ---------------------------------------------------------------------------
__device__ float g_h1   [NB * 128  * NPTS];
__device__ float g_h0   [NB * 128  * NPTS];
__device__ float g_q    [NB * 32   * NPTS];
__device__ float g_v    [NB * 128  * NPTS];
__device__ float g_E    [(size_t)NB * NPTS * NPTS];   // holds unnormalized P
__device__ float g_t    [NB * 128  * NPTS];
__device__ float g_feats[NB * 512  * NPTS];
__device__ float g_hf   [NB * 1024 * NPTS];
__device__ float g_pool [NB * 2048];
__device__ float g_pbias[NB * 512];
__device__ float g_h512 [NB * 512  * NPTS];
__device__ float g_h256 [NB * 256  * NPTS];
__device__ float g_pOut [KS * NB * 128 * NPTS];       // apply partials
__device__ float g_pSum [KS * NB * NPTS];             // colsum partials
__device__ float g_nq2  [NB * NPTS];                  // ||q_i||^2
__device__ float g_nq2M [NB];                         // max_i ||q_i||^2
__device__ float g_s    [NB * NPTS];                  // row exp-sums
__device__ float g_invs [NB * NPTS];                  // 1/s

// ---------------------------------------------------------------------------
// Input MLP stage 1: h1 = relu(bn1(w1 @ x[:,9:12,:]))
// ---------------------------------------------------------------------------
__global__ void mlp1_kernel(const float* __restrict__ x, const float* __restrict__ w1,
                            const float* __restrict__ g, const float* __restrict__ bb,
                            float* __restrict__ h1)
{
    int n = blockIdx.x * 256 + threadIdx.x;
    int c = blockIdx.y;
    int b = blockIdx.z;
    float x0 = x[((long)b * 15 +  9) * NPTS + n];
    float x1 = x[((long)b * 15 + 10) * NPTS + n];
    float x2 = x[((long)b * 15 + 11) * NPTS + n];
    float acc = w1[c*3+0]*x0 + w1[c*3+1]*x1 + w1[c*3+2]*x2;
    acc = acc * (g[c] * RSQ) + bb[c];
    h1[((long)b * 128 + c) * NPTS + n] = fmaxf(acc, 0.f);
}

// ---------------------------------------------------------------------------
// FFMA2 GEMM (small convs: q, v, wt, w2)
// ---------------------------------------------------------------------------
template<int TN>
__global__ __launch_bounds__(256) void gemm_kernel(
    const float* __restrict__ W, int ldW,
    const float* __restrict__ X, long strideX,
    float* __restrict__ Y, long strideY,
    int O, int C,
    const float* __restrict__ convBias, int convBiasStride,
    const float* __restrict__ scale,
    const float* __restrict__ bias,
    int act,
    const float* __restrict__ resid, long strideResid)
{
    constexpr int CT = TN / 16;
    constexpr int XL = (4 * TN) / 256;
    const int bN = blockIdx.x * TN;
    const int bM = blockIdx.y * 128;
    const int b  = blockIdx.z;
    const float* Wb = W;
    const float* Xb = X + (long)b * strideX;

    __shared__ __align__(16) float Ws[2][16][128];
    __shared__ __align__(16) float Xs[2][16][TN];

    const int tid = threadIdx.x;
    const int tm0 = (tid >> 4) * 4;
    const int tn0 = (tid & 15) * 4;

    const int wm  = tid >> 2;
    const int wkq = (tid & 3) * 4;
    int xk[XL], xn[XL];
    #pragma unroll
    for (int l = 0; l < XL; l++) {
        int idx = tid + l * 256;
        xk[l] = idx / (TN / 4);
        xn[l] = (idx % (TN / 4)) * 4;
    }

    unsigned long long acc2[4][CT];
    #pragma unroll
    for (int i = 0; i < 4; i++)
        #pragma unroll
        for (int j = 0; j < CT; j++) acc2[i][j] = 0ull;

    float4 wr0, wr1, xr[XL];
    const int T = C / 16;

    {
        wr0 = make_float4(0.f,0.f,0.f,0.f);
        wr1 = make_float4(0.f,0.f,0.f,0.f);
        if (bM + wm      < O) wr0 = *(const float4*)&Wb[(long)(bM + wm     ) * ldW + wkq];
        if (bM + wm + 64 < O) wr1 = *(const float4*)&Wb[(long)(bM + wm + 64) * ldW + wkq];
        #pragma unroll
        for (int l = 0; l < XL; l++)
            xr[l] = *(const float4*)&Xb[(long)xk[l] * NPTS + bN + xn[l]];
        Ws[0][wkq+0][wm] = wr0.x; Ws[0][wkq+1][wm] = wr0.y;
        Ws[0][wkq+2][wm] = wr0.z; Ws[0][wkq+3][wm] = wr0.w;
        Ws[0][wkq+0][wm+64] = wr1.x; Ws[0][wkq+1][wm+64] = wr1.y;
        Ws[0][wkq+2][wm+64] = wr1.z; Ws[0][wkq+3][wm+64] = wr1.w;
        #pragma unroll
        for (int l = 0; l < XL; l++)
            *(float4*)&Xs[0][xk[l]][xn[l]] = xr[l];
    }
    __syncthreads();

    for (int t = 0; t < T; t++) {
        const int cur = t & 1;
        const int nxt = cur ^ 1;
        const bool more = (t + 1 < T);

        if (more) {
            int k0 = (t + 1) * 16;
            wr0 = make_float4(0.f,0.f,0.f,0.f);
            wr1 = make_float4(0.f,0.f,0.f,0.f);
            if (bM + wm      < O) wr0 = *(const float4*)&Wb[(long)(bM + wm     ) * ldW + k0 + wkq];
            if (bM + wm + 64 < O) wr1 = *(const float4*)&Wb[(long)(bM + wm + 64) * ldW + k0 + wkq];
            #pragma unroll
            for (int l = 0; l < XL; l++)
                xr[l] = *(const float4*)&Xb[(long)(k0 + xk[l]) * NPTS + bN + xn[l]];
        }

        #pragma unroll
        for (int k = 0; k < 16; k++) {
            ulonglong2 a01 = *(const ulonglong2*)&Ws[cur][k][tm0];
            ulonglong2 a23 = *(const ulonglong2*)&Ws[cur][k][tm0 + 64];
            unsigned long long ap[4] = {a01.x, a01.y, a23.x, a23.y};
            float xv[CT];
            float4 x0 = *(const float4*)&Xs[cur][k][tn0];
            xv[0] = x0.x; xv[1] = x0.y; xv[2] = x0.z; xv[3] = x0.w;
            if (CT == 8) {
                float4 x1 = *(const float4*)&Xs[cur][k][tn0 + 64];
                xv[4] = x1.x; xv[5] = x1.y; xv[6] = x1.z; xv[7] = x1.w;
            }
            unsigned long long bs[CT];
            #pragma unroll
            for (int c = 0; c < CT; c++) bs[c] = pack2(xv[c], xv[c]);
            #pragma unroll
            for (int mp = 0; mp < 4; mp++)
                #pragma unroll
                for (int c = 0; c < CT; c++)
                    ffma2(acc2[mp][c], ap[mp], bs[c]);
        }

        if (more) {
            Ws[nxt][wkq+0][wm] = wr0.x; Ws[nxt][wkq+1][wm] = wr0.y;
            Ws[nxt][wkq+2][wm] = wr0.z; Ws[nxt][wkq+3][wm] = wr0.w;
            Ws[nxt][wkq+0][wm+64] = wr1.x; Ws[nxt][wkq+1][wm+64] = wr1.y;
            Ws[nxt][wkq+2][wm+64] = wr1.z; Ws[nxt][wkq+3][wm+64] = wr1.w;
            #pragma unroll
            for (int l = 0; l < XL; l++)
                *(float4*)&Xs[nxt][xk[l]][xn[l]] = xr[l];
            __syncthreads();
        }
    }

    #pragma unroll
    for (int mp = 0; mp < 4; mp++) {
        int rowbase = bM + tm0 + ((mp >= 2) ? 64 : 0) + (mp & 1) * 2;
        #pragma unroll
        for (int sub = 0; sub < 2; sub++) {
            int o = rowbase + sub;
            if (o >= O) continue;
            float cb = convBias ? convBias[b * convBiasStride + o] : 0.f;
            float sc = scale ? scale[o] * RSQ : 1.f;
            float bi = bias ? bias[o] : 0.f;
            float* Yrow = Y + (long)b * strideY + (long)o * NPTS;
            const float* resRow = resid ? (resid + (long)b * strideResid + (long)o * NPTS) : (const float*)0;
            #pragma unroll
            for (int c = 0; c < CT; c++) {
                int n = bN + tn0 + ((c < 4) ? c : (64 + c - 4));
                float2 pr = unpack2(acc2[mp][c]);
                float v = sub ? pr.y : pr.x;
                v = (v + cb) * sc + bi;
                if (act == 1)      v = fmaxf(v, 0.f);
                else if (act == 2) v = (v > 0.f) ? v : 0.2f * v;
                if (resRow) v += resRow[n];
                Yrow[n] = v;
            }
        }
    }
}

// ---------------------------------------------------------------------------
// TC GEMM (3xTF32, m16n8k8): 256 threads, 8 warps = 2(M)x4(N),
// warp tile 64x32 (4 m16 x 4 n8), in-register splits.
// ---------------------------------------------------------------------------
__global__ __launch_bounds__(256, 2) void tc_gemm_kernel(
    const float* __restrict__ W, int ldW,
    const float* __restrict__ X, long strideX,
    float* __restrict__ Y, long strideY,
    int C,
    const float* __restrict__ convBias, int convBiasStride,
    const float* __restrict__ scale,
    const float* __restrict__ bias,
    int act)
{
    const int bN = blockIdx.x * 128;
    const int bM = blockIdx.y * 128;
    const int b  = blockIdx.z;
    const float* Wb = W;
    const float* Xb = X + (long)b * strideX;

    __shared__ __align__(16) float Ws[2][16][132];
    __shared__ __align__(16) float Xs[2][16][132];

    const int tid    = threadIdx.x;
    const int wid    = tid >> 5;
    const int lane   = tid & 31;
    const int warp_m = wid >> 2;       // 0..1
    const int warp_n = wid & 3;        // 0..3

    const int wm  = tid >> 2;          // 0..63
    const int wkq = (tid & 3) * 4;
    const int xka = tid >> 5, xna = (tid & 31) * 4;   // k 0..7
    const int xkb = xka + 8;                          // k 8..15

    float acc[4][4][4];
    #pragma unroll
    for (int mi = 0; mi < 4; mi++)
        #pragma unroll
        for (int ni = 0; ni < 4; ni++)
            #pragma unroll
            for (int r = 0; r < 4; r++) acc[mi][ni][r] = 0.f;

    float4 wr0, wr1, xr0, xr1;
    const int T = C / 16;

    {
        wr0 = *(const float4*)&Wb[(long)(bM + wm     ) * ldW + wkq];
        wr1 = *(const float4*)&Wb[(long)(bM + wm + 64) * ldW + wkq];
        xr0 = *(const float4*)&Xb[(long)xka * NPTS + bN + xna];
        xr1 = *(const float4*)&Xb[(long)xkb * NPTS + bN + xna];
        Ws[0][wkq+0][wm] = wr0.x; Ws[0][wkq+1][wm] = wr0.y;
        Ws[0][wkq+2][wm] = wr0.z; Ws[0][wkq+3][wm] = wr0.w;
        Ws[0][wkq+0][wm+64] = wr1.x; Ws[0][wkq+1][wm+64] = wr1.y;
        Ws[0][wkq+2][wm+64] = wr1.z; Ws[0][wkq+3][wm+64] = wr1.w;
        *(float4*)&Xs[0][xka][xna] = xr0;
        *(float4*)&Xs[0][xkb][xna] = xr1;
    }
    __syncthreads();

    const int alr = lane >> 2;   // 0..7
    const int akc = lane & 3;    // 0..3
    const int bnr = warp_n * 32 + (lane >> 2);

    for (int t = 0; t < T; t++) {
        const int cur = t & 1;
        const int nxt = cur ^ 1;
        const bool more = (t + 1 < T);

        if (more) {
            int k0 = (t + 1) * 16;
            wr0 = *(const float4*)&Wb[(long)(bM + wm     ) * ldW + k0 + wkq];
            wr1 = *(const float4*)&Wb[(long)(bM + wm + 64) * ldW + k0 + wkq];
            xr0 = *(const float4*)&Xb[(long)(k0 + xka) * NPTS + bN + xna];
            xr1 = *(const float4*)&Xb[(long)(k0 + xkb) * NPTS + bN + xna];
        }

        #pragma unroll
        for (int kk = 0; kk < 2; kk++) {
            const int k0 = kk * 8;
            unsigned bh[4][2], bl[4][2];
            #pragma unroll
            for (int ni = 0; ni < 4; ni++) {
                #pragma unroll
                for (int r = 0; r < 2; r++) {
                    float f = Xs[cur][k0 + akc + r*4][bnr + ni*8];
                    split_tf(f, bh[ni][r], bl[ni][r]);
                }
            }
            #pragma unroll
            for (int mi = 0; mi < 4; mi++) {
                int m0 = warp_m * 64 + mi * 16 + alr;
                float f0 = Ws[cur][k0 + akc    ][m0];
                float f1 = Ws[cur][k0 + akc    ][m0 + 8];
                float f2 = Ws[cur][k0 + akc + 4][m0];
                float f3 = Ws[cur][k0 + akc + 4][m0 + 8];
                unsigned ah[4], al[4];
                split_tf(f0, ah[0], al[0]);
                split_tf(f1, ah[1], al[1]);
                split_tf(f2, ah[2], al[2]);
                split_tf(f3, ah[3], al[3]);
                #pragma unroll
                for (int ni = 0; ni < 4; ni++) {
                    mma_tf32(acc[mi][ni], ah, bh[ni]);
                    mma_tf32(acc[mi][ni], al, bh[ni]);
                    mma_tf32(acc[mi][ni], ah, bl[ni]);
                }
            }
        }

        if (more) {
            Ws[nxt][wkq+0][wm] = wr0.x; Ws[nxt][wkq+1][wm] = wr0.y;
            Ws[nxt][wkq+2][wm] = wr0.z; Ws[nxt][wkq+3][wm] = wr0.w;
            Ws[nxt][wkq+0][wm+64] = wr1.x; Ws[nxt][wkq+1][wm+64] = wr1.y;
            Ws[nxt][wkq+2][wm+64] = wr1.z; Ws[nxt][wkq+3][wm+64] = wr1.w;
            *(float4*)&Xs[nxt][xka][xna] = xr0;
            *(float4*)&Xs[nxt][xkb][xna] = xr1;
            __syncthreads();
        }
    }

    // epilogue
    #pragma unroll
    for (int mi = 0; mi < 4; mi++) {
        #pragma unroll
        for (int rr = 0; rr < 2; rr++) {
            int o = bM + warp_m * 64 + mi * 16 + (lane >> 2) + rr * 8;
            float cb = convBias ? convBias[b * convBiasStride + o] : 0.f;
            float sc = scale ? scale[o] * RSQ : 1.f;
            float bi = bias ? bias[o] : 0.f;
            float* Yrow = Y + (long)b * strideY + (long)o * NPTS;
            #pragma unroll
            for (int ni = 0; ni < 4; ni++) {
                int col = bN + warp_n * 32 + ni * 8 + (lane & 3) * 2;
                #pragma unroll
                for (int cc = 0; cc < 2; cc++) {
                    float v = acc[mi][ni][rr * 2 + cc];
                    v = (v + cb) * sc + bi;
                    if (act == 1)      v = fmaxf(v, 0.f);
                    else if (act == 2) v = (v > 0.f) ? v : 0.2f * v;
                    Yrow[col + cc] = v;
                }
            }
        }
    }
}

// ---------------------------------------------------------------------------
// TC apply (K-split, fused colsum): A rows scaled by invs at load time.
// 2-term TF32 (ah*bh + al*bh): V fully compensated, P single tf32 (P in [0,1];
// truncation ~2^-11 relative enters only the numerator; colsum uses exact P).
// ---------------------------------------------------------------------------
__global__ __launch_bounds__(256, 2) void tc_apply_kernel(
    const float* __restrict__ V,
    const float* __restrict__ A,
    const float* __restrict__ invs,
    float* __restrict__ pOut,
    float* __restrict__ pSum)
{
    const int bN = blockIdx.x * 128;
    const int ks = blockIdx.y;
    const int b  = blockIdx.z;
    const float* Wb = V + (long)b * 128 * NPTS + (long)ks * KC;
    const float* Xb = A + (long)b * NPTS * NPTS + (long)ks * KC * NPTS;
    const float* invb = invs + (long)b * NPTS + (long)ks * KC;

    __shared__ __align__(16) float Ws[2][16][132];
    __shared__ __align__(16) float Xs[2][16][132];

    const int tid    = threadIdx.x;
    const int wid    = tid >> 5;
    const int lane   = tid & 31;
    const int warp_m = wid >> 2;
    const int warp_n = wid & 3;

    const int wm  = tid >> 2;
    const int wkq = (tid & 3) * 4;
    const int xka = tid >> 5, xna = (tid & 31) * 4;
    const int xkb = xka + 8;

    float acc[4][4][4];
    #pragma unroll
    for (int mi = 0; mi < 4; mi++)
        #pragma unroll
        for (int ni = 0; ni < 4; ni++)
            #pragma unroll
            for (int r = 0; r < 4; r++) acc[mi][ni][r] = 0.f;
    float ssum = 0.f;

    float4 wr0, wr1, xr0, xr1;

    {
        float ia = invb[xka], ib = invb[xkb];
        wr0 = *(const float4*)&Wb[(long)(wm     ) * NPTS + wkq];
        wr1 = *(const float4*)&Wb[(long)(wm + 64) * NPTS + wkq];
        xr0 = *(const float4*)&Xb[(long)xka * NPTS + bN + xna];
        xr1 = *(const float4*)&Xb[(long)xkb * NPTS + bN + xna];
        xr0.x *= ia; xr0.y *= ia; xr0.z *= ia; xr0.w *= ia;
        xr1.x *= ib; xr1.y *= ib; xr1.z *= ib; xr1.w *= ib;
        Ws[0][wkq+0][wm] = wr0.x; Ws[0][wkq+1][wm] = wr0.y;
        Ws[0][wkq+2][wm] = wr0.z; Ws[0][wkq+3][wm] = wr0.w;
        Ws[0][wkq+0][wm+64] = wr1.x; Ws[0][wkq+1][wm+64] = wr1.y;
        Ws[0][wkq+2][wm+64] = wr1.z; Ws[0][wkq+3][wm+64] = wr1.w;
        *(float4*)&Xs[0][xka][xna] = xr0;
        *(float4*)&Xs[0][xkb][xna] = xr1;
    }
    __syncthreads();

    const int alr = lane >> 2;
    const int akc = lane & 3;
    const int bnr = warp_n * 32 + (lane >> 2);

    const int T = KC / 16;
    for (int t = 0; t < T; t++) {
        const int cur = t & 1;
        const int nxt = cur ^ 1;
        const bool more = (t + 1 < T);

        if (more) {
            int k0 = (t + 1) * 16;
            float ia = invb[k0 + xka], ib = invb[k0 + xkb];
            wr0 = *(const float4*)&Wb[(long)(wm     ) * NPTS + k0 + wkq];
            wr1 = *(const float4*)&Wb[(long)(wm + 64) * NPTS + k0 + wkq];
            xr0 = *(const float4*)&Xb[(long)(k0 + xka) * NPTS + bN + xna];
            xr1 = *(const float4*)&Xb[(long)(k0 + xkb) * NPTS + bN + xna];
            xr0.x *= ia; xr0.y *= ia; xr0.z *= ia; xr0.w *= ia;
            xr1.x *= ib; xr1.y *= ib; xr1.z *= ib; xr1.w *= ib;
        }

        #pragma unroll
        for (int kk = 0; kk < 2; kk++) {
            const int k0 = kk * 8;
            unsigned bh[4][2];
            #pragma unroll
            for (int ni = 0; ni < 4; ni++) {
                #pragma unroll
                for (int r = 0; r < 2; r++) {
                    float f = Xs[cur][k0 + akc + r*4][bnr + ni*8];
                    bh[ni][r] = f2tf(f);
                }
            }
            #pragma unroll
            for (int mi = 0; mi < 4; mi++) {
                int m0 = warp_m * 64 + mi * 16 + alr;
                float f0 = Ws[cur][k0 + akc    ][m0];
                float f1 = Ws[cur][k0 + akc    ][m0 + 8];
                float f2 = Ws[cur][k0 + akc + 4][m0];
                float f3 = Ws[cur][k0 + akc + 4][m0 + 8];
                unsigned ah[4], al[4];
                split_tf(f0, ah[0], al[0]);
                split_tf(f1, ah[1], al[1]);
                split_tf(f2, ah[2], al[2]);
                split_tf(f3, ah[3], al[3]);
                #pragma unroll
                for (int ni = 0; ni < 4; ni++) {
                    mma_tf32(acc[mi][ni], ah, bh[ni]);
                    mma_tf32(acc[mi][ni], al, bh[ni]);
                }
            }
        }

        // fused colsum over true A values (threads 0..127, one column each)
        if (tid < 128) {
            float s = 0.f;
            #pragma unroll
            for (int k = 0; k < 16; k++) s += Xs[cur][k][tid];
            ssum += s;
        }

        if (more) {
            Ws[nxt][wkq+0][wm] = wr0.x; Ws[nxt][wkq+1][wm] = wr0.y;
            Ws[nxt][wkq+2][wm] = wr0.z; Ws[nxt][wkq+3][wm] = wr0.w;
            Ws[nxt][wkq+0][wm+64] = wr1.x; Ws[nxt][wkq+1][wm+64] = wr1.y;
            Ws[nxt][wkq+2][wm+64] = wr1.z; Ws[nxt][wkq+3][wm+64] = wr1.w;
            *(float4*)&Xs[nxt][xka][xna] = xr0;
            *(float4*)&Xs[nxt][xkb][xna] = xr1;
            __syncthreads();
        }
    }

    float* Ob = pOut + ((long)(ks * NB + b) * 128) * NPTS;
    #pragma unroll
    for (int mi = 0; mi < 4; mi++) {
        #pragma unroll
        for (int rr = 0; rr < 2; rr++) {
            int o = warp_m * 64 + mi * 16 + (lane >> 2) + rr * 8;
            float* Yrow = Ob + (long)o * NPTS;
            #pragma unroll
            for (int ni = 0; ni < 4; ni++) {
                int col = bN + warp_n * 32 + ni * 8 + (lane & 3) * 2;
                Yrow[col]     = acc[mi][ni][rr * 2];
                Yrow[col + 1] = acc[mi][ni][rr * 2 + 1];
            }
        }
    }
    if (tid < 128)
        pSum[(long)(ks * NB + b) * NPTS + bN + tid] = ssum;
}

// ---------------------------------------------------------------------------
// Apply reduce: t[b,c,n] = h[b,c,n] - (sum_ks pOut)/(1e-9 + sum_ks pSum)
// ---------------------------------------------------------------------------
__global__ __launch_bounds__(256) void apply_reduce_kernel(
    const float* __restrict__ pOut, const float* __restrict__ pSum,
    const float* __restrict__ h, long hStride, float* __restrict__ t)
{
    int n = blockIdx.x * 256 + threadIdx.x;
    int c = blockIdx.y;
    int b = blockIdx.z;
    float num = 0.f, den = 0.f;
    #pragma unroll
    for (int ks = 0; ks < KS; ks++) {
        num += pOut[((long)(ks * NB + b) * 128 + c) * NPTS + n];
        den += pSum[(long)(ks * NB + b) * NPTS + n];
    }
    t[((long)b * 128 + c) * NPTS + n] =
        h[(long)b * hStride + (long)c * NPTS + n] - num / (1e-9f + den);
}

// ---------------------------------------------------------------------------
// qnorm: nq2[i] = ||q_i||^2 and per-batch max (atomicMax on int bits; values
// are >= 0 and nq2M is zero-initialized, so signed-int ordering is correct).
// ---------------------------------------------------------------------------
__global__ __launch_bounds__(256) void qnorm_kernel(const float* __restrict__ q,
                                                    float* __restrict__ nq2,
                                                    float* __restrict__ nq2M)
{
    int i = blockIdx.x * 256 + threadIdx.x;
    int b = blockIdx.y;
    const float* Q = q + (long)b * 32 * NPTS;
    float s = 0.f;
    #pragma unroll
    for (int d = 0; d < 32; d++) {
        float v = Q[(long)d * NPTS + i];
        s += v * v;
    }
    nq2[b * NPTS + i] = s;

    __shared__ float red[256];
    int tid = threadIdx.x;
    red[tid] = s; __syncthreads();
    for (int st = 128; st > 0; st >>= 1) {
        if (tid < st) red[tid] = fmaxf(red[tid], red[tid + st]);
        __syncthreads();
    }
    if (tid == 0) atomicMax((int*)&nq2M[b], __float_as_int(red[0]));
}

// ---------------------------------------------------------------------------
// pexp: compute E tile, write P = exp(E - m_i) with the Cauchy-Schwarz shift
// m_i = ||q_i|| * max_j ||q_j||  (>= row max; softmax is shift-invariant),
// accumulate row sums via atomicAdd.
// ---------------------------------------------------------------------------
__global__ __launch_bounds__(256) void pexp_kernel(const float* __restrict__ q,
                                                   const float* __restrict__ nq2,
                                                   const float* __restrict__ nq2M,
                                                   float* __restrict__ P,
                                                   float* __restrict__ s)
{
    int bj = blockIdx.x * 64;
    int bi = blockIdx.y * 64;
    int b  = blockIdx.z;
    const float* Q = q + (long)b * 32 * NPTS;
    float* Pb = P + (long)b * NPTS * NPTS;

    __shared__ __align__(16) float Qi[32][64];
    __shared__ __align__(16) float Qj[32][64];
    __shared__ float sm[64][17];

    int tid = threadIdx.x;
    #pragma unroll
    for (int l = 0; l < 2; l++) {
        int idx = tid + l * 256;
        int d   = idx >> 4;
        int nq  = (idx & 15) * 4;
        *(float4*)&Qi[d][nq] = *(const float4*)&Q[(long)d * NPTS + bi + nq];
        *(float4*)&Qj[d][nq] = *(const float4*)&Q[(long)d * NPTS + bj + nq];
    }
    __syncthreads();

    int ti = (tid >> 4) * 4;
    int tj = (tid & 15) * 4;
    unsigned long long acc2[2][4];
    #pragma unroll
    for (int p = 0; p < 2; p++)
        #pragma unroll
        for (int c = 0; c < 4; c++) acc2[p][c] = 0ull;

    #pragma unroll
    for (int d = 0; d < 32; d++) {
        ulonglong2 a = *(const ulonglong2*)&Qi[d][ti];
        unsigned long long ap[2] = {a.x, a.y};
        float4 c4 = *(const float4*)&Qj[d][tj];
        float cv[4] = {c4.x, c4.y, c4.z, c4.w};
        unsigned long long bs[4];
        #pragma unroll
        for (int c = 0; c < 4; c++) bs[c] = pack2(cv[c], cv[c]);
        #pragma unroll
        for (int p = 0; p < 2; p++)
            #pragma unroll
            for (int c = 0; c < 4; c++) ffma2(acc2[p][c], ap[p], bs[c]);
    }

    float sM = sqrtf(nq2M[b]);
    float mrow[4], rsum[4] = {0.f, 0.f, 0.f, 0.f};
    #pragma unroll
    for (int r = 0; r < 4; r++)
        mrow[r] = sqrtf(nq2[b * NPTS + bi + ti + r]) * sM;

    #pragma unroll
    for (int p = 0; p < 2; p++) {
        float2 u0 = unpack2(acc2[p][0]);
        float2 u1 = unpack2(acc2[p][1]);
        float2 u2 = unpack2(acc2[p][2]);
        float2 u3 = unpack2(acc2[p][3]);
        int r0 = bi + ti + p * 2;
        float m0 = mrow[p*2], m1 = mrow[p*2 + 1];
        float4 row0 = make_float4(__expf(u0.x - m0), __expf(u1.x - m0),
                                  __expf(u2.x - m0), __expf(u3.x - m0));
        float4 row1 = make_float4(__expf(u0.y - m1), __expf(u1.y - m1),
                                  __expf(u2.y - m1), __expf(u3.y - m1));
        rsum[p*2]     += row0.x + row0.y + row0.z + row0.w;
        rsum[p*2 + 1] += row1.x + row1.y + row1.z + row1.w;
        *(float4*)&Pb[(long)r0       * NPTS + bj + tj] = row0;
        *(float4*)&Pb[(long)(r0 + 1) * NPTS + bj + tj] = row1;
    }

    #pragma unroll
    for (int r = 0; r < 4; r++) sm[ti + r][tid & 15] = rsum[r];
    __syncthreads();
    if (tid < 64) {
        float v = 0.f;
        #pragma unroll
        for (int k = 0; k < 16; k++) v += sm[tid][k];
        atomicAdd(&s[b * NPTS + bi + tid], v);
    }
}

// zero s (len) and nq2M (NB)
__global__ void zero2_kernel(float* __restrict__ a, float* __restrict__ c, int len)
{
    int i = blockIdx.x * 256 + threadIdx.x;
    if (i < len) a[i] = 0.f;
    if (i < NB)  c[i] = 0.f;
}

// invs = 1/s  (guard against pathological underflow)
__global__ void inv_kernel(const float* __restrict__ s, float* __restrict__ invs, int len)
{
    int i = blockIdx.x * 256 + threadIdx.x;
    if (i < len) invs[i] = 1.0f / fmaxf(s[i], 1e-37f);
}

// ---------------------------------------------------------------------------
// Global max / mean pool over N for hf (1024 channels)
// ---------------------------------------------------------------------------
__global__ __launch_bounds__(256) void pool_kernel(const float* __restrict__ hf,
                                                   float* __restrict__ pool)
{
    int c = blockIdx.x, b = blockIdx.y, tid = threadIdx.x;
    const float* row = hf + ((long)b * 1024 + c) * NPTS;
    float m = -1e30f, sum = 0.f;
    for (int n = tid; n < NPTS; n += 256) {
        float v = row[n];
        m = fmaxf(m, v);
        sum += v;
    }
    __shared__ float sm[256], ss[256];
    sm[tid] = m; ss[tid] = sum; __syncthreads();
    for (int st = 128; st > 0; st >>= 1) {
        if (tid < st) {
            sm[tid] = fmaxf(sm[tid], sm[tid + st]);
            ss[tid] += ss[tid + st];
        }
        __syncthreads();
    }
    if (tid == 0) {
        pool[b * 2048 + c]        = sm[0];
        pool[b * 2048 + 1024 + c] = ss[0] * (1.f / NPTS);
    }
}

// ---------------------------------------------------------------------------
// pbias[b,o] = bs1[o] + sum_c ws1[o,1024+c]*max[b,c] + ws1[o,2048+c]*mean[b,c]
// ---------------------------------------------------------------------------
__global__ __launch_bounds__(256) void pbias_kernel(const float* __restrict__ ws1,
                                                    const float* __restrict__ bs1,
                                                    const float* __restrict__ pool,
                                                    float* __restrict__ pbias)
{
    int o = blockIdx.x, b = blockIdx.y, tid = threadIdx.x;
    float acc = 0.f;
    for (int c = tid; c < 1024; c += 256) {
        acc += ws1[(long)o * 3072 + 1024 + c] * pool[b * 2048 + c];
        acc += ws1[(long)o * 3072 + 2048 + c] * pool[b * 2048 + 1024 + c];
    }
    __shared__ float red[256];
    red[tid] = acc; __syncthreads();
    for (int st = 128; st > 0; st >>= 1) {
        if (tid < st) red[tid] += red[tid + st];
        __syncthreads();
    }
    if (tid == 0) pbias[b * 512 + o] = bs1[o] + red[0];
}

// ---------------------------------------------------------------------------
// Final: logits = ws3 @ h256 + bs3; log_softmax over 8 channels; transpose out
// ---------------------------------------------------------------------------
__global__ __launch_bounds__(128) void final_kernel(const float* __restrict__ h256,
                                                    const float* __restrict__ ws3,
                                                    const float* __restrict__ bs3,
                                                    float* __restrict__ out)
{
    __shared__ float Wsh[8][256];
    int tid = threadIdx.x;
    for (int l = tid; l < 2048; l += 128) Wsh[l >> 8][l & 255] = ws3[l];
    __syncthreads();

    int n = blockIdx.x * 128 + tid;
    int b = blockIdx.y;
    const float* hb = h256 + (long)b * 256 * NPTS;

    float acc[8];
    #pragma unroll
    for (int k = 0; k < 8; k++) acc[k] = bs3[k];
    for (int c = 0; c < 256; c++) {
        float xv = hb[(long)c * NPTS + n];
        #pragma unroll
        for (int k = 0; k < 8; k++) acc[k] += Wsh[k][c] * xv;
    }
    float m = acc[0];
    #pragma unroll
    for (int k = 1; k < 8; k++) m = fmaxf(m, acc[k]);
    float s = 0.f;
    #pragma unroll
    for (int k = 0; k < 8; k++) s += __expf(acc[k] - m);
    float lse = m + logf(s);
    float* op = out + ((long)b * NPTS + n) * 8;
    #pragma unroll
    for (int k = 0; k < 8; k++) op[k] = acc[k] - lse;
}

// ---------------------------------------------------------------------------
// Host orchestration
// ---------------------------------------------------------------------------
static inline void launch_gemm64(const float* W, int ldW,
                                 const float* X, long sX,
                                 float* Y, long sY, int O, int C,
                                 const float* cb, int cbs,
                                 const float* sc, const float* bi, int act,
                                 const float* res, long sres)
{
    dim3 grid(NPTS / 64, (O + 127) / 128, NB);
    gemm_kernel<64><<<grid, 256>>>(W, ldW, X, sX, Y, sY, O, C,
                                   cb, cbs, sc, bi, act, res, sres);
}

static inline void launch_tc(const float* W, int ldW,
                             const float* X, long sX,
                             float* Y, long sY, int O, int C,
                             const float* cb, int cbs,
                             const float* sc, const float* bi, int act)
{
    dim3 grid(NPTS / 128, O / 128, NB);
    tc_gemm_kernel<<<grid, 256>>>(W, ldW, X, sX, Y, sY, C, cb, cbs, sc, bi, act);
}

extern "C" void kernel_launch(void* const* d_in, const int* in_sizes, int n_in,
                              void* d_out, int out_size)
{
    (void)in_sizes; (void)n_in; (void)out_size;

    const float* x      = (const float*)d_in[0];
    const float* w1     = (const float*)d_in[1];
    const float* bn1_g  = (const float*)d_in[2];
    const float* bn1_b  = (const float*)d_in[3];
    const float* w2     = (const float*)d_in[4];
    const float* bn2_g  = (const float*)d_in[5];
    const float* bn2_b  = (const float*)d_in[6];
    const float* sa_wqk = (const float*)d_in[7];
    const float* sa_wv  = (const float*)d_in[8];
    const float* sa_bv  = (const float*)d_in[9];
    const float* sa_wt  = (const float*)d_in[10];
    const float* sa_bt  = (const float*)d_in[11];
    const float* sa_bng = (const float*)d_in[12];
    const float* sa_bnb = (const float*)d_in[13];
    const float* wf     = (const float*)d_in[14];
    const float* bnf_g  = (const float*)d_in[15];
    const float* bnf_b  = (const float*)d_in[16];
    const float* ws1    = (const float*)d_in[17];
    const float* bs1    = (const float*)d_in[18];
    const float* bns1_g = (const float*)d_in[19];
    const float* bns1_b = (const float*)d_in[20];
    const float* ws2    = (const float*)d_in[21];
    const float* bs2    = (const float*)d_in[22];
    const float* bns2_g = (const float*)d_in[23];
    const float* bns2_b = (const float*)d_in[24];
    const float* ws3    = (const float*)d_in[25];
    const float* bs3    = (const float*)d_in[26];

    float *p_h1, *p_h0, *p_q, *p_v, *p_E, *p_t, *p_feats, *p_hf, *p_pool,
          *p_pbias, *p_h512, *p_h256, *p_pOut, *p_pSum, *p_nq2, *p_nq2M,
          *p_s, *p_invs;
    cudaGetSymbolAddress((void**)&p_h1,    g_h1);
    cudaGetSymbolAddress((void**)&p_h0,    g_h0);
    cudaGetSymbolAddress((void**)&p_q,     g_q);
    cudaGetSymbolAddress((void**)&p_v,     g_v);
    cudaGetSymbolAddress((void**)&p_E,     g_E);
    cudaGetSymbolAddress((void**)&p_t,     g_t);
    cudaGetSymbolAddress((void**)&p_feats, g_feats);
    cudaGetSymbolAddress((void**)&p_hf,    g_hf);
    cudaGetSymbolAddress((void**)&p_pool,  g_pool);
    cudaGetSymbolAddress((void**)&p_pbias, g_pbias);
    cudaGetSymbolAddress((void**)&p_h512,  g_h512);
    cudaGetSymbolAddress((void**)&p_h256,  g_h256);
    cudaGetSymbolAddress((void**)&p_pOut,  g_pOut);
    cudaGetSymbolAddress((void**)&p_pSum,  g_pSum);
    cudaGetSymbolAddress((void**)&p_nq2,   g_nq2);
    cudaGetSymbolAddress((void**)&p_nq2M,  g_nq2M);
    cudaGetSymbolAddress((void**)&p_s,     g_s);
    cudaGetSymbolAddress((void**)&p_invs,  g_invs);

    // input MLP
    mlp1_kernel<<<dim3(NPTS / 256, 128, NB), 256>>>(x, w1, bn1_g, bn1_b, p_h1);
    launch_gemm64(w2, 128, p_h1, 128L * NPTS, p_h0, 128L * NPTS, 128, 128,
                  0, 0, bn2_g, bn2_b, 1, 0, 0);

    // 4 self-attention layers
    for (int i = 0; i < 4; i++) {
        const float* h   = (i == 0) ? p_h0 : (p_feats + (long)(i - 1) * 128 * NPTS);
        long hStride     = (i == 0) ? 128L * NPTS : 512L * NPTS;

        // q = wqk_i @ h
        launch_gemm64(sa_wqk + (long)i * 32 * 128, 128, h, hStride,
                      p_q, 32L * NPTS, 32, 128, 0, 0, 0, 0, 0, 0, 0);
        // v = wv_i @ h + bv_i
        launch_gemm64(sa_wv + (long)i * 128 * 128, 128, h, hStride,
                      p_v, 128L * NPTS, 128, 128,
                      sa_bv + (long)i * 128, 0, 0, 0, 0, 0, 0);

        // fused energy/softmax: norm bound, P = exp(E - m), row sums, invs
        zero2_kernel<<<(NB * NPTS + 255) / 256, 256>>>(p_s, p_nq2M, NB * NPTS);
        qnorm_kernel<<<dim3(NPTS / 256, NB), 256>>>(p_q, p_nq2, p_nq2M);
        pexp_kernel<<<dim3(64, 64, NB), 256>>>(p_q, p_nq2, p_nq2M, p_E, p_s);
        inv_kernel<<<(NB * NPTS + 255) / 256, 256>>>(p_s, p_invs, NB * NPTS);

        // TC K-split apply (A scaled at load) with fused colsum, then reduce
        tc_apply_kernel<<<dim3(NPTS / 128, KS, NB), 256>>>(p_v, p_E, p_invs,
                                                           p_pOut, p_pSum);
        apply_reduce_kernel<<<dim3(NPTS / 256, 128, NB), 256>>>(p_pOut, p_pSum,
                                                                h, hStride, p_t);

        // h_new = relu(bn(wt_i @ t + bt_i)) + h  -> feats slice i
        launch_gemm64(sa_wt + (long)i * 128 * 128, 128, p_t, 128L * NPTS,
                      p_feats + (long)i * 128 * NPTS, 512L * NPTS, 128, 128,
                      sa_bt + (long)i * 128, 0,
                      sa_bng + (long)i * 128, sa_bnb + (long)i * 128, 1,
                      h, hStride);
    }

    // hf = leaky_relu(bn(wf @ feats), 0.2)   [TC]
    launch_tc(wf, 512, p_feats, 512L * NPTS, p_hf, 1024L * NPTS, 1024, 512,
              0, 0, bnf_g, bnf_b, 2);

    // pooling + folded per-batch bias for ws1
    pool_kernel<<<dim3(1024, NB), 256>>>(p_hf, p_pool);
    pbias_kernel<<<dim3(512, NB), 256>>>(ws1, bs1, p_pool, p_pbias);

    // h512 = relu(bn(ws1[:, :1024] @ hf + pbias))   [TC]
    launch_tc(ws1, 3072, p_hf, 1024L * NPTS, p_h512, 512L * NPTS, 512, 1024,
              p_pbias, 512, bns1_g, bns1_b, 1);

    // h256 = relu(bn(ws2 @ h512 + bs2))   [TC]
    launch_tc(ws2, 512, p_h512, 512L * NPTS, p_h256, 256L * NPTS, 256, 512,
              bs2, 0, bns2_g, bns2_b, 1);

    // logits + log_softmax + transpose
    final_kernel<<<dim3(NPTS / 128, NB), 128>>>(p_h256, ws3, bs3, (float*)d_out);
}

// round 17
// speedup vs baseline: 1.5305x; 1.1520x over previous
#include <cuda_runtime.h>
#include <math.h>

#define NPTS 4096
#define NB   2
#define KS   8
#define KC   (NPTS / KS)     // 512
#define RSQ  0.99999500003749968f   // 1/sqrt(1 + 1e-5)

// ---------------------------------------------------------------------------
// Packed fp32x2 helpers (Blackwell FFMA2 — only reachable via PTX)
// ---------------------------------------------------------------------------
__device__ __forceinline__ unsigned long long pack2(float x, float y) {
    unsigned long long r;
    asm("mov.b64 %0, {%1, %2};" : "=l"(r) : "f"(x), "f"(y));
    return r;
}
__device__ __forceinline__ void ffma2(unsigned long long& d,
                                      unsigned long long a,
                                      unsigned long long b) {
    asm("fma.rn.f32x2 %0, %1, %2, %0;" : "+l"(d) : "l"(a), "l"(b));
}
__device__ __forceinline__ float2 unpack2(unsigned long long v) {
    float2 f;
    asm("mov.b64 {%0, %1}, %2;" : "=f"(f.x), "=f"(f.y) : "l"(v));
    return f;
}

// ---------------------------------------------------------------------------
// TF32 tensor-core helpers
// ---------------------------------------------------------------------------
__device__ __forceinline__ unsigned f2tf(float f) {
    unsigned r;
    asm("cvt.rna.tf32.f32 %0, %1;" : "=r"(r) : "f"(f));
    return r;
}
__device__ __forceinline__ void split_tf(float f, unsigned& hi, unsigned& lo) {
    hi = f2tf(f);
    lo = f2tf(f - __uint_as_float(hi));
}
__device__ __forceinline__ void mma_tf32(float* d, const unsigned* a, const unsigned* b) {
    asm("mma.sync.aligned.m16n8k8.row.col.f32.tf32.tf32.f32 "
        "{%0,%1,%2,%3}, {%4,%5,%6,%7}, {%8,%9}, {%0,%1,%2,%3};"
        : "+f"(d[0]), "+f"(d[1]), "+f"(d[2]), "+f"(d[3])
        : "r"(a[0]), "r"(a[1]), "r"(a[2]), "r"(a[3]), "r"(b[0]), "r"(b[1]));
}

// ---------------------------------------------------------------------------
// Scratch (static __device__ globals; no allocations anywhere)
// ---------------------------------------------------------------------------
__device__ float g_h1   [NB * 128  * NPTS];
__device__ float g_h0   [NB * 128  * NPTS];
__device__ float g_q    [NB * 32   * NPTS];
__device__ float g_v    [NB * 128  * NPTS];
__device__ float g_E    [(size_t)NB * NPTS * NPTS];   // holds unnormalized P
__device__ float g_t    [NB * 128  * NPTS];
__device__ float g_feats[NB * 512  * NPTS];
__device__ float g_hf   [NB * 1024 * NPTS];
__device__ float g_pool [NB * 2048];
__device__ float g_pbias[NB * 512];
__device__ float g_h512 [NB * 512  * NPTS];
__device__ float g_h256 [NB * 256  * NPTS];
__device__ float g_pOut [KS * NB * 128 * NPTS];       // apply partials
__device__ float g_pSum [KS * NB * NPTS];             // colsum partials
__device__ float g_nq2  [NB * NPTS];                  // ||q_i||^2
__device__ float g_nq2M [NB];                         // max_i ||q_i||^2
__device__ float g_s    [NB * NPTS];                  // row exp-sums
__device__ float g_invs [NB * NPTS];                  // 1/s

// ---------------------------------------------------------------------------
// Input MLP stage 1: h1 = relu(bn1(w1 @ x[:,9:12,:]))
// ---------------------------------------------------------------------------
__global__ void mlp1_kernel(const float* __restrict__ x, const float* __restrict__ w1,
                            const float* __restrict__ g, const float* __restrict__ bb,
                            float* __restrict__ h1)
{
    int n = blockIdx.x * 256 + threadIdx.x;
    int c = blockIdx.y;
    int b = blockIdx.z;
    float x0 = x[((long)b * 15 +  9) * NPTS + n];
    float x1 = x[((long)b * 15 + 10) * NPTS + n];
    float x2 = x[((long)b * 15 + 11) * NPTS + n];
    float acc = w1[c*3+0]*x0 + w1[c*3+1]*x1 + w1[c*3+2]*x2;
    acc = acc * (g[c] * RSQ) + bb[c];
    h1[((long)b * 128 + c) * NPTS + n] = fmaxf(acc, 0.f);
}

// ---------------------------------------------------------------------------
// FFMA2 GEMM (small convs: q, v, wt, w2)
// ---------------------------------------------------------------------------
template<int TN>
__global__ __launch_bounds__(256) void gemm_kernel(
    const float* __restrict__ W, int ldW,
    const float* __restrict__ X, long strideX,
    float* __restrict__ Y, long strideY,
    int O, int C,
    const float* __restrict__ convBias, int convBiasStride,
    const float* __restrict__ scale,
    const float* __restrict__ bias,
    int act,
    const float* __restrict__ resid, long strideResid)
{
    constexpr int CT = TN / 16;
    constexpr int XL = (4 * TN) / 256;
    const int bN = blockIdx.x * TN;
    const int bM = blockIdx.y * 128;
    const int b  = blockIdx.z;
    const float* Wb = W;
    const float* Xb = X + (long)b * strideX;

    __shared__ __align__(16) float Ws[2][16][128];
    __shared__ __align__(16) float Xs[2][16][TN];

    const int tid = threadIdx.x;
    const int tm0 = (tid >> 4) * 4;
    const int tn0 = (tid & 15) * 4;

    const int wm  = tid >> 2;
    const int wkq = (tid & 3) * 4;
    int xk[XL], xn[XL];
    #pragma unroll
    for (int l = 0; l < XL; l++) {
        int idx = tid + l * 256;
        xk[l] = idx / (TN / 4);
        xn[l] = (idx % (TN / 4)) * 4;
    }

    unsigned long long acc2[4][CT];
    #pragma unroll
    for (int i = 0; i < 4; i++)
        #pragma unroll
        for (int j = 0; j < CT; j++) acc2[i][j] = 0ull;

    float4 wr0, wr1, xr[XL];
    const int T = C / 16;

    {
        wr0 = make_float4(0.f,0.f,0.f,0.f);
        wr1 = make_float4(0.f,0.f,0.f,0.f);
        if (bM + wm      < O) wr0 = *(const float4*)&Wb[(long)(bM + wm     ) * ldW + wkq];
        if (bM + wm + 64 < O) wr1 = *(const float4*)&Wb[(long)(bM + wm + 64) * ldW + wkq];
        #pragma unroll
        for (int l = 0; l < XL; l++)
            xr[l] = *(const float4*)&Xb[(long)xk[l] * NPTS + bN + xn[l]];
        Ws[0][wkq+0][wm] = wr0.x; Ws[0][wkq+1][wm] = wr0.y;
        Ws[0][wkq+2][wm] = wr0.z; Ws[0][wkq+3][wm] = wr0.w;
        Ws[0][wkq+0][wm+64] = wr1.x; Ws[0][wkq+1][wm+64] = wr1.y;
        Ws[0][wkq+2][wm+64] = wr1.z; Ws[0][wkq+3][wm+64] = wr1.w;
        #pragma unroll
        for (int l = 0; l < XL; l++)
            *(float4*)&Xs[0][xk[l]][xn[l]] = xr[l];
    }
    __syncthreads();

    for (int t = 0; t < T; t++) {
        const int cur = t & 1;
        const int nxt = cur ^ 1;
        const bool more = (t + 1 < T);

        if (more) {
            int k0 = (t + 1) * 16;
            wr0 = make_float4(0.f,0.f,0.f,0.f);
            wr1 = make_float4(0.f,0.f,0.f,0.f);
            if (bM + wm      < O) wr0 = *(const float4*)&Wb[(long)(bM + wm     ) * ldW + k0 + wkq];
            if (bM + wm + 64 < O) wr1 = *(const float4*)&Wb[(long)(bM + wm + 64) * ldW + k0 + wkq];
            #pragma unroll
            for (int l = 0; l < XL; l++)
                xr[l] = *(const float4*)&Xb[(long)(k0 + xk[l]) * NPTS + bN + xn[l]];
        }

        #pragma unroll
        for (int k = 0; k < 16; k++) {
            ulonglong2 a01 = *(const ulonglong2*)&Ws[cur][k][tm0];
            ulonglong2 a23 = *(const ulonglong2*)&Ws[cur][k][tm0 + 64];
            unsigned long long ap[4] = {a01.x, a01.y, a23.x, a23.y};
            float xv[CT];
            float4 x0 = *(const float4*)&Xs[cur][k][tn0];
            xv[0] = x0.x; xv[1] = x0.y; xv[2] = x0.z; xv[3] = x0.w;
            if (CT == 8) {
                float4 x1 = *(const float4*)&Xs[cur][k][tn0 + 64];
                xv[4] = x1.x; xv[5] = x1.y; xv[6] = x1.z; xv[7] = x1.w;
            }
            unsigned long long bs[CT];
            #pragma unroll
            for (int c = 0; c < CT; c++) bs[c] = pack2(xv[c], xv[c]);
            #pragma unroll
            for (int mp = 0; mp < 4; mp++)
                #pragma unroll
                for (int c = 0; c < CT; c++)
                    ffma2(acc2[mp][c], ap[mp], bs[c]);
        }

        if (more) {
            Ws[nxt][wkq+0][wm] = wr0.x; Ws[nxt][wkq+1][wm] = wr0.y;
            Ws[nxt][wkq+2][wm] = wr0.z; Ws[nxt][wkq+3][wm] = wr0.w;
            Ws[nxt][wkq+0][wm+64] = wr1.x; Ws[nxt][wkq+1][wm+64] = wr1.y;
            Ws[nxt][wkq+2][wm+64] = wr1.z; Ws[nxt][wkq+3][wm+64] = wr1.w;
            #pragma unroll
            for (int l = 0; l < XL; l++)
                *(float4*)&Xs[nxt][xk[l]][xn[l]] = xr[l];
            __syncthreads();
        }
    }

    #pragma unroll
    for (int mp = 0; mp < 4; mp++) {
        int rowbase = bM + tm0 + ((mp >= 2) ? 64 : 0) + (mp & 1) * 2;
        #pragma unroll
        for (int sub = 0; sub < 2; sub++) {
            int o = rowbase + sub;
            if (o >= O) continue;
            float cb = convBias ? convBias[b * convBiasStride + o] : 0.f;
            float sc = scale ? scale[o] * RSQ : 1.f;
            float bi = bias ? bias[o] : 0.f;
            float* Yrow = Y + (long)b * strideY + (long)o * NPTS;
            const float* resRow = resid ? (resid + (long)b * strideResid + (long)o * NPTS) : (const float*)0;
            #pragma unroll
            for (int c = 0; c < CT; c++) {
                int n = bN + tn0 + ((c < 4) ? c : (64 + c - 4));
                float2 pr = unpack2(acc2[mp][c]);
                float v = sub ? pr.y : pr.x;
                v = (v + cb) * sc + bi;
                if (act == 1)      v = fmaxf(v, 0.f);
                else if (act == 2) v = (v > 0.f) ? v : 0.2f * v;
                if (resRow) v += resRow[n];
                Yrow[n] = v;
            }
        }
    }
}

// ---------------------------------------------------------------------------
// TC GEMM (2-term TF32: W split-compensated, X single tf32), m16n8k8.
// 256 threads, 8 warps = 2(M)x4(N), warp tile 64x32.
// ---------------------------------------------------------------------------
__global__ __launch_bounds__(256, 2) void tc_gemm_kernel(
    const float* __restrict__ W, int ldW,
    const float* __restrict__ X, long strideX,
    float* __restrict__ Y, long strideY,
    int C,
    const float* __restrict__ convBias, int convBiasStride,
    const float* __restrict__ scale,
    const float* __restrict__ bias,
    int act)
{
    const int bN = blockIdx.x * 128;
    const int bM = blockIdx.y * 128;
    const int b  = blockIdx.z;
    const float* Wb = W;
    const float* Xb = X + (long)b * strideX;

    __shared__ __align__(16) float Ws[2][16][132];
    __shared__ __align__(16) float Xs[2][16][132];

    const int tid    = threadIdx.x;
    const int wid    = tid >> 5;
    const int lane   = tid & 31;
    const int warp_m = wid >> 2;       // 0..1
    const int warp_n = wid & 3;        // 0..3

    const int wm  = tid >> 2;          // 0..63
    const int wkq = (tid & 3) * 4;
    const int xka = tid >> 5, xna = (tid & 31) * 4;   // k 0..7
    const int xkb = xka + 8;                          // k 8..15

    float acc[4][4][4];
    #pragma unroll
    for (int mi = 0; mi < 4; mi++)
        #pragma unroll
        for (int ni = 0; ni < 4; ni++)
            #pragma unroll
            for (int r = 0; r < 4; r++) acc[mi][ni][r] = 0.f;

    float4 wr0, wr1, xr0, xr1;
    const int T = C / 16;

    {
        wr0 = *(const float4*)&Wb[(long)(bM + wm     ) * ldW + wkq];
        wr1 = *(const float4*)&Wb[(long)(bM + wm + 64) * ldW + wkq];
        xr0 = *(const float4*)&Xb[(long)xka * NPTS + bN + xna];
        xr1 = *(const float4*)&Xb[(long)xkb * NPTS + bN + xna];
        Ws[0][wkq+0][wm] = wr0.x; Ws[0][wkq+1][wm] = wr0.y;
        Ws[0][wkq+2][wm] = wr0.z; Ws[0][wkq+3][wm] = wr0.w;
        Ws[0][wkq+0][wm+64] = wr1.x; Ws[0][wkq+1][wm+64] = wr1.y;
        Ws[0][wkq+2][wm+64] = wr1.z; Ws[0][wkq+3][wm+64] = wr1.w;
        *(float4*)&Xs[0][xka][xna] = xr0;
        *(float4*)&Xs[0][xkb][xna] = xr1;
    }
    __syncthreads();

    const int alr = lane >> 2;   // 0..7
    const int akc = lane & 3;    // 0..3
    const int bnr = warp_n * 32 + (lane >> 2);

    for (int t = 0; t < T; t++) {
        const int cur = t & 1;
        const int nxt = cur ^ 1;
        const bool more = (t + 1 < T);

        if (more) {
            int k0 = (t + 1) * 16;
            wr0 = *(const float4*)&Wb[(long)(bM + wm     ) * ldW + k0 + wkq];
            wr1 = *(const float4*)&Wb[(long)(bM + wm + 64) * ldW + k0 + wkq];
            xr0 = *(const float4*)&Xb[(long)(k0 + xka) * NPTS + bN + xna];
            xr1 = *(const float4*)&Xb[(long)(k0 + xkb) * NPTS + bN + xna];
        }

        #pragma unroll
        for (int kk = 0; kk < 2; kk++) {
            const int k0 = kk * 8;
            unsigned bh[4][2];
            #pragma unroll
            for (int ni = 0; ni < 4; ni++) {
                #pragma unroll
                for (int r = 0; r < 2; r++) {
                    float f = Xs[cur][k0 + akc + r*4][bnr + ni*8];
                    bh[ni][r] = f2tf(f);
                }
            }
            #pragma unroll
            for (int mi = 0; mi < 4; mi++) {
                int m0 = warp_m * 64 + mi * 16 + alr;
                float f0 = Ws[cur][k0 + akc    ][m0];
                float f1 = Ws[cur][k0 + akc    ][m0 + 8];
                float f2 = Ws[cur][k0 + akc + 4][m0];
                float f3 = Ws[cur][k0 + akc + 4][m0 + 8];
                unsigned ah[4], al[4];
                split_tf(f0, ah[0], al[0]);
                split_tf(f1, ah[1], al[1]);
                split_tf(f2, ah[2], al[2]);
                split_tf(f3, ah[3], al[3]);
                #pragma unroll
                for (int ni = 0; ni < 4; ni++) {
                    mma_tf32(acc[mi][ni], ah, bh[ni]);
                    mma_tf32(acc[mi][ni], al, bh[ni]);
                }
            }
        }

        if (more) {
            Ws[nxt][wkq+0][wm] = wr0.x; Ws[nxt][wkq+1][wm] = wr0.y;
            Ws[nxt][wkq+2][wm] = wr0.z; Ws[nxt][wkq+3][wm] = wr0.w;
            Ws[nxt][wkq+0][wm+64] = wr1.x; Ws[nxt][wkq+1][wm+64] = wr1.y;
            Ws[nxt][wkq+2][wm+64] = wr1.z; Ws[nxt][wkq+3][wm+64] = wr1.w;
            *(float4*)&Xs[nxt][xka][xna] = xr0;
            *(float4*)&Xs[nxt][xkb][xna] = xr1;
            __syncthreads();
        }
    }

    // epilogue
    #pragma unroll
    for (int mi = 0; mi < 4; mi++) {
        #pragma unroll
        for (int rr = 0; rr < 2; rr++) {
            int o = bM + warp_m * 64 + mi * 16 + (lane >> 2) + rr * 8;
            float cb = convBias ? convBias[b * convBiasStride + o] : 0.f;
            float sc = scale ? scale[o] * RSQ : 1.f;
            float bi = bias ? bias[o] : 0.f;
            float* Yrow = Y + (long)b * strideY + (long)o * NPTS;
            #pragma unroll
            for (int ni = 0; ni < 4; ni++) {
                int col = bN + warp_n * 32 + ni * 8 + (lane & 3) * 2;
                #pragma unroll
                for (int cc = 0; cc < 2; cc++) {
                    float v = acc[mi][ni][rr * 2 + cc];
                    v = (v + cb) * sc + bi;
                    if (act == 1)      v = fmaxf(v, 0.f);
                    else if (act == 2) v = (v > 0.f) ? v : 0.2f * v;
                    Yrow[col + cc] = v;
                }
            }
        }
    }
}

// ---------------------------------------------------------------------------
// TC apply (K-split, fused colsum): A rows scaled by invs at load time.
// Single-term TF32 (ah*bh): truncation errors of V and P are random-signed
// and average out over the K=4096 attn-weighted sum (verified: dropping the
// P-low term moved rel_err by 0). Colsum uses exact fp32 P values.
// ---------------------------------------------------------------------------
__global__ __launch_bounds__(256, 2) void tc_apply_kernel(
    const float* __restrict__ V,
    const float* __restrict__ A,
    const float* __restrict__ invs,
    float* __restrict__ pOut,
    float* __restrict__ pSum)
{
    const int bN = blockIdx.x * 128;
    const int ks = blockIdx.y;
    const int b  = blockIdx.z;
    const float* Wb = V + (long)b * 128 * NPTS + (long)ks * KC;
    const float* Xb = A + (long)b * NPTS * NPTS + (long)ks * KC * NPTS;
    const float* invb = invs + (long)b * NPTS + (long)ks * KC;

    __shared__ __align__(16) float Ws[2][16][132];
    __shared__ __align__(16) float Xs[2][16][132];

    const int tid    = threadIdx.x;
    const int wid    = tid >> 5;
    const int lane   = tid & 31;
    const int warp_m = wid >> 2;
    const int warp_n = wid & 3;

    const int wm  = tid >> 2;
    const int wkq = (tid & 3) * 4;
    const int xka = tid >> 5, xna = (tid & 31) * 4;
    const int xkb = xka + 8;

    float acc[4][4][4];
    #pragma unroll
    for (int mi = 0; mi < 4; mi++)
        #pragma unroll
        for (int ni = 0; ni < 4; ni++)
            #pragma unroll
            for (int r = 0; r < 4; r++) acc[mi][ni][r] = 0.f;
    float ssum = 0.f;

    float4 wr0, wr1, xr0, xr1;

    {
        float ia = invb[xka], ib = invb[xkb];
        wr0 = *(const float4*)&Wb[(long)(wm     ) * NPTS + wkq];
        wr1 = *(const float4*)&Wb[(long)(wm + 64) * NPTS + wkq];
        xr0 = *(const float4*)&Xb[(long)xka * NPTS + bN + xna];
        xr1 = *(const float4*)&Xb[(long)xkb * NPTS + bN + xna];
        xr0.x *= ia; xr0.y *= ia; xr0.z *= ia; xr0.w *= ia;
        xr1.x *= ib; xr1.y *= ib; xr1.z *= ib; xr1.w *= ib;
        Ws[0][wkq+0][wm] = wr0.x; Ws[0][wkq+1][wm] = wr0.y;
        Ws[0][wkq+2][wm] = wr0.z; Ws[0][wkq+3][wm] = wr0.w;
        Ws[0][wkq+0][wm+64] = wr1.x; Ws[0][wkq+1][wm+64] = wr1.y;
        Ws[0][wkq+2][wm+64] = wr1.z; Ws[0][wkq+3][wm+64] = wr1.w;
        *(float4*)&Xs[0][xka][xna] = xr0;
        *(float4*)&Xs[0][xkb][xna] = xr1;
    }
    __syncthreads();

    const int alr = lane >> 2;
    const int akc = lane & 3;
    const int bnr = warp_n * 32 + (lane >> 2);

    const int T = KC / 16;
    for (int t = 0; t < T; t++) {
        const int cur = t & 1;
        const int nxt = cur ^ 1;
        const bool more = (t + 1 < T);

        if (more) {
            int k0 = (t + 1) * 16;
            float ia = invb[k0 + xka], ib = invb[k0 + xkb];
            wr0 = *(const float4*)&Wb[(long)(wm     ) * NPTS + k0 + wkq];
            wr1 = *(const float4*)&Wb[(long)(wm + 64) * NPTS + k0 + wkq];
            xr0 = *(const float4*)&Xb[(long)(k0 + xka) * NPTS + bN + xna];
            xr1 = *(const float4*)&Xb[(long)(k0 + xkb) * NPTS + bN + xna];
            xr0.x *= ia; xr0.y *= ia; xr0.z *= ia; xr0.w *= ia;
            xr1.x *= ib; xr1.y *= ib; xr1.z *= ib; xr1.w *= ib;
        }

        #pragma unroll
        for (int kk = 0; kk < 2; kk++) {
            const int k0 = kk * 8;
            unsigned bh[4][2];
            #pragma unroll
            for (int ni = 0; ni < 4; ni++) {
                #pragma unroll
                for (int r = 0; r < 2; r++) {
                    float f = Xs[cur][k0 + akc + r*4][bnr + ni*8];
                    bh[ni][r] = f2tf(f);
                }
            }
            #pragma unroll
            for (int mi = 0; mi < 4; mi++) {
                int m0 = warp_m * 64 + mi * 16 + alr;
                unsigned ah[4];
                ah[0] = f2tf(Ws[cur][k0 + akc    ][m0]);
                ah[1] = f2tf(Ws[cur][k0 + akc    ][m0 + 8]);
                ah[2] = f2tf(Ws[cur][k0 + akc + 4][m0]);
                ah[3] = f2tf(Ws[cur][k0 + akc + 4][m0 + 8]);
                #pragma unroll
                for (int ni = 0; ni < 4; ni++)
                    mma_tf32(acc[mi][ni], ah, bh[ni]);
            }
        }

        // fused colsum over true A values (threads 0..127, one column each)
        if (tid < 128) {
            float s = 0.f;
            #pragma unroll
            for (int k = 0; k < 16; k++) s += Xs[cur][k][tid];
            ssum += s;
        }

        if (more) {
            Ws[nxt][wkq+0][wm] = wr0.x; Ws[nxt][wkq+1][wm] = wr0.y;
            Ws[nxt][wkq+2][wm] = wr0.z; Ws[nxt][wkq+3][wm] = wr0.w;
            Ws[nxt][wkq+0][wm+64] = wr1.x; Ws[nxt][wkq+1][wm+64] = wr1.y;
            Ws[nxt][wkq+2][wm+64] = wr1.z; Ws[nxt][wkq+3][wm+64] = wr1.w;
            *(float4*)&Xs[nxt][xka][xna] = xr0;
            *(float4*)&Xs[nxt][xkb][xna] = xr1;
            __syncthreads();
        }
    }

    float* Ob = pOut + ((long)(ks * NB + b) * 128) * NPTS;
    #pragma unroll
    for (int mi = 0; mi < 4; mi++) {
        #pragma unroll
        for (int rr = 0; rr < 2; rr++) {
            int o = warp_m * 64 + mi * 16 + (lane >> 2) + rr * 8;
            float* Yrow = Ob + (long)o * NPTS;
            #pragma unroll
            for (int ni = 0; ni < 4; ni++) {
                int col = bN + warp_n * 32 + ni * 8 + (lane & 3) * 2;
                Yrow[col]     = acc[mi][ni][rr * 2];
                Yrow[col + 1] = acc[mi][ni][rr * 2 + 1];
            }
        }
    }
    if (tid < 128)
        pSum[(long)(ks * NB + b) * NPTS + bN + tid] = ssum;
}

// ---------------------------------------------------------------------------
// Apply reduce: t[b,c,n] = h[b,c,n] - (sum_ks pOut)/(1e-9 + sum_ks pSum)
// ---------------------------------------------------------------------------
__global__ __launch_bounds__(256) void apply_reduce_kernel(
    const float* __restrict__ pOut, const float* __restrict__ pSum,
    const float* __restrict__ h, long hStride, float* __restrict__ t)
{
    int n = blockIdx.x * 256 + threadIdx.x;
    int c = blockIdx.y;
    int b = blockIdx.z;
    float num = 0.f, den = 0.f;
    #pragma unroll
    for (int ks = 0; ks < KS; ks++) {
        num += pOut[((long)(ks * NB + b) * 128 + c) * NPTS + n];
        den += pSum[(long)(ks * NB + b) * NPTS + n];
    }
    t[((long)b * 128 + c) * NPTS + n] =
        h[(long)b * hStride + (long)c * NPTS + n] - num / (1e-9f + den);
}

// ---------------------------------------------------------------------------
// qnorm: nq2[i] = ||q_i||^2 and per-batch max (atomicMax on int bits; values
// are >= 0 and nq2M is zero-initialized, so signed-int ordering is correct).
// ---------------------------------------------------------------------------
__global__ __launch_bounds__(256) void qnorm_kernel(const float* __restrict__ q,
                                                    float* __restrict__ nq2,
                                                    float* __restrict__ nq2M)
{
    int i = blockIdx.x * 256 + threadIdx.x;
    int b = blockIdx.y;
    const float* Q = q + (long)b * 32 * NPTS;
    float s = 0.f;
    #pragma unroll
    for (int d = 0; d < 32; d++) {
        float v = Q[(long)d * NPTS + i];
        s += v * v;
    }
    nq2[b * NPTS + i] = s;

    __shared__ float red[256];
    int tid = threadIdx.x;
    red[tid] = s; __syncthreads();
    for (int st = 128; st > 0; st >>= 1) {
        if (tid < st) red[tid] = fmaxf(red[tid], red[tid + st]);
        __syncthreads();
    }
    if (tid == 0) atomicMax((int*)&nq2M[b], __float_as_int(red[0]));
}

// ---------------------------------------------------------------------------
// pexp: compute E tile, write P = exp(E - m_i) with the Cauchy-Schwarz shift
// m_i = ||q_i|| * max_j ||q_j||, accumulate row sums via atomicAdd.
// ---------------------------------------------------------------------------
__global__ __launch_bounds__(256) void pexp_kernel(const float* __restrict__ q,
                                                   const float* __restrict__ nq2,
                                                   const float* __restrict__ nq2M,
                                                   float* __restrict__ P,
                                                   float* __restrict__ s)
{
    int bj = blockIdx.x * 64;
    int bi = blockIdx.y * 64;
    int b  = blockIdx.z;
    const float* Q = q + (long)b * 32 * NPTS;
    float* Pb = P + (long)b * NPTS * NPTS;

    __shared__ __align__(16) float Qi[32][64];
    __shared__ __align__(16) float Qj[32][64];
    __shared__ float sm[64][17];

    int tid = threadIdx.x;
    #pragma unroll
    for (int l = 0; l < 2; l++) {
        int idx = tid + l * 256;
        int d   = idx >> 4;
        int nq  = (idx & 15) * 4;
        *(float4*)&Qi[d][nq] = *(const float4*)&Q[(long)d * NPTS + bi + nq];
        *(float4*)&Qj[d][nq] = *(const float4*)&Q[(long)d * NPTS + bj + nq];
    }
    __syncthreads();

    int ti = (tid >> 4) * 4;
    int tj = (tid & 15) * 4;
    unsigned long long acc2[2][4];
    #pragma unroll
    for (int p = 0; p < 2; p++)
        #pragma unroll
        for (int c = 0; c < 4; c++) acc2[p][c] = 0ull;

    #pragma unroll
    for (int d = 0; d < 32; d++) {
        ulonglong2 a = *(const ulonglong2*)&Qi[d][ti];
        unsigned long long ap[2] = {a.x, a.y};
        float4 c4 = *(const float4*)&Qj[d][tj];
        float cv[4] = {c4.x, c4.y, c4.z, c4.w};
        unsigned long long bs[4];
        #pragma unroll
        for (int c = 0; c < 4; c++) bs[c] = pack2(cv[c], cv[c]);
        #pragma unroll
        for (int p = 0; p < 2; p++)
            #pragma unroll
            for (int c = 0; c < 4; c++) ffma2(acc2[p][c], ap[p], bs[c]);
    }

    float sM = sqrtf(nq2M[b]);
    float mrow[4], rsum[4] = {0.f, 0.f, 0.f, 0.f};
    #pragma unroll
    for (int r = 0; r < 4; r++)
        mrow[r] = sqrtf(nq2[b * NPTS + bi + ti + r]) * sM;

    #pragma unroll
    for (int p = 0; p < 2; p++) {
        float2 u0 = unpack2(acc2[p][0]);
        float2 u1 = unpack2(acc2[p][1]);
        float2 u2 = unpack2(acc2[p][2]);
        float2 u3 = unpack2(acc2[p][3]);
        int r0 = bi + ti + p * 2;
        float m0 = mrow[p*2], m1 = mrow[p*2 + 1];
        float4 row0 = make_float4(__expf(u0.x - m0), __expf(u1.x - m0),
                                  __expf(u2.x - m0), __expf(u3.x - m0));
        float4 row1 = make_float4(__expf(u0.y - m1), __expf(u1.y - m1),
                                  __expf(u2.y - m1), __expf(u3.y - m1));
        rsum[p*2]     += row0.x + row0.y + row0.z + row0.w;
        rsum[p*2 + 1] += row1.x + row1.y + row1.z + row1.w;
        *(float4*)&Pb[(long)r0       * NPTS + bj + tj] = row0;
        *(float4*)&Pb[(long)(r0 + 1) * NPTS + bj + tj] = row1;
    }

    #pragma unroll
    for (int r = 0; r < 4; r++) sm[ti + r][tid & 15] = rsum[r];
    __syncthreads();
    if (tid < 64) {
        float v = 0.f;
        #pragma unroll
        for (int k = 0; k < 16; k++) v += sm[tid][k];
        atomicAdd(&s[b * NPTS + bi + tid], v);
    }
}

// zero s (len) and nq2M (NB)
__global__ void zero2_kernel(float* __restrict__ a, float* __restrict__ c, int len)
{
    int i = blockIdx.x * 256 + threadIdx.x;
    if (i < len) a[i] = 0.f;
    if (i < NB)  c[i] = 0.f;
}

// invs = 1/s  (guard against pathological underflow)
__global__ void inv_kernel(const float* __restrict__ s, float* __restrict__ invs, int len)
{
    int i = blockIdx.x * 256 + threadIdx.x;
    if (i < len) invs[i] = 1.0f / fmaxf(s[i], 1e-37f);
}

// ---------------------------------------------------------------------------
// Global max / mean pool over N for hf (1024 channels)
// ---------------------------------------------------------------------------
__global__ __launch_bounds__(256) void pool_kernel(const float* __restrict__ hf,
                                                   float* __restrict__ pool)
{
    int c = blockIdx.x, b = blockIdx.y, tid = threadIdx.x;
    const float* row = hf + ((long)b * 1024 + c) * NPTS;
    float m = -1e30f, sum = 0.f;
    for (int n = tid; n < NPTS; n += 256) {
        float v = row[n];
        m = fmaxf(m, v);
        sum += v;
    }
    __shared__ float sm[256], ss[256];
    sm[tid] = m; ss[tid] = sum; __syncthreads();
    for (int st = 128; st > 0; st >>= 1) {
        if (tid < st) {
            sm[tid] = fmaxf(sm[tid], sm[tid + st]);
            ss[tid] += ss[tid + st];
        }
        __syncthreads();
    }
    if (tid == 0) {
        pool[b * 2048 + c]        = sm[0];
        pool[b * 2048 + 1024 + c] = ss[0] * (1.f / NPTS);
    }
}

// ---------------------------------------------------------------------------
// pbias[b,o] = bs1[o] + sum_c ws1[o,1024+c]*max[b,c] + ws1[o,2048+c]*mean[b,c]
// ---------------------------------------------------------------------------
__global__ __launch_bounds__(256) void pbias_kernel(const float* __restrict__ ws1,
                                                    const float* __restrict__ bs1,
                                                    const float* __restrict__ pool,
                                                    float* __restrict__ pbias)
{
    int o = blockIdx.x, b = blockIdx.y, tid = threadIdx.x;
    float acc = 0.f;
    for (int c = tid; c < 1024; c += 256) {
        acc += ws1[(long)o * 3072 + 1024 + c] * pool[b * 2048 + c];
        acc += ws1[(long)o * 3072 + 2048 + c] * pool[b * 2048 + 1024 + c];
    }
    __shared__ float red[256];
    red[tid] = acc; __syncthreads();
    for (int st = 128; st > 0; st >>= 1) {
        if (tid < st) red[tid] += red[tid + st];
        __syncthreads();
    }
    if (tid == 0) pbias[b * 512 + o] = bs1[o] + red[0];
}

// ---------------------------------------------------------------------------
// Final: logits = ws3 @ h256 + bs3; log_softmax over 8 channels; transpose out
// ---------------------------------------------------------------------------
__global__ __launch_bounds__(128) void final_kernel(const float* __restrict__ h256,
                                                    const float* __restrict__ ws3,
                                                    const float* __restrict__ bs3,
                                                    float* __restrict__ out)
{
    __shared__ float Wsh[8][256];
    int tid = threadIdx.x;
    for (int l = tid; l < 2048; l += 128) Wsh[l >> 8][l & 255] = ws3[l];
    __syncthreads();

    int n = blockIdx.x * 128 + tid;
    int b = blockIdx.y;
    const float* hb = h256 + (long)b * 256 * NPTS;

    float acc[8];
    #pragma unroll
    for (int k = 0; k < 8; k++) acc[k] = bs3[k];
    for (int c = 0; c < 256; c++) {
        float xv = hb[(long)c * NPTS + n];
        #pragma unroll
        for (int k = 0; k < 8; k++) acc[k] += Wsh[k][c] * xv;
    }
    float m = acc[0];
    #pragma unroll
    for (int k = 1; k < 8; k++) m = fmaxf(m, acc[k]);
    float s = 0.f;
    #pragma unroll
    for (int k = 0; k < 8; k++) s += __expf(acc[k] - m);
    float lse = m + logf(s);
    float* op = out + ((long)b * NPTS + n) * 8;
    #pragma unroll
    for (int k = 0; k < 8; k++) op[k] = acc[k] - lse;
}

// ---------------------------------------------------------------------------
// Host orchestration
// ---------------------------------------------------------------------------
static inline void launch_gemm64(const float* W, int ldW,
                                 const float* X, long sX,
                                 float* Y, long sY, int O, int C,
                                 const float* cb, int cbs,
                                 const float* sc, const float* bi, int act,
                                 const float* res, long sres)
{
    dim3 grid(NPTS / 64, (O + 127) / 128, NB);
    gemm_kernel<64><<<grid, 256>>>(W, ldW, X, sX, Y, sY, O, C,
                                   cb, cbs, sc, bi, act, res, sres);
}

static inline void launch_tc(const float* W, int ldW,
                             const float* X, long sX,
                             float* Y, long sY, int O, int C,
                             const float* cb, int cbs,
                             const float* sc, const float* bi, int act)
{
    dim3 grid(NPTS / 128, O / 128, NB);
    tc_gemm_kernel<<<grid, 256>>>(W, ldW, X, sX, Y, sY, C, cb, cbs, sc, bi, act);
}

extern "C" void kernel_launch(void* const* d_in, const int* in_sizes, int n_in,
                              void* d_out, int out_size)
{
    (void)in_sizes; (void)n_in; (void)out_size;

    const float* x      = (const float*)d_in[0];
    const float* w1     = (const float*)d_in[1];
    const float* bn1_g  = (const float*)d_in[2];
    const float* bn1_b  = (const float*)d_in[3];
    const float* w2     = (const float*)d_in[4];
    const float* bn2_g  = (const float*)d_in[5];
    const float* bn2_b  = (const float*)d_in[6];
    const float* sa_wqk = (const float*)d_in[7];
    const float* sa_wv  = (const float*)d_in[8];
    const float* sa_bv  = (const float*)d_in[9];
    const float* sa_wt  = (const float*)d_in[10];
    const float* sa_bt  = (const float*)d_in[11];
    const float* sa_bng = (const float*)d_in[12];
    const float* sa_bnb = (const float*)d_in[13];
    const float* wf     = (const float*)d_in[14];
    const float* bnf_g  = (const float*)d_in[15];
    const float* bnf_b  = (const float*)d_in[16];
    const float* ws1    = (const float*)d_in[17];
    const float* bs1    = (const float*)d_in[18];
    const float* bns1_g = (const float*)d_in[19];
    const float* bns1_b = (const float*)d_in[20];
    const float* ws2    = (const float*)d_in[21];
    const float* bs2    = (const float*)d_in[22];
    const float* bns2_g = (const float*)d_in[23];
    const float* bns2_b = (const float*)d_in[24];
    const float* ws3    = (const float*)d_in[25];
    const float* bs3    = (const float*)d_in[26];

    float *p_h1, *p_h0, *p_q, *p_v, *p_E, *p_t, *p_feats, *p_hf, *p_pool,
          *p_pbias, *p_h512, *p_h256, *p_pOut, *p_pSum, *p_nq2, *p_nq2M,
          *p_s, *p_invs;
    cudaGetSymbolAddress((void**)&p_h1,    g_h1);
    cudaGetSymbolAddress((void**)&p_h0,    g_h0);
    cudaGetSymbolAddress((void**)&p_q,     g_q);
    cudaGetSymbolAddress((void**)&p_v,     g_v);
    cudaGetSymbolAddress((void**)&p_E,     g_E);
    cudaGetSymbolAddress((void**)&p_t,     g_t);
    cudaGetSymbolAddress((void**)&p_feats, g_feats);
    cudaGetSymbolAddress((void**)&p_hf,    g_hf);
    cudaGetSymbolAddress((void**)&p_pool,  g_pool);
    cudaGetSymbolAddress((void**)&p_pbias, g_pbias);
    cudaGetSymbolAddress((void**)&p_h512,  g_h512);
    cudaGetSymbolAddress((void**)&p_h256,  g_h256);
    cudaGetSymbolAddress((void**)&p_pOut,  g_pOut);
    cudaGetSymbolAddress((void**)&p_pSum,  g_pSum);
    cudaGetSymbolAddress((void**)&p_nq2,   g_nq2);
    cudaGetSymbolAddress((void**)&p_nq2M,  g_nq2M);
    cudaGetSymbolAddress((void**)&p_s,     g_s);
    cudaGetSymbolAddress((void**)&p_invs,  g_invs);

    // input MLP
    mlp1_kernel<<<dim3(NPTS / 256, 128, NB), 256>>>(x, w1, bn1_g, bn1_b, p_h1);
    launch_gemm64(w2, 128, p_h1, 128L * NPTS, p_h0, 128L * NPTS, 128, 128,
                  0, 0, bn2_g, bn2_b, 1, 0, 0);

    // 4 self-attention layers
    for (int i = 0; i < 4; i++) {
        const float* h   = (i == 0) ? p_h0 : (p_feats + (long)(i - 1) * 128 * NPTS);
        long hStride     = (i == 0) ? 128L * NPTS : 512L * NPTS;

        // q = wqk_i @ h
        launch_gemm64(sa_wqk + (long)i * 32 * 128, 128, h, hStride,
                      p_q, 32L * NPTS, 32, 128, 0, 0, 0, 0, 0, 0, 0);
        // v = wv_i @ h + bv_i
        launch_gemm64(sa_wv + (long)i * 128 * 128, 128, h, hStride,
                      p_v, 128L * NPTS, 128, 128,
                      sa_bv + (long)i * 128, 0, 0, 0, 0, 0, 0);

        // fused energy/softmax: norm bound, P = exp(E - m), row sums, invs
        zero2_kernel<<<(NB * NPTS + 255) / 256, 256>>>(p_s, p_nq2M, NB * NPTS);
        qnorm_kernel<<<dim3(NPTS / 256, NB), 256>>>(p_q, p_nq2, p_nq2M);
        pexp_kernel<<<dim3(64, 64, NB), 256>>>(p_q, p_nq2, p_nq2M, p_E, p_s);
        inv_kernel<<<(NB * NPTS + 255) / 256, 256>>>(p_s, p_invs, NB * NPTS);

        // TC K-split apply (A scaled at load) with fused colsum, then reduce
        tc_apply_kernel<<<dim3(NPTS / 128, KS, NB), 256>>>(p_v, p_E, p_invs,
                                                           p_pOut, p_pSum);
        apply_reduce_kernel<<<dim3(NPTS / 256, 128, NB), 256>>>(p_pOut, p_pSum,
                                                                h, hStride, p_t);

        // h_new = relu(bn(wt_i @ t + bt_i)) + h  -> feats slice i
        launch_gemm64(sa_wt + (long)i * 128 * 128, 128, p_t, 128L * NPTS,
                      p_feats + (long)i * 128 * NPTS, 512L * NPTS, 128, 128,
                      sa_bt + (long)i * 128, 0,
                      sa_bng + (long)i * 128, sa_bnb + (long)i * 128, 1,
                      h, hStride);
    }

    // hf = leaky_relu(bn(wf @ feats), 0.2)   [TC]
    launch_tc(wf, 512, p_feats, 512L * NPTS, p_hf, 1024L * NPTS, 1024, 512,
              0, 0, bnf_g, bnf_b, 2);

    // pooling + folded per-batch bias for ws1
    pool_kernel<<<dim3(1024, NB), 256>>>(p_hf, p_pool);
    pbias_kernel<<<dim3(512, NB), 256>>>(ws1, bs1, p_pool, p_pbias);

    // h512 = relu(bn(ws1[:, :1024] @ hf + pbias))   [TC]
    launch_tc(ws1, 3072, p_hf, 1024L * NPTS, p_h512, 512L * NPTS, 512, 1024,
              p_pbias, 512, bns1_g, bns1_b, 1);

    // h256 = relu(bn(ws2 @ h512 + bs2))   [TC]
    launch_tc(ws2, 512, p_h512, 512L * NPTS, p_h256, 256L * NPTS, 256, 512,
              bs2, 0, bns2_g, bns2_b, 1);

    // logits + log_softmax + transpose
    final_kernel<<<dim3(NPTS / 128, NB), 128>>>(p_h256, ws3, bs3, (float*)d_out);
}